// round 3
// baseline (speedup 1.0000x reference)
#include <cuda_runtime.h>
#include <math.h>

#define NB   2048
#define DIMT 480
#define HID  1024
#define ZD   256
#define K0   16384
#define K1   4096
#define K2   1024

// ---------------- scratch (device globals; no allocations allowed) ----------------
constexpr long SZ_P0  = (long)NB * K0;
constexpr long SZ_P1  = (long)NB * K1;
constexpr long SZ_P2  = (long)NB * K2;
constexpr long SZ_H   = (long)NB * HID;
constexpr long SZ_Z   = (long)NB * ZD;

constexpr long OFF_P0   = 0;
constexpr long OFF_P1   = OFF_P0 + SZ_P0;
constexpr long OFF_P2   = OFF_P1 + SZ_P1;
constexpr long OFF_E    = OFF_P2 + SZ_P2;
constexpr long OFF_A1   = OFF_E  + SZ_H;
constexpr long OFF_XH1  = OFF_A1 + SZ_H;
constexpr long OFF_H1   = OFF_XH1 + SZ_H;
constexpr long OFF_A2   = OFF_H1 + SZ_H;
constexpr long OFF_XH2  = OFF_A2 + SZ_Z;
constexpr long OFF_DA2  = OFF_XH2 + SZ_Z;
constexpr long OFF_DH1  = OFF_DA2 + SZ_Z;
constexpr long OFF_DA1  = OFF_DH1 + SZ_H;
constexpr long OFF_DE   = OFF_DA1 + SZ_H;
constexpr long OFF_RS1  = OFF_DE  + SZ_H;
constexpr long OFF_RS2  = OFF_RS1 + NB;
constexpr long SZ_TOTAL = OFF_RS2 + NB;

__device__ float g_scratch[SZ_TOTAL];

// ---------------- SGEMM: C = alpha*A@B(^T) + beta*C + bias ----------------
// A: MxK row-major.  NT=false: B is KxN row-major.  NT=true: B is NxK row-major (B^T).
template<bool NT>
__global__ __launch_bounds__(256) void sgemm(
    const float* __restrict__ A, const float* __restrict__ B, float* __restrict__ C,
    int M, int Nn, int K, float alpha, float beta, const float* __restrict__ bias)
{
    __shared__ float As[16][132];
    __shared__ float Bs[16][132];
    int tid = threadIdx.x;
    int bm = blockIdx.y * 128, bn = blockIdx.x * 128;
    int tx = tid & 15, ty = tid >> 4;
    float acc[8][8];
    #pragma unroll
    for (int i = 0; i < 8; i++)
        #pragma unroll
        for (int j = 0; j < 8; j++) acc[i][j] = 0.f;

    for (int kt = 0; kt < K; kt += 16) {
        #pragma unroll
        for (int i = 0; i < 2; i++) {
            int idx = tid + i * 256;          // 0..511
            int row = idx >> 2;               // 0..127 (m within tile)
            int k4  = (idx & 3) << 2;         // 0,4,8,12
            float4 v = *(const float4*)(A + (long)(bm + row) * K + kt + k4);
            As[k4+0][row] = v.x; As[k4+1][row] = v.y;
            As[k4+2][row] = v.z; As[k4+3][row] = v.w;
        }
        if (NT) {
            #pragma unroll
            for (int i = 0; i < 2; i++) {
                int idx = tid + i * 256;
                int row = idx >> 2;           // n within tile
                int k4  = (idx & 3) << 2;
                float4 v = *(const float4*)(B + (long)(bn + row) * K + kt + k4);
                Bs[k4+0][row] = v.x; Bs[k4+1][row] = v.y;
                Bs[k4+2][row] = v.z; Bs[k4+3][row] = v.w;
            }
        } else {
            #pragma unroll
            for (int i = 0; i < 2; i++) {
                int idx = tid + i * 256;
                int krow = idx >> 5;          // 0..15
                int n4   = (idx & 31) << 2;   // 0..124
                float4 v = *(const float4*)(B + (long)(kt + krow) * Nn + bn + n4);
                *(float4*)&Bs[krow][n4] = v;
            }
        }
        __syncthreads();
        #pragma unroll
        for (int kk = 0; kk < 16; kk++) {
            float a[8], b[8];
            *(float4*)(a)     = *(const float4*)&As[kk][ty * 8];
            *(float4*)(a + 4) = *(const float4*)&As[kk][ty * 8 + 4];
            *(float4*)(b)     = *(const float4*)&Bs[kk][tx * 8];
            *(float4*)(b + 4) = *(const float4*)&Bs[kk][tx * 8 + 4];
            #pragma unroll
            for (int i = 0; i < 8; i++)
                #pragma unroll
                for (int j = 0; j < 8; j++)
                    acc[i][j] += a[i] * b[j];
        }
        __syncthreads();
    }
    #pragma unroll
    for (int i = 0; i < 8; i++) {
        int m = bm + ty * 8 + i;
        float* Crow = C + (long)m * Nn + bn + tx * 8;
        #pragma unroll
        for (int j = 0; j < 8; j++) {
            float v = alpha * acc[i][j];
            if (beta != 0.f) v += beta * Crow[j];
            if (bias) v += bias[bn + tx * 8 + j];
            Crow[j] = v;
        }
    }
}

// ---------------- build pairwise product matrices ----------------
__global__ void build_P0(const float* __restrict__ t, float* __restrict__ P) {
    int idx = blockIdx.x * 256 + threadIdx.x;     // NB*K0 total
    int b = idx >> 14;
    int uv = idx & (K0 - 1);
    int u = uv >> 7, v = uv & 127;
    const float* r = t + (long)b * DIMT;
    P[idx] = r[u] * r[v];
}
__global__ void build_P1(const float* __restrict__ t, float* __restrict__ P) {
    int idx = blockIdx.x * 256 + threadIdx.x;     // NB*K1
    int b = idx >> 12;
    int uv = idx & (K1 - 1);
    int u = uv >> 6, v = uv & 63;
    const float* r = t + (long)b * DIMT + 128;
    float s = 0.f;
    #pragma unroll
    for (int m = 0; m < 3; m++) s += r[u * 3 + m] * r[v * 3 + m];
    P[idx] = s;
}
__global__ void build_P2(const float* __restrict__ t, float* __restrict__ P) {
    int idx = blockIdx.x * 256 + threadIdx.x;     // NB*K2
    int b = idx >> 10;
    int uv = idx & (K2 - 1);
    int u = uv >> 5, v = uv & 31;
    const float* r = t + (long)b * DIMT + 320;
    float s = 0.f;
    #pragma unroll
    for (int m = 0; m < 5; m++) s += r[u * 5 + m] * r[v * 5 + m];
    P[idx] = s;
}

// ---------------- block reduce ----------------
__device__ __forceinline__ float blockReduceSum(float val) {
    __shared__ float sh[8];
    int lane = threadIdx.x & 31, w = threadIdx.x >> 5;
    #pragma unroll
    for (int o = 16; o > 0; o >>= 1) val += __shfl_down_sync(0xffffffffu, val, o);
    __syncthreads();
    if (lane == 0) sh[w] = val;
    __syncthreads();
    float r = 0.f;
    if (threadIdx.x == 0) {
        int nw = blockDim.x >> 5;
        for (int i = 0; i < nw; i++) r += sh[i];
    }
    return r;  // valid on thread 0 only
}

// ---------------- LayerNorm + SiLU forward (per row) ----------------
template<int PER>
__global__ __launch_bounds__(256) void ln_silu_fwd(
    const float* __restrict__ a, const float* __restrict__ gam, const float* __restrict__ bet,
    float* __restrict__ xh, float* __restrict__ rstd, float* __restrict__ h)
{
    const int D = PER * 256;
    int b = blockIdx.x, tid = threadIdx.x;
    const float* row = a + (long)b * D;
    float v[PER];
    float s = 0.f;
    #pragma unroll
    for (int i = 0; i < PER; i++) { v[i] = row[tid + (i << 8)]; s += v[i]; }
    s = blockReduceSum(s);
    __shared__ float bc;
    if (tid == 0) bc = s * (1.f / D);
    __syncthreads();
    float mu = bc;
    float q = 0.f;
    #pragma unroll
    for (int i = 0; i < PER; i++) { float d = v[i] - mu; q += d * d; }
    q = blockReduceSum(q);
    if (tid == 0) { float r = rsqrtf(q * (1.f / D) + 1e-6f); bc = r; rstd[b] = r; }
    __syncthreads();
    float r = bc;
    #pragma unroll
    for (int i = 0; i < PER; i++) {
        int c = tid + (i << 8);
        float x = (v[i] - mu) * r;
        xh[(long)b * D + c] = x;
        float z = x * gam[c] + bet[c];
        float sg = 1.f / (1.f + expf(-z));
        h[(long)b * D + c] = z * sg;
    }
}

// ---------------- (SiLU + LN) backward (per row) ----------------
// dh==nullptr means upstream cotangent of ones.
template<int PER>
__global__ __launch_bounds__(256) void ln_silu_bwd(
    const float* __restrict__ dh, const float* __restrict__ xhv_, const float* __restrict__ rstd,
    const float* __restrict__ gam, const float* __restrict__ bet, float* __restrict__ da)
{
    const int D = PER * 256;
    int b = blockIdx.x, tid = threadIdx.x;
    float xh[PER], dxh[PER];
    float s1 = 0.f, s2 = 0.f;
    #pragma unroll
    for (int i = 0; i < PER; i++) {
        int c = tid + (i << 8);
        float x = xhv_[(long)b * D + c];
        float z = x * gam[c] + bet[c];
        float sg = 1.f / (1.f + expf(-z));
        float ds = sg * (1.f + z * (1.f - sg));        // silu'(z)
        float up = dh ? dh[(long)b * D + c] : 1.f;
        float dx = up * ds * gam[c];                   // d wrt xhat
        xh[i] = x; dxh[i] = dx;
        s1 += dx; s2 += dx * x;
    }
    __shared__ float m1s, m2s;
    float t1 = blockReduceSum(s1);
    if (tid == 0) m1s = t1 * (1.f / D);
    float t2 = blockReduceSum(s2);
    if (tid == 0) m2s = t2 * (1.f / D);
    __syncthreads();
    float m1 = m1s, m2 = m2s, r = rstd[b];
    #pragma unroll
    for (int i = 0; i < PER; i++) {
        int c = tid + (i << 8);
        da[(long)b * D + c] = r * (dxh[i] - m1 - xh[i] * m2);
    }
}

// ---------------- quadratic-form gradients -> y ----------------
__global__ __launch_bounds__(128) void grad0(const float* __restrict__ dP,
                                             const float* __restrict__ t, float* __restrict__ y)
{
    __shared__ float Ts[64][129];
    __shared__ float xs[128];
    int b = blockIdx.x, tid = threadIdx.x;
    xs[tid] = t[(long)b * DIMT + tid];
    float racc = 0.f, cacc = 0.f;
    for (int ch = 0; ch < 2; ch++) {
        __syncthreads();
        const float* P = dP + (long)b * K0 + ch * 64 * 128;
        for (int i = tid; i < 2048; i += 128) {       // 2048 float4 = 64x128
            float4 v = *(const float4*)(P + i * 4);
            int r = (i * 4) >> 7, c = (i * 4) & 127;
            Ts[r][c] = v.x; Ts[r][c + 1] = v.y; Ts[r][c + 2] = v.z; Ts[r][c + 3] = v.w;
        }
        __syncthreads();
        int u = tid;
        if ((u >> 6) == ch) {
            int ul = u & 63;
            float s = 0.f;
            #pragma unroll 8
            for (int v = 0; v < 128; v++) s += Ts[ul][v] * xs[v];
            racc = s;
        }
        float s = 0.f;
        #pragma unroll 8
        for (int up = 0; up < 64; up++) s += Ts[up][u] * xs[ch * 64 + up];
        cacc += s;
    }
    y[(long)b * DIMT + tid] = racc + cacc;
}

__global__ __launch_bounds__(192) void grad1(const float* __restrict__ dP,
                                             const float* __restrict__ t, float* __restrict__ y)
{
    __shared__ float Ts[64][65];
    __shared__ float xs[192];
    int b = blockIdx.x, tid = threadIdx.x;
    const float* P = dP + (long)b * K1;
    for (int i = tid; i < 4096; i += 192) Ts[i >> 6][i & 63] = P[i];
    xs[tid] = t[(long)b * DIMT + 128 + tid];
    __syncthreads();
    int u = tid / 3, m = tid - u * 3;
    float s = 0.f;
    #pragma unroll 8
    for (int v = 0; v < 64; v++) s += (Ts[u][v] + Ts[v][u]) * xs[v * 3 + m];
    y[(long)b * DIMT + 128 + tid] = s;
}

__global__ __launch_bounds__(160) void grad2(const float* __restrict__ dP,
                                             const float* __restrict__ t, float* __restrict__ y)
{
    __shared__ float Ts[32][33];
    __shared__ float xs[160];
    int b = blockIdx.x, tid = threadIdx.x;
    const float* P = dP + (long)b * K2;
    for (int i = tid; i < 1024; i += 160) Ts[i >> 5][i & 31] = P[i];
    xs[tid] = t[(long)b * DIMT + 320 + tid];
    __syncthreads();
    int u = tid / 5, m = tid - u * 5;
    float s = 0.f;
    #pragma unroll 8
    for (int v = 0; v < 32; v++) s += (Ts[u][v] + Ts[v][u]) * xs[v * 5 + m];
    y[(long)b * DIMT + 320 + tid] = s;
}

// ---------------- launch ----------------
extern "C" void kernel_launch(void* const* d_in, const int* in_sizes, int n_in,
                              void* d_out, int out_size)
{
    const float* tin = (const float*)d_in[0];
    const float* w0  = (const float*)d_in[1];   // (128,128,HID) -> flat (K0, HID)
    const float* w1  = (const float*)d_in[2];   // (64,64,HID)   -> flat (K1, HID)
    const float* w2  = (const float*)d_in[3];   // (32,32,HID)   -> flat (K2, HID)
    const float* W1  = (const float*)d_in[4];   // (HID, HID)
    const float* b1  = (const float*)d_in[5];
    const float* g1  = (const float*)d_in[6];
    const float* be1 = (const float*)d_in[7];
    const float* W2  = (const float*)d_in[8];   // (HID, ZD)
    const float* b2  = (const float*)d_in[9];
    const float* g2  = (const float*)d_in[10];
    const float* be2 = (const float*)d_in[11];

    float* out  = (float*)d_out;
    float* xout = out;                          // (NB, ZD)
    float* yout = out + (long)NB * ZD;          // (NB, DIMT)

    float* base = nullptr;
    cudaGetSymbolAddress((void**)&base, g_scratch);
    float* P0  = base + OFF_P0;
    float* P1  = base + OFF_P1;
    float* P2  = base + OFF_P2;
    float* e   = base + OFF_E;
    float* a1  = base + OFF_A1;
    float* xh1 = base + OFF_XH1;
    float* h1  = base + OFF_H1;
    float* a2  = base + OFF_A2;
    float* xh2 = base + OFF_XH2;
    float* da2 = base + OFF_DA2;
    float* dh1 = base + OFF_DH1;
    float* da1 = base + OFF_DA1;
    float* de  = base + OFF_DE;
    float* rs1 = base + OFF_RS1;
    float* rs2 = base + OFF_RS2;

    const float s0 = 1.0f / sqrtf(21504.0f);
    const float s1 = s0 / sqrtf(3.0f);
    const float s2 = s0 / sqrtf(5.0f);

    // ---- forward ----
    build_P0<<<(NB * K0) / 256, 256>>>(tin, P0);
    build_P1<<<(NB * K1) / 256, 256>>>(tin, P1);
    build_P2<<<(NB * K2) / 256, 256>>>(tin, P2);

    dim3 gE(HID / 128, NB / 128);
    sgemm<false><<<gE, 256>>>(P0, w0, e, NB, HID, K0, s0, 0.f, nullptr);
    sgemm<false><<<gE, 256>>>(P1, w1, e, NB, HID, K1, s1, 1.f, nullptr);
    sgemm<false><<<gE, 256>>>(P2, w2, e, NB, HID, K2, s2, 1.f, nullptr);

    sgemm<false><<<dim3(HID / 128, NB / 128), 256>>>(e, W1, a1, NB, HID, HID, 1.f, 0.f, b1);
    ln_silu_fwd<4><<<NB, 256>>>(a1, g1, be1, xh1, rs1, h1);
    sgemm<false><<<dim3(ZD / 128, NB / 128), 256>>>(h1, W2, a2, NB, ZD, HID, 1.f, 0.f, b2);
    ln_silu_fwd<1><<<NB, 256>>>(a2, g2, be2, xh2, rs2, xout);

    // ---- backward ----
    ln_silu_bwd<1><<<NB, 256>>>(nullptr, xh2, rs2, g2, be2, da2);
    sgemm<true><<<dim3(HID / 128, NB / 128), 256>>>(da2, W2, dh1, NB, HID, ZD, 1.f, 0.f, nullptr);
    ln_silu_bwd<4><<<NB, 256>>>(dh1, xh1, rs1, g1, be1, da1);
    sgemm<true><<<dim3(HID / 128, NB / 128), 256>>>(da1, W1, de, NB, HID, HID, 1.f, 0.f, nullptr);

    sgemm<true><<<dim3(K0 / 128, NB / 128), 256>>>(de, w0, P0, NB, K0, HID, s0, 0.f, nullptr);
    sgemm<true><<<dim3(K1 / 128, NB / 128), 256>>>(de, w1, P1, NB, K1, HID, s1, 0.f, nullptr);
    sgemm<true><<<dim3(K2 / 128, NB / 128), 256>>>(de, w2, P2, NB, K2, HID, s2, 0.f, nullptr);

    grad0<<<NB, 128>>>(P0, tin, yout);
    grad1<<<NB, 192>>>(P1, tin, yout);
    grad2<<<NB, 160>>>(P2, tin, yout);
}

// round 5
// speedup vs baseline: 2.5781x; 2.5781x over previous
#include <cuda_runtime.h>
#include <cuda_bf16.h>
#include <math.h>
#include <stdint.h>

#define NB   2048
#define DIMT 480
#define HID  1024
#define ZD   256
#define K0   16384
#define K1   4096
#define K2   1024
#define KC   21504

typedef __nv_bfloat16 bf16;

// ---------------- scratch pools ----------------
constexpr long NBKC = (long)NB * KC;     // 44,040,192
constexpr long HKC  = (long)HID * KC;    // 22,020,096
constexpr long HH   = (long)HID * HID;
constexpr long ZH   = (long)ZD * HID;
constexpr long NH   = (long)NB * HID;
constexpr long NZ   = (long)NB * ZD;

// bf16 pool offsets
constexpr long B_PCHI = 0;
constexpr long B_PCLO = B_PCHI + NBKC;
constexpr long B_WTHI = B_PCLO + NBKC;
constexpr long B_WTLO = B_WTHI + HKC;
constexpr long B_WCHI = B_WTLO + HKC;
constexpr long B_WCLO = B_WCHI + HKC;
constexpr long B_W1THI= B_WCLO + HKC;
constexpr long B_W1TLO= B_W1THI + HH;
constexpr long B_W1HI = B_W1TLO + HH;
constexpr long B_W1LO = B_W1HI + HH;
constexpr long B_W2THI= B_W1LO + HH;
constexpr long B_W2TLO= B_W2THI + ZH;
constexpr long B_W2HI = B_W2TLO + ZH;
constexpr long B_W2LO = B_W2HI + ZH;
constexpr long B_EHI  = B_W2LO + ZH;
constexpr long B_ELO  = B_EHI + NH;
constexpr long B_H1HI = B_ELO + NH;
constexpr long B_H1LO = B_H1HI + NH;
constexpr long B_DA2HI= B_H1LO + NH;
constexpr long B_DA2LO= B_DA2HI + NZ;
constexpr long B_DA1HI= B_DA2LO + NZ;
constexpr long B_DA1LO= B_DA1HI + NH;
constexpr long B_DEHI = B_DA1LO + NH;
constexpr long B_DELO = B_DEHI + NH;
constexpr long B_TOT  = B_DELO + NH;

// fp32 pool offsets
constexpr long F_DPC  = 0;
constexpr long F_A1   = F_DPC + NBKC;
constexpr long F_XH1  = F_A1  + NH;
constexpr long F_A2   = F_XH1 + NH;
constexpr long F_XH2  = F_A2  + NZ;
constexpr long F_DH1  = F_XH2 + NZ;
constexpr long F_RS1  = F_DH1 + NH;
constexpr long F_RS2  = F_RS1 + NB;
constexpr long F_TOT  = F_RS2 + NB;

__device__ bf16  g_hbuf[B_TOT];
__device__ float g_fbuf[F_TOT];

// ---------------- helpers ----------------
__device__ __forceinline__ uint32_t smem_u32(const void* p) {
    uint32_t a;
    asm("{ .reg .u64 t; cvta.to.shared.u64 t, %1; cvt.u32.u64 %0, t; }" : "=r"(a) : "l"(p));
    return a;
}
__device__ __forceinline__ void ldsm4(uint32_t* r, uint32_t a) {
    asm volatile("ldmatrix.sync.aligned.m8n8.x4.shared.b16 {%0,%1,%2,%3},[%4];"
                 : "=r"(r[0]), "=r"(r[1]), "=r"(r[2]), "=r"(r[3]) : "r"(a));
}
__device__ __forceinline__ void mma_bf16(float* d, const uint32_t* a, const uint32_t* b) {
    asm volatile("mma.sync.aligned.m16n8k16.row.col.f32.bf16.bf16.f32 "
                 "{%0,%1,%2,%3},{%4,%5,%6,%7},{%8,%9},{%0,%1,%2,%3};"
                 : "+f"(d[0]), "+f"(d[1]), "+f"(d[2]), "+f"(d[3])
                 : "r"(a[0]), "r"(a[1]), "r"(a[2]), "r"(a[3]), "r"(b[0]), "r"(b[1]));
}
#define CPA(dst, src) asm volatile("cp.async.cg.shared.global [%0], [%1], 16;" :: "r"(dst), "l"(src) : "memory")
#define CPCOMMIT()    asm volatile("cp.async.commit_group;" ::: "memory")
#define CPWAIT1()     asm volatile("cp.async.wait_group 1;" ::: "memory")

__device__ __forceinline__ void split2(float v, bf16& h, bf16& l) {
    h = __float2bfloat16(v);
    l = __float2bfloat16(v - __bfloat162float(h));
}

// ---------------- bf16 split NT GEMM ----------------
// C[m,n] = alpha * sum_k A[m,k]*B[n,k] (+bias[n]); A=(Ahi+Alo), B=(Bhi+Blo), lo*lo dropped.
// grid = (N/128, M/128), 256 threads. K%64==0.
#define TILEB 16384            // one 128x64 bf16 tile (rows of 128B)
#define STG   (4 * TILEB)      // Ahi,Alo,Bhi,Blo per stage
#define GSMEM (3 * STG + 1024)

__global__ __launch_bounds__(256, 1) void bf_gemm_nt(
    const bf16* __restrict__ Ahi, const bf16* __restrict__ Alo,
    const bf16* __restrict__ Bhi, const bf16* __restrict__ Blo,
    float* __restrict__ C, bf16* __restrict__ Chi, bf16* __restrict__ Clo,
    int K, long ldc, float alpha, const float* __restrict__ bias)
{
    extern __shared__ char smem[];
    const uint32_t st0 = (smem_u32(smem) + 1023) & ~1023u;
    const int tid = threadIdx.x, wid = tid >> 5, lane = tid & 31;
    const int wm = wid >> 2, wn = wid & 3;
    const long bm = (long)blockIdx.y * 128, bn = (long)blockIdx.x * 128;

    // cp.async slots: 16 chunks/thread/stage (4 tiles x 4)
    const bf16* gp[16];
    uint32_t so[16];
    #pragma unroll
    for (int t = 0; t < 16; t++) {
        int q = tid + (t & 3) * 256;        // 0..1023
        int r = q >> 3, c = q & 7;
        int tile = t >> 2;                  // 0=Ahi 1=Alo 2=Bhi 3=Blo
        const bf16* base = (tile == 0) ? Ahi : (tile == 1) ? Alo : (tile == 2) ? Bhi : Blo;
        long row = (tile < 2 ? bm : bn) + r;
        gp[t] = base + row * K + c * 8;
        so[t] = st0 + tile * TILEB + ((r * 128 + c * 16) ^ ((r & 7) << 4));
    }
    const int nk = K >> 6;

    #pragma unroll
    for (int p = 0; p < 2; p++) {
        #pragma unroll
        for (int t = 0; t < 16; t++) CPA(so[t] + p * STG, gp[t] + (long)p * 64);
        CPCOMMIT();
    }

    float acc[4][4][4];
    #pragma unroll
    for (int a = 0; a < 4; a++)
        #pragma unroll
        for (int b = 0; b < 4; b++)
            #pragma unroll
            for (int c = 0; c < 4; c++) acc[a][b][c] = 0.f;

    const int lr = lane & 15, lc = lane >> 4;
    const uint32_t xa = (lr & 7) << 4;
    const uint32_t arow = (wm * 64 + lr) * 128 + lc * 16;
    const uint32_t brow = (wn * 32 + lr) * 128 + lc * 16;

    for (int i = 0; i < nk; i++) {
        CPWAIT1();
        __syncthreads();
        if (i + 2 < nk) {
            const uint32_t sst = ((i + 2) % 3) * STG;
            #pragma unroll
            for (int t = 0; t < 16; t++) CPA(so[t] + sst, gp[t] + (long)(i + 2) * 64);
        }
        CPCOMMIT();

        const uint32_t sa = st0 + (i % 3) * STG;
        #pragma unroll
        for (int kk = 0; kk < 4; kk++) {
            uint32_t af[4][4], al[4][4], bf_[4][2], bl[4][2];
            #pragma unroll
            for (int mi = 0; mi < 4; mi++) {
                uint32_t off = (arow + mi * 2048 + kk * 32) ^ xa;
                ldsm4(af[mi], sa + off);
                ldsm4(al[mi], sa + TILEB + off);
            }
            #pragma unroll
            for (int pi = 0; pi < 2; pi++) {
                uint32_t off = (brow + pi * 2048 + kk * 32) ^ xa;
                uint32_t t0[4], t1[4];
                ldsm4(t0, sa + 2 * TILEB + off);
                ldsm4(t1, sa + 3 * TILEB + off);
                bf_[2 * pi][0] = t0[0]; bf_[2 * pi + 1][0] = t0[1];
                bf_[2 * pi][1] = t0[2]; bf_[2 * pi + 1][1] = t0[3];
                bl[2 * pi][0] = t1[0]; bl[2 * pi + 1][0] = t1[1];
                bl[2 * pi][1] = t1[2]; bl[2 * pi + 1][1] = t1[3];
            }
            #pragma unroll
            for (int mi = 0; mi < 4; mi++)
                #pragma unroll
                for (int ni = 0; ni < 4; ni++) {
                    mma_bf16(acc[mi][ni], af[mi], bf_[ni]);
                    mma_bf16(acc[mi][ni], af[mi], bl[ni]);
                    mma_bf16(acc[mi][ni], al[mi], bf_[ni]);
                }
        }
    }

    // epilogue
    const int g = lane >> 2, tg = lane & 3;
    #pragma unroll
    for (int mi = 0; mi < 4; mi++) {
        #pragma unroll
        for (int ni = 0; ni < 4; ni++) {
            long m0 = bm + wm * 64 + mi * 16 + g;
            long n0 = bn + wn * 32 + ni * 8 + tg * 2;
            float v00 = alpha * acc[mi][ni][0], v01 = alpha * acc[mi][ni][1];
            float v10 = alpha * acc[mi][ni][2], v11 = alpha * acc[mi][ni][3];
            if (bias) {
                float bb0 = bias[n0], bb1 = bias[n0 + 1];
                v00 += bb0; v01 += bb1; v10 += bb0; v11 += bb1;
            }
            if (C) {
                *(float2*)(C + m0 * ldc + n0) = make_float2(v00, v01);
                *(float2*)(C + (m0 + 8) * ldc + n0) = make_float2(v10, v11);
            }
            if (Chi) {
                bf16 h0, l0, h1, l1;
                split2(v00, h0, l0); split2(v01, h1, l1);
                *(__nv_bfloat162*)(Chi + m0 * ldc + n0) = __nv_bfloat162(h0, h1);
                *(__nv_bfloat162*)(Clo + m0 * ldc + n0) = __nv_bfloat162(l0, l1);
                split2(v10, h0, l0); split2(v11, h1, l1);
                *(__nv_bfloat162*)(Chi + (m0 + 8) * ldc + n0) = __nv_bfloat162(h0, h1);
                *(__nv_bfloat162*)(Clo + (m0 + 8) * ldc + n0) = __nv_bfloat162(l0, l1);
            }
        }
    }
}

// ---------------- prep kernels ----------------
// transpose + scale + split: src R x C fp32 -> dst[(c)*ldd + coff + r] hi/lo
__global__ __launch_bounds__(256) void tsc(
    const float* __restrict__ src, bf16* __restrict__ dhi, bf16* __restrict__ dlo,
    int R, int C, long ldd, long coff, float s)
{
    __shared__ float t[32][33];
    int bx = blockIdx.x * 32, by = blockIdx.y * 32;
    int tx = threadIdx.x & 31, ty = threadIdx.x >> 5;
    #pragma unroll
    for (int i = 0; i < 32; i += 8)
        t[ty + i][tx] = src[(long)(by + ty + i) * C + bx + tx];
    __syncthreads();
    #pragma unroll
    for (int i = 0; i < 32; i += 8) {
        float v = s * t[tx][ty + i];
        bf16 h, l; split2(v, h, l);
        long o = (long)(bx + ty + i) * ldd + coff + by + tx;
        dhi[o] = h; dlo[o] = l;
    }
}
// elementwise scale + split
__global__ void sconv(const float* __restrict__ src, bf16* __restrict__ dhi,
                      bf16* __restrict__ dlo, long n, float s)
{
    long i = (long)blockIdx.x * 256 + threadIdx.x;
    if (i < n) {
        bf16 h, l; split2(s * src[i], h, l);
        dhi[i] = h; dlo[i] = l;
    }
}

// pairwise products -> PChi/PClo (stride KC)
__global__ void build_P0(const float* __restrict__ t, bf16* __restrict__ Ph, bf16* __restrict__ Pl) {
    int idx = blockIdx.x * 256 + threadIdx.x;
    int b = idx >> 14, uv = idx & (K0 - 1);
    int u = uv >> 7, v = uv & 127;
    const float* r = t + (long)b * DIMT;
    bf16 h, l; split2(r[u] * r[v], h, l);
    long o = (long)b * KC + uv; Ph[o] = h; Pl[o] = l;
}
__global__ void build_P1(const float* __restrict__ t, bf16* __restrict__ Ph, bf16* __restrict__ Pl) {
    int idx = blockIdx.x * 256 + threadIdx.x;
    int b = idx >> 12, uv = idx & (K1 - 1);
    int u = uv >> 6, v = uv & 63;
    const float* r = t + (long)b * DIMT + 128;
    float s = 0.f;
    #pragma unroll
    for (int m = 0; m < 3; m++) s += r[u * 3 + m] * r[v * 3 + m];
    bf16 h, l; split2(s, h, l);
    long o = (long)b * KC + K0 + uv; Ph[o] = h; Pl[o] = l;
}
__global__ void build_P2(const float* __restrict__ t, bf16* __restrict__ Ph, bf16* __restrict__ Pl) {
    int idx = blockIdx.x * 256 + threadIdx.x;
    int b = idx >> 10, uv = idx & (K2 - 1);
    int u = uv >> 5, v = uv & 31;
    const float* r = t + (long)b * DIMT + 320;
    float s = 0.f;
    #pragma unroll
    for (int m = 0; m < 5; m++) s += r[u * 5 + m] * r[v * 5 + m];
    bf16 h, l; split2(s, h, l);
    long o = (long)b * KC + K0 + K1 + uv; Ph[o] = h; Pl[o] = l;
}

// ---------------- block reduce ----------------
__device__ __forceinline__ float blockReduceSum(float val) {
    __shared__ float sh[8];
    int lane = threadIdx.x & 31, w = threadIdx.x >> 5;
    #pragma unroll
    for (int o = 16; o > 0; o >>= 1) val += __shfl_down_sync(0xffffffffu, val, o);
    __syncthreads();
    if (lane == 0) sh[w] = val;
    __syncthreads();
    float r = 0.f;
    if (threadIdx.x == 0) {
        int nw = blockDim.x >> 5;
        for (int i = 0; i < nw; i++) r += sh[i];
    }
    return r;
}

// ---------------- LayerNorm + SiLU forward ----------------
template<int PER>
__global__ __launch_bounds__(256) void ln_silu_fwd(
    const float* __restrict__ a, const float* __restrict__ gam, const float* __restrict__ bet,
    float* __restrict__ xh, float* __restrict__ rstd,
    float* __restrict__ h, bf16* __restrict__ hhi, bf16* __restrict__ hlo)
{
    const int D = PER * 256;
    int b = blockIdx.x, tid = threadIdx.x;
    const float* row = a + (long)b * D;
    float v[PER];
    float s = 0.f;
    #pragma unroll
    for (int i = 0; i < PER; i++) { v[i] = row[tid + (i << 8)]; s += v[i]; }
    s = blockReduceSum(s);
    __shared__ float bc;
    if (tid == 0) bc = s * (1.f / D);
    __syncthreads();
    float mu = bc;
    float q = 0.f;
    #pragma unroll
    for (int i = 0; i < PER; i++) { float d = v[i] - mu; q += d * d; }
    q = blockReduceSum(q);
    if (tid == 0) { float r = rsqrtf(q * (1.f / D) + 1e-6f); bc = r; rstd[b] = r; }
    __syncthreads();
    float r = bc;
    #pragma unroll
    for (int i = 0; i < PER; i++) {
        int c = tid + (i << 8);
        float x = (v[i] - mu) * r;
        xh[(long)b * D + c] = x;
        float z = x * gam[c] + bet[c];
        float sg = 1.f / (1.f + expf(-z));
        float hv = z * sg;
        if (h) h[(long)b * D + c] = hv;
        if (hhi) {
            bf16 hi, lo; split2(hv, hi, lo);
            hhi[(long)b * D + c] = hi; hlo[(long)b * D + c] = lo;
        }
    }
}

// ---------------- (SiLU + LN) backward ----------------
template<int PER>
__global__ __launch_bounds__(256) void ln_silu_bwd(
    const float* __restrict__ dh, const float* __restrict__ xhv_, const float* __restrict__ rstd,
    const float* __restrict__ gam, const float* __restrict__ bet,
    float* __restrict__ da, bf16* __restrict__ dahi, bf16* __restrict__ dalo)
{
    const int D = PER * 256;
    int b = blockIdx.x, tid = threadIdx.x;
    float xh[PER], dxh[PER];
    float s1 = 0.f, s2 = 0.f;
    #pragma unroll
    for (int i = 0; i < PER; i++) {
        int c = tid + (i << 8);
        float x = xhv_[(long)b * D + c];
        float z = x * gam[c] + bet[c];
        float sg = 1.f / (1.f + expf(-z));
        float ds = sg * (1.f + z * (1.f - sg));
        float up = dh ? dh[(long)b * D + c] : 1.f;
        float dx = up * ds * gam[c];
        xh[i] = x; dxh[i] = dx;
        s1 += dx; s2 += dx * x;
    }
    __shared__ float m1s, m2s;
    float t1 = blockReduceSum(s1);
    if (tid == 0) m1s = t1 * (1.f / D);
    float t2 = blockReduceSum(s2);
    if (tid == 0) m2s = t2 * (1.f / D);
    __syncthreads();
    float m1 = m1s, m2 = m2s, r = rstd[b];
    #pragma unroll
    for (int i = 0; i < PER; i++) {
        int c = tid + (i << 8);
        float dv = r * (dxh[i] - m1 - xh[i] * m2);
        if (da) da[(long)b * D + c] = dv;
        if (dahi) {
            bf16 hi, lo; split2(dv, hi, lo);
            dahi[(long)b * D + c] = hi; dalo[(long)b * D + c] = lo;
        }
    }
}

// ---------------- quadratic-form gradients -> y (dPC stride KC) ----------------
__global__ __launch_bounds__(128) void grad0(const float* __restrict__ dPc,
                                             const float* __restrict__ t, float* __restrict__ y)
{
    __shared__ float Ts[64][129];
    __shared__ float xs[128];
    int b = blockIdx.x, tid = threadIdx.x;
    xs[tid] = t[(long)b * DIMT + tid];
    float racc = 0.f, cacc = 0.f;
    for (int ch = 0; ch < 2; ch++) {
        __syncthreads();
        const float* P = dPc + (long)b * KC + ch * 64 * 128;
        for (int i = tid; i < 2048; i += 128) {
            float4 v = *(const float4*)(P + i * 4);
            int r = (i * 4) >> 7, c = (i * 4) & 127;
            Ts[r][c] = v.x; Ts[r][c + 1] = v.y; Ts[r][c + 2] = v.z; Ts[r][c + 3] = v.w;
        }
        __syncthreads();
        int u = tid;
        if ((u >> 6) == ch) {
            int ul = u & 63;
            float s = 0.f;
            #pragma unroll 8
            for (int v = 0; v < 128; v++) s += Ts[ul][v] * xs[v];
            racc = s;
        }
        float s = 0.f;
        #pragma unroll 8
        for (int up = 0; up < 64; up++) s += Ts[up][u] * xs[ch * 64 + up];
        cacc += s;
    }
    y[(long)b * DIMT + tid] = racc + cacc;
}

__global__ __launch_bounds__(192) void grad1(const float* __restrict__ dPc,
                                             const float* __restrict__ t, float* __restrict__ y)
{
    __shared__ float Ts[64][65];
    __shared__ float xs[192];
    int b = blockIdx.x, tid = threadIdx.x;
    const float* P = dPc + (long)b * KC + K0;
    for (int i = tid; i < 4096; i += 192) Ts[i >> 6][i & 63] = P[i];
    xs[tid] = t[(long)b * DIMT + 128 + tid];
    __syncthreads();
    int u = tid / 3, m = tid - u * 3;
    float s = 0.f;
    #pragma unroll 8
    for (int v = 0; v < 64; v++) s += (Ts[u][v] + Ts[v][u]) * xs[v * 3 + m];
    y[(long)b * DIMT + 128 + tid] = s;
}

__global__ __launch_bounds__(160) void grad2(const float* __restrict__ dPc,
                                             const float* __restrict__ t, float* __restrict__ y)
{
    __shared__ float Ts[32][33];
    __shared__ float xs[160];
    int b = blockIdx.x, tid = threadIdx.x;
    const float* P = dPc + (long)b * KC + K0 + K1;
    for (int i = tid; i < 1024; i += 160) Ts[i >> 5][i & 31] = P[i];
    xs[tid] = t[(long)b * DIMT + 320 + tid];
    __syncthreads();
    int u = tid / 5, m = tid - u * 5;
    float s = 0.f;
    #pragma unroll 8
    for (int v = 0; v < 32; v++) s += (Ts[u][v] + Ts[v][u]) * xs[v * 5 + m];
    y[(long)b * DIMT + 320 + tid] = s;
}

// ---------------- launch ----------------
extern "C" void kernel_launch(void* const* d_in, const int* in_sizes, int n_in,
                              void* d_out, int out_size)
{
    const float* tin = (const float*)d_in[0];
    const float* w0  = (const float*)d_in[1];
    const float* w1  = (const float*)d_in[2];
    const float* w2  = (const float*)d_in[3];
    const float* W1  = (const float*)d_in[4];
    const float* b1  = (const float*)d_in[5];
    const float* g1  = (const float*)d_in[6];
    const float* be1 = (const float*)d_in[7];
    const float* W2  = (const float*)d_in[8];
    const float* b2  = (const float*)d_in[9];
    const float* g2  = (const float*)d_in[10];
    const float* be2 = (const float*)d_in[11];

    float* out  = (float*)d_out;
    float* xout = out;
    float* yout = out + (long)NB * ZD;

    bf16* hb = nullptr; float* fb = nullptr;
    cudaGetSymbolAddress((void**)&hb, g_hbuf);
    cudaGetSymbolAddress((void**)&fb, g_fbuf);

    bf16 *PChi = hb + B_PCHI, *PClo = hb + B_PCLO;
    bf16 *WThi = hb + B_WTHI, *WTlo = hb + B_WTLO;
    bf16 *WChi = hb + B_WCHI, *WClo = hb + B_WCLO;
    bf16 *W1Thi= hb + B_W1THI,*W1Tlo= hb + B_W1TLO;
    bf16 *W1hi = hb + B_W1HI, *W1lo = hb + B_W1LO;
    bf16 *W2Thi= hb + B_W2THI,*W2Tlo= hb + B_W2TLO;
    bf16 *W2hi = hb + B_W2HI, *W2lo = hb + B_W2LO;
    bf16 *ehi  = hb + B_EHI,  *elo  = hb + B_ELO;
    bf16 *h1hi = hb + B_H1HI, *h1lo = hb + B_H1LO;
    bf16 *da2hi= hb + B_DA2HI,*da2lo= hb + B_DA2LO;
    bf16 *da1hi= hb + B_DA1HI,*da1lo= hb + B_DA1LO;
    bf16 *dehi = hb + B_DEHI, *delo = hb + B_DELO;

    float *dPC = fb + F_DPC, *a1 = fb + F_A1, *xh1 = fb + F_XH1;
    float *a2  = fb + F_A2,  *xh2= fb + F_XH2, *dh1 = fb + F_DH1;
    float *rs1 = fb + F_RS1, *rs2= fb + F_RS2;

    const float s0 = 1.0f / sqrtf(21504.0f);
    const float s1 = s0 / sqrtf(3.0f);
    const float s2 = s0 / sqrtf(5.0f);

    cudaFuncSetAttribute(bf_gemm_nt, cudaFuncAttributeMaxDynamicSharedMemorySize, GSMEM);

    // ---- prep: weight transposes/scales + splits ----
    tsc<<<dim3(HID / 32, K0 / 32), 256>>>(w0, WThi, WTlo, K0, HID, KC, 0, s0);
    tsc<<<dim3(HID / 32, K1 / 32), 256>>>(w1, WThi, WTlo, K1, HID, KC, K0, s1);
    tsc<<<dim3(HID / 32, K2 / 32), 256>>>(w2, WThi, WTlo, K2, HID, KC, K0 + K1, s2);
    tsc<<<dim3(HID / 32, HID / 32), 256>>>(W1, W1Thi, W1Tlo, HID, HID, HID, 0, 1.f);
    tsc<<<dim3(ZD / 32, HID / 32), 256>>>(W2, W2Thi, W2Tlo, HID, ZD, HID, 0, 1.f);
    sconv<<<(int)(((long)K0 * HID + 255) / 256), 256>>>(w0, WChi, WClo, (long)K0 * HID, s0);
    sconv<<<(int)(((long)K1 * HID + 255) / 256), 256>>>(w1, WChi + (long)K0 * HID, WClo + (long)K0 * HID, (long)K1 * HID, s1);
    sconv<<<(int)(((long)K2 * HID + 255) / 256), 256>>>(w2, WChi + (long)(K0 + K1) * HID, WClo + (long)(K0 + K1) * HID, (long)K2 * HID, s2);
    sconv<<<(int)((HH + 255) / 256), 256>>>(W1, W1hi, W1lo, HH, 1.f);
    sconv<<<(int)((ZH + 255) / 256), 256>>>(W2, W2hi, W2lo, ZH, 1.f);
    build_P0<<<(int)((long)NB * K0 / 256), 256>>>(tin, PChi, PClo);
    build_P1<<<(int)((long)NB * K1 / 256), 256>>>(tin, PChi, PClo);
    build_P2<<<(int)((long)NB * K2 / 256), 256>>>(tin, PChi, PClo);

    // ---- forward ----
    bf_gemm_nt<<<dim3(HID / 128, NB / 128), 256, GSMEM>>>(
        PChi, PClo, WThi, WTlo, nullptr, ehi, elo, KC, HID, 1.f, nullptr);
    bf_gemm_nt<<<dim3(HID / 128, NB / 128), 256, GSMEM>>>(
        ehi, elo, W1Thi, W1Tlo, a1, nullptr, nullptr, HID, HID, 1.f, b1);
    ln_silu_fwd<4><<<NB, 256>>>(a1, g1, be1, xh1, rs1, nullptr, h1hi, h1lo);
    bf_gemm_nt<<<dim3(ZD / 128, NB / 128), 256, GSMEM>>>(
        h1hi, h1lo, W2Thi, W2Tlo, a2, nullptr, nullptr, HID, ZD, 1.f, b2);
    ln_silu_fwd<1><<<NB, 256>>>(a2, g2, be2, xh2, rs2, xout, nullptr, nullptr);

    // ---- backward ----
    ln_silu_bwd<1><<<NB, 256>>>(nullptr, xh2, rs2, g2, be2, nullptr, da2hi, da2lo);
    bf_gemm_nt<<<dim3(HID / 128, NB / 128), 256, GSMEM>>>(
        da2hi, da2lo, W2hi, W2lo, dh1, nullptr, nullptr, ZD, HID, 1.f, nullptr);
    ln_silu_bwd<4><<<NB, 256>>>(dh1, xh1, rs1, g1, be1, nullptr, da1hi, da1lo);
    bf_gemm_nt<<<dim3(HID / 128, NB / 128), 256, GSMEM>>>(
        da1hi, da1lo, W1hi, W1lo, nullptr, dehi, delo, HID, HID, 1.f, nullptr);
    bf_gemm_nt<<<dim3(KC / 128, NB / 128), 256, GSMEM>>>(
        dehi, delo, WChi, WClo, dPC, nullptr, nullptr, HID, KC, 1.f, nullptr);

    grad0<<<NB, 128>>>(dPC, tin, yout);
    grad1<<<NB, 192>>>(dPC, tin, yout);
    grad2<<<NB, 160>>>(dPC, tin, yout);
}

// round 6
// speedup vs baseline: 4.0831x; 1.5837x over previous
#include <cuda_runtime.h>
#include <cuda_bf16.h>
#include <math.h>
#include <stdint.h>

#define NB   2048
#define DIMT 480
#define HID  1024
#define ZD   256
// packed symmetric pair counts
#define T0   8256
#define KP0  8256
#define T1   2080
#define KP1  2112
#define T2   528
#define KP2  640
#define KCP  11008      // KP0+KP1+KP2, multiple of 128
#define S1   8256
#define S2   10368

typedef __nv_bfloat16 bf16;

// ---------------- scratch pools ----------------
constexpr long NBKC = (long)NB * KCP;
constexpr long HKC  = (long)HID * KCP;
constexpr long HH   = (long)HID * HID;
constexpr long ZH   = (long)ZD * HID;
constexpr long NH   = (long)NB * HID;
constexpr long NZ   = (long)NB * ZD;

constexpr long B_PCHI = 0;
constexpr long B_PCLO = B_PCHI + NBKC;
constexpr long B_WTHI = B_PCLO + NBKC;   // packed-T [HID, KCP]
constexpr long B_WTLO = B_WTHI + HKC;
constexpr long B_WPHI = B_WTLO + HKC;    // packed   [KCP, HID]
constexpr long B_WPLO = B_WPHI + HKC;
constexpr long B_W1THI= B_WPLO + HKC;
constexpr long B_W1TLO= B_W1THI + HH;
constexpr long B_W1HI = B_W1TLO + HH;
constexpr long B_W1LO = B_W1HI + HH;
constexpr long B_W2THI= B_W1LO + HH;
constexpr long B_W2TLO= B_W2THI + ZH;
constexpr long B_W2HI = B_W2TLO + ZH;
constexpr long B_W2LO = B_W2HI + ZH;
constexpr long B_EHI  = B_W2LO + ZH;
constexpr long B_ELO  = B_EHI + NH;
constexpr long B_H1HI = B_ELO + NH;
constexpr long B_H1LO = B_H1HI + NH;
constexpr long B_DA2HI= B_H1LO + NH;
constexpr long B_DA2LO= B_DA2HI + NZ;
constexpr long B_DA1HI= B_DA2LO + NZ;
constexpr long B_DA1LO= B_DA1HI + NH;
constexpr long B_DEHI = B_DA1LO + NH;
constexpr long B_DELO = B_DEHI + NH;
constexpr long B_TOT  = B_DELO + NH;

constexpr long F_DPC  = 0;
constexpr long F_A1   = F_DPC + NBKC;
constexpr long F_XH1  = F_A1  + NH;
constexpr long F_A2   = F_XH1 + NH;
constexpr long F_XH2  = F_A2  + NZ;
constexpr long F_DH1  = F_XH2 + NZ;
constexpr long F_RS1  = F_DH1 + NH;
constexpr long F_RS2  = F_RS1 + NB;
constexpr long F_TOT  = F_RS2 + NB;

__device__ bf16     g_hbuf[B_TOT];
__device__ float    g_fbuf[F_TOT];
__device__ uint32_t g_uv[KCP];

// ---------------- helpers ----------------
__device__ __forceinline__ uint32_t smem_u32(const void* p) {
    uint32_t a;
    asm("{ .reg .u64 t; cvta.to.shared.u64 t, %1; cvt.u32.u64 %0, t; }" : "=r"(a) : "l"(p));
    return a;
}
__device__ __forceinline__ void ldsm4(uint32_t* r, uint32_t a) {
    asm volatile("ldmatrix.sync.aligned.m8n8.x4.shared.b16 {%0,%1,%2,%3},[%4];"
                 : "=r"(r[0]), "=r"(r[1]), "=r"(r[2]), "=r"(r[3]) : "r"(a));
}
__device__ __forceinline__ void mma_bf16(float* d, const uint32_t* a, const uint32_t* b) {
    asm volatile("mma.sync.aligned.m16n8k16.row.col.f32.bf16.bf16.f32 "
                 "{%0,%1,%2,%3},{%4,%5,%6,%7},{%8,%9},{%0,%1,%2,%3};"
                 : "+f"(d[0]), "+f"(d[1]), "+f"(d[2]), "+f"(d[3])
                 : "r"(a[0]), "r"(a[1]), "r"(a[2]), "r"(a[3]), "r"(b[0]), "r"(b[1]));
}
#define CPA(dst, src) asm volatile("cp.async.cg.shared.global [%0], [%1], 16;" :: "r"(dst), "l"(src) : "memory")
#define CPCOMMIT()    asm volatile("cp.async.commit_group;" ::: "memory")
#define CPWAIT1()     asm volatile("cp.async.wait_group 1;" ::: "memory")

__device__ __forceinline__ void split2(float v, bf16& h, bf16& l) {
    h = __float2bfloat16(v);
    l = __float2bfloat16(v - __bfloat162float(h));
}

// ---------------- pair LUT ----------------
__global__ void uv_init() {
    int p = blockIdx.x * 256 + threadIdx.x;
    if (p >= KCP) return;
    int n, lp, T;
    if (p < S1)      { n = 128; lp = p;      T = T0; }
    else if (p < S2) { n = 64;  lp = p - S1; T = T1; }
    else             { n = 32;  lp = p - S2; T = T2; }
    if (lp >= T) { g_uv[p] = 0u; return; }
    float tn = 2.f * n + 1.f;
    int u = (int)((tn - sqrtf(tn * tn - 8.f * lp)) * 0.5f);
    if (u < 0) u = 0; if (u > n - 1) u = n - 1;
    while (u > 0 && u * n - u * (u - 1) / 2 > lp) u--;
    while (u < n - 1 && (u + 1) * n - (u + 1) * u / 2 <= lp) u++;
    int v = u + (lp - (u * n - u * (u - 1) / 2));
    g_uv[p] = ((uint32_t)u << 16) | (uint32_t)v;
}

// ---------------- bf16 split NT GEMM (unchanged from R5) ----------------
#define TILEB 16384
#define STG   (4 * TILEB)
#define GSMEM (3 * STG + 1024)

__global__ __launch_bounds__(256, 1) void bf_gemm_nt(
    const bf16* __restrict__ Ahi, const bf16* __restrict__ Alo,
    const bf16* __restrict__ Bhi, const bf16* __restrict__ Blo,
    float* __restrict__ C, bf16* __restrict__ Chi, bf16* __restrict__ Clo,
    int K, long ldc, float alpha, const float* __restrict__ bias)
{
    extern __shared__ char smem[];
    const uint32_t st0 = (smem_u32(smem) + 1023) & ~1023u;
    const int tid = threadIdx.x, wid = tid >> 5, lane = tid & 31;
    const int wm = wid >> 2, wn = wid & 3;
    const long bm = (long)blockIdx.y * 128, bn = (long)blockIdx.x * 128;

    const bf16* gp[16];
    uint32_t so[16];
    #pragma unroll
    for (int t = 0; t < 16; t++) {
        int q = tid + (t & 3) * 256;
        int r = q >> 3, c = q & 7;
        int tile = t >> 2;
        const bf16* base = (tile == 0) ? Ahi : (tile == 1) ? Alo : (tile == 2) ? Bhi : Blo;
        long row = (tile < 2 ? bm : bn) + r;
        gp[t] = base + row * K + c * 8;
        so[t] = st0 + tile * TILEB + ((r * 128 + c * 16) ^ ((r & 7) << 4));
    }
    const int nk = K >> 6;

    #pragma unroll
    for (int p = 0; p < 2; p++) {
        #pragma unroll
        for (int t = 0; t < 16; t++) CPA(so[t] + p * STG, gp[t] + (long)p * 64);
        CPCOMMIT();
    }

    float acc[4][4][4];
    #pragma unroll
    for (int a = 0; a < 4; a++)
        #pragma unroll
        for (int b = 0; b < 4; b++)
            #pragma unroll
            for (int c = 0; c < 4; c++) acc[a][b][c] = 0.f;

    const int lr = lane & 15, lc = lane >> 4;
    const uint32_t xa = (lr & 7) << 4;
    const uint32_t arow = (wm * 64 + lr) * 128 + lc * 16;
    const uint32_t brow = (wn * 32 + lr) * 128 + lc * 16;

    for (int i = 0; i < nk; i++) {
        CPWAIT1();
        __syncthreads();
        if (i + 2 < nk) {
            const uint32_t sst = ((i + 2) % 3) * STG;
            #pragma unroll
            for (int t = 0; t < 16; t++) CPA(so[t] + sst, gp[t] + (long)(i + 2) * 64);
        }
        CPCOMMIT();

        const uint32_t sa = st0 + (i % 3) * STG;
        #pragma unroll
        for (int kk = 0; kk < 4; kk++) {
            uint32_t af[4][4], al[4][4], bf_[4][2], bl[4][2];
            #pragma unroll
            for (int mi = 0; mi < 4; mi++) {
                uint32_t off = (arow + mi * 2048 + kk * 32) ^ xa;
                ldsm4(af[mi], sa + off);
                ldsm4(al[mi], sa + TILEB + off);
            }
            #pragma unroll
            for (int pi = 0; pi < 2; pi++) {
                uint32_t off = (brow + pi * 2048 + kk * 32) ^ xa;
                uint32_t t0[4], t1[4];
                ldsm4(t0, sa + 2 * TILEB + off);
                ldsm4(t1, sa + 3 * TILEB + off);
                bf_[2 * pi][0] = t0[0]; bf_[2 * pi + 1][0] = t0[1];
                bf_[2 * pi][1] = t0[2]; bf_[2 * pi + 1][1] = t0[3];
                bl[2 * pi][0] = t1[0]; bl[2 * pi + 1][0] = t1[1];
                bl[2 * pi][1] = t1[2]; bl[2 * pi + 1][1] = t1[3];
            }
            #pragma unroll
            for (int mi = 0; mi < 4; mi++)
                #pragma unroll
                for (int ni = 0; ni < 4; ni++) {
                    mma_bf16(acc[mi][ni], af[mi], bf_[ni]);
                    mma_bf16(acc[mi][ni], af[mi], bl[ni]);
                    mma_bf16(acc[mi][ni], al[mi], bf_[ni]);
                }
        }
    }

    const int g = lane >> 2, tg = lane & 3;
    #pragma unroll
    for (int mi = 0; mi < 4; mi++) {
        #pragma unroll
        for (int ni = 0; ni < 4; ni++) {
            long m0 = bm + wm * 64 + mi * 16 + g;
            long n0 = bn + wn * 32 + ni * 8 + tg * 2;
            float v00 = alpha * acc[mi][ni][0], v01 = alpha * acc[mi][ni][1];
            float v10 = alpha * acc[mi][ni][2], v11 = alpha * acc[mi][ni][3];
            if (bias) {
                float bb0 = bias[n0], bb1 = bias[n0 + 1];
                v00 += bb0; v01 += bb1; v10 += bb0; v11 += bb1;
            }
            if (C) {
                *(float2*)(C + m0 * ldc + n0) = make_float2(v00, v01);
                *(float2*)(C + (m0 + 8) * ldc + n0) = make_float2(v10, v11);
            }
            if (Chi) {
                bf16 h0, l0, h1, l1;
                split2(v00, h0, l0); split2(v01, h1, l1);
                *(__nv_bfloat162*)(Chi + m0 * ldc + n0) = __nv_bfloat162(h0, h1);
                *(__nv_bfloat162*)(Clo + m0 * ldc + n0) = __nv_bfloat162(l0, l1);
                split2(v10, h0, l0); split2(v11, h1, l1);
                *(__nv_bfloat162*)(Chi + (m0 + 8) * ldc + n0) = __nv_bfloat162(h0, h1);
                *(__nv_bfloat162*)(Clo + (m0 + 8) * ldc + n0) = __nv_bfloat162(l0, l1);
            }
        }
    }
}

// ---------------- packed weight prep ----------------
// wpack [KCP, HID]: row kbase+p, col h = s*(w[u,v,h] (+ w[v,u,h] if u!=v))
__global__ void pack_nt(const float* __restrict__ w, bf16* __restrict__ dhi,
                        bf16* __restrict__ dlo, int n, int T, int KP, long kbase, float s)
{
    long idx = (long)blockIdx.x * 256 + threadIdx.x;
    if (idx >= (long)KP * HID) return;
    int p = (int)(idx / HID), h = (int)(idx % HID);
    float val = 0.f;
    if (p < T) {
        uint32_t uv = g_uv[kbase + p];
        int u = uv >> 16, v = uv & 0xffff;
        val = w[((long)u * n + v) * HID + h];
        if (u != v) val += w[((long)v * n + u) * HID + h];
        val *= s;
    }
    bf16 hh, ll; split2(val, hh, ll);
    long o = (kbase + p) * HID + h;
    dhi[o] = hh; dlo[o] = ll;
}

// wpackT [HID, KCP]: row h, col kbase+p (smem transpose)
__global__ __launch_bounds__(256) void pack_t(
    const float* __restrict__ w, bf16* __restrict__ dhi, bf16* __restrict__ dlo,
    int n, int T, int KP, long kbase, float s)
{
    __shared__ float sv[32][33];
    int pb = blockIdx.x * 32, hb = blockIdx.y * 32;
    int tx = threadIdx.x & 31, ty = threadIdx.x >> 5;
    #pragma unroll
    for (int i = 0; i < 32; i += 8) {
        int pp = pb + ty + i;
        float val = 0.f;
        if (pp < T) {
            uint32_t uv = g_uv[kbase + pp];
            int u = uv >> 16, v = uv & 0xffff;
            val = w[((long)u * n + v) * HID + hb + tx];
            if (u != v) val += w[((long)v * n + u) * HID + hb + tx];
            val *= s;
        }
        sv[ty + i][tx] = val;
    }
    __syncthreads();
    #pragma unroll
    for (int i = 0; i < 32; i += 8) {
        float val = sv[tx][ty + i];
        bf16 hh, ll; split2(val, hh, ll);
        long o = (long)(hb + ty + i) * KCP + kbase + pb + tx;
        dhi[o] = hh; dlo[o] = ll;
    }
}

// dense transpose+split (W1T, W2T)
__global__ __launch_bounds__(256) void tsc(
    const float* __restrict__ src, bf16* __restrict__ dhi, bf16* __restrict__ dlo,
    int R, int C, long ldd)
{
    __shared__ float t[32][33];
    int bx = blockIdx.x * 32, by = blockIdx.y * 32;
    int tx = threadIdx.x & 31, ty = threadIdx.x >> 5;
    #pragma unroll
    for (int i = 0; i < 32; i += 8)
        t[ty + i][tx] = src[(long)(by + ty + i) * C + bx + tx];
    __syncthreads();
    #pragma unroll
    for (int i = 0; i < 32; i += 8) {
        bf16 h, l; split2(t[tx][ty + i], h, l);
        long o = (long)(bx + ty + i) * ldd + by + tx;
        dhi[o] = h; dlo[o] = l;
    }
}
__global__ void sconv(const float* __restrict__ src, bf16* __restrict__ dhi,
                      bf16* __restrict__ dlo, long n)
{
    long i = (long)blockIdx.x * 256 + threadIdx.x;
    if (i < n) {
        bf16 h, l; split2(src[i], h, l);
        dhi[i] = h; dlo[i] = l;
    }
}

// ---------------- packed pairwise products ----------------
__global__ void build_Pp(const float* __restrict__ t, bf16* __restrict__ Ph,
                         bf16* __restrict__ Pl, int nm, int xoff, int T, int KP, long kbase)
{
    long idx = (long)blockIdx.x * 256 + threadIdx.x;
    if (idx >= (long)NB * KP) return;
    int b = (int)(idx / KP), p = (int)(idx % KP);
    float val = 0.f;
    if (p < T) {
        uint32_t uv = g_uv[kbase + p];
        int u = uv >> 16, v = uv & 0xffff;
        const float* r = t + (long)b * DIMT + xoff;
        for (int m = 0; m < nm; m++) val += r[u * nm + m] * r[v * nm + m];
    }
    bf16 hh, ll; split2(val, hh, ll);
    long o = (long)b * KCP + kbase + p;
    Ph[o] = hh; Pl[o] = ll;
}

// ---------------- block reduce ----------------
__device__ __forceinline__ float blockReduceSum(float val) {
    __shared__ float sh[8];
    int lane = threadIdx.x & 31, w = threadIdx.x >> 5;
    #pragma unroll
    for (int o = 16; o > 0; o >>= 1) val += __shfl_down_sync(0xffffffffu, val, o);
    __syncthreads();
    if (lane == 0) sh[w] = val;
    __syncthreads();
    float r = 0.f;
    if (threadIdx.x == 0) {
        int nw = blockDim.x >> 5;
        for (int i = 0; i < nw; i++) r += sh[i];
    }
    return r;
}

// ---------------- LayerNorm + SiLU forward ----------------
template<int PER>
__global__ __launch_bounds__(256) void ln_silu_fwd(
    const float* __restrict__ a, const float* __restrict__ gam, const float* __restrict__ bet,
    float* __restrict__ xh, float* __restrict__ rstd,
    float* __restrict__ h, bf16* __restrict__ hhi, bf16* __restrict__ hlo)
{
    const int D = PER * 256;
    int b = blockIdx.x, tid = threadIdx.x;
    const float* row = a + (long)b * D;
    float v[PER];
    float s = 0.f;
    #pragma unroll
    for (int i = 0; i < PER; i++) { v[i] = row[tid + (i << 8)]; s += v[i]; }
    s = blockReduceSum(s);
    __shared__ float bc;
    if (tid == 0) bc = s * (1.f / D);
    __syncthreads();
    float mu = bc;
    float q = 0.f;
    #pragma unroll
    for (int i = 0; i < PER; i++) { float d = v[i] - mu; q += d * d; }
    q = blockReduceSum(q);
    if (tid == 0) { float r = rsqrtf(q * (1.f / D) + 1e-6f); bc = r; rstd[b] = r; }
    __syncthreads();
    float r = bc;
    #pragma unroll
    for (int i = 0; i < PER; i++) {
        int c = tid + (i << 8);
        float x = (v[i] - mu) * r;
        xh[(long)b * D + c] = x;
        float z = x * gam[c] + bet[c];
        float sg = 1.f / (1.f + expf(-z));
        float hv = z * sg;
        if (h) h[(long)b * D + c] = hv;
        if (hhi) {
            bf16 hi, lo; split2(hv, hi, lo);
            hhi[(long)b * D + c] = hi; hlo[(long)b * D + c] = lo;
        }
    }
}

// ---------------- (SiLU + LN) backward ----------------
template<int PER>
__global__ __launch_bounds__(256) void ln_silu_bwd(
    const float* __restrict__ dh, const float* __restrict__ xhv_, const float* __restrict__ rstd,
    const float* __restrict__ gam, const float* __restrict__ bet,
    float* __restrict__ da, bf16* __restrict__ dahi, bf16* __restrict__ dalo)
{
    const int D = PER * 256;
    int b = blockIdx.x, tid = threadIdx.x;
    float xh[PER], dxh[PER];
    float s1 = 0.f, s2 = 0.f;
    #pragma unroll
    for (int i = 0; i < PER; i++) {
        int c = tid + (i << 8);
        float x = xhv_[(long)b * D + c];
        float z = x * gam[c] + bet[c];
        float sg = 1.f / (1.f + expf(-z));
        float ds = sg * (1.f + z * (1.f - sg));
        float up = dh ? dh[(long)b * D + c] : 1.f;
        float dx = up * ds * gam[c];
        xh[i] = x; dxh[i] = dx;
        s1 += dx; s2 += dx * x;
    }
    __shared__ float m1s, m2s;
    float t1 = blockReduceSum(s1);
    if (tid == 0) m1s = t1 * (1.f / D);
    float t2 = blockReduceSum(s2);
    if (tid == 0) m2s = t2 * (1.f / D);
    __syncthreads();
    float m1 = m1s, m2 = m2s, r = rstd[b];
    #pragma unroll
    for (int i = 0; i < PER; i++) {
        int c = tid + (i << 8);
        float dv = r * (dxh[i] - m1 - xh[i] * m2);
        if (da) da[(long)b * D + c] = dv;
        if (dahi) {
            bf16 hi, lo; split2(dv, hi, lo);
            dahi[(long)b * D + c] = hi; dalo[(long)b * D + c] = lo;
        }
    }
}

// ---------------- packed quadratic-form gradients -> y ----------------
__global__ __launch_bounds__(128) void grad0(const float* __restrict__ dPc,
                                             const float* __restrict__ t, float* __restrict__ y)
{
    extern __shared__ float Ts[];   // 128*129 + 128
    float* xs = Ts + 128 * 129;
    int b = blockIdx.x, tid = threadIdx.x;
    xs[tid] = t[(long)b * DIMT + tid];
    const float* P = dPc + (long)b * KCP;
    for (int i = tid; i < T0; i += 128) {
        uint32_t uv = g_uv[i];
        int u = uv >> 16, v = uv & 0xffff;
        float val = P[i];
        Ts[u * 129 + v] = val;
        Ts[v * 129 + u] = (u == v) ? 2.f * val : val;
    }
    __syncthreads();
    float s = 0.f;
    #pragma unroll 8
    for (int v = 0; v < 128; v++) s += Ts[tid * 129 + v] * xs[v];
    y[(long)b * DIMT + tid] = s;
}

__global__ __launch_bounds__(192) void grad1(const float* __restrict__ dPc,
                                             const float* __restrict__ t, float* __restrict__ y)
{
    __shared__ float Ts[64][65];
    __shared__ float xs[192];
    int b = blockIdx.x, tid = threadIdx.x;
    xs[tid] = t[(long)b * DIMT + 128 + tid];
    const float* P = dPc + (long)b * KCP + S1;
    for (int i = tid; i < T1; i += 192) {
        uint32_t uv = g_uv[S1 + i];
        int u = uv >> 16, v = uv & 0xffff;
        float val = P[i];
        Ts[u][v] = val;
        Ts[v][u] = (u == v) ? 2.f * val : val;
    }
    __syncthreads();
    int u = tid / 3, m = tid - u * 3;
    float s = 0.f;
    #pragma unroll 8
    for (int v = 0; v < 64; v++) s += Ts[u][v] * xs[v * 3 + m];
    y[(long)b * DIMT + 128 + tid] = s;
}

__global__ __launch_bounds__(160) void grad2(const float* __restrict__ dPc,
                                             const float* __restrict__ t, float* __restrict__ y)
{
    __shared__ float Ts[32][33];
    __shared__ float xs[160];
    int b = blockIdx.x, tid = threadIdx.x;
    xs[tid] = t[(long)b * DIMT + 320 + tid];
    const float* P = dPc + (long)b * KCP + S2;
    for (int i = tid; i < T2; i += 160) {
        uint32_t uv = g_uv[S2 + i];
        int u = uv >> 16, v = uv & 0xffff;
        float val = P[i];
        Ts[u][v] = val;
        Ts[v][u] = (u == v) ? 2.f * val : val;
    }
    __syncthreads();
    int u = tid / 5, m = tid - u * 5;
    float s = 0.f;
    #pragma unroll 8
    for (int v = 0; v < 32; v++) s += Ts[u][v] * xs[v * 5 + m];
    y[(long)b * DIMT + 320 + tid] = s;
}

// ---------------- launch ----------------
extern "C" void kernel_launch(void* const* d_in, const int* in_sizes, int n_in,
                              void* d_out, int out_size)
{
    const float* tin = (const float*)d_in[0];
    const float* w0  = (const float*)d_in[1];
    const float* w1  = (const float*)d_in[2];
    const float* w2  = (const float*)d_in[3];
    const float* W1  = (const float*)d_in[4];
    const float* b1  = (const float*)d_in[5];
    const float* g1  = (const float*)d_in[6];
    const float* be1 = (const float*)d_in[7];
    const float* W2  = (const float*)d_in[8];
    const float* b2  = (const float*)d_in[9];
    const float* g2  = (const float*)d_in[10];
    const float* be2 = (const float*)d_in[11];

    float* out  = (float*)d_out;
    float* xout = out;
    float* yout = out + (long)NB * ZD;

    bf16* hb = nullptr; float* fb = nullptr;
    cudaGetSymbolAddress((void**)&hb, g_hbuf);
    cudaGetSymbolAddress((void**)&fb, g_fbuf);

    bf16 *PChi = hb + B_PCHI, *PClo = hb + B_PCLO;
    bf16 *WThi = hb + B_WTHI, *WTlo = hb + B_WTLO;
    bf16 *WPhi = hb + B_WPHI, *WPlo = hb + B_WPLO;
    bf16 *W1Thi= hb + B_W1THI,*W1Tlo= hb + B_W1TLO;
    bf16 *W1hi = hb + B_W1HI, *W1lo = hb + B_W1LO;
    bf16 *W2Thi= hb + B_W2THI,*W2Tlo= hb + B_W2TLO;
    bf16 *W2hi = hb + B_W2HI, *W2lo = hb + B_W2LO;
    bf16 *ehi  = hb + B_EHI,  *elo  = hb + B_ELO;
    bf16 *h1hi = hb + B_H1HI, *h1lo = hb + B_H1LO;
    bf16 *da2hi= hb + B_DA2HI,*da2lo= hb + B_DA2LO;
    bf16 *da1hi= hb + B_DA1HI,*da1lo= hb + B_DA1LO;
    bf16 *dehi = hb + B_DEHI, *delo = hb + B_DELO;

    float *dPC = fb + F_DPC, *a1 = fb + F_A1, *xh1 = fb + F_XH1;
    float *a2  = fb + F_A2,  *xh2= fb + F_XH2, *dh1 = fb + F_DH1;
    float *rs1 = fb + F_RS1, *rs2= fb + F_RS2;

    const float s0 = 1.0f / sqrtf(21504.0f);
    const float s1 = s0 / sqrtf(3.0f);
    const float s2 = s0 / sqrtf(5.0f);

    cudaFuncSetAttribute(bf_gemm_nt, cudaFuncAttributeMaxDynamicSharedMemorySize, GSMEM);
    cudaFuncSetAttribute(grad0, cudaFuncAttributeMaxDynamicSharedMemorySize, 128 * 129 * 4 + 512);

    // ---- prep ----
    uv_init<<<(KCP + 255) / 256, 256>>>();
    pack_t<<<dim3(KP0 / 32, HID / 32), 256>>>(w0, WThi, WTlo, 128, T0, KP0, 0, s0);
    pack_t<<<dim3(KP1 / 32, HID / 32), 256>>>(w1, WThi, WTlo, 64, T1, KP1, S1, s1);
    pack_t<<<dim3(KP2 / 32, HID / 32), 256>>>(w2, WThi, WTlo, 32, T2, KP2, S2, s2);
    pack_nt<<<(int)(((long)KP0 * HID + 255) / 256), 256>>>(w0, WPhi, WPlo, 128, T0, KP0, 0, s0);
    pack_nt<<<(int)(((long)KP1 * HID + 255) / 256), 256>>>(w1, WPhi, WPlo, 64, T1, KP1, S1, s1);
    pack_nt<<<(int)(((long)KP2 * HID + 255) / 256), 256>>>(w2, WPhi, WPlo, 32, T2, KP2, S2, s2);
    tsc<<<dim3(HID / 32, HID / 32), 256>>>(W1, W1Thi, W1Tlo, HID, HID, HID);
    tsc<<<dim3(ZD / 32, HID / 32), 256>>>(W2, W2Thi, W2Tlo, HID, ZD, HID);
    sconv<<<(int)((HH + 255) / 256), 256>>>(W1, W1hi, W1lo, HH);
    sconv<<<(int)((ZH + 255) / 256), 256>>>(W2, W2hi, W2lo, ZH);
    build_Pp<<<(int)(((long)NB * KP0 + 255) / 256), 256>>>(tin, PChi, PClo, 1, 0, T0, KP0, 0);
    build_Pp<<<(int)(((long)NB * KP1 + 255) / 256), 256>>>(tin, PChi, PClo, 3, 128, T1, KP1, S1);
    build_Pp<<<(int)(((long)NB * KP2 + 255) / 256), 256>>>(tin, PChi, PClo, 5, 320, T2, KP2, S2);

    // ---- forward ----
    bf_gemm_nt<<<dim3(HID / 128, NB / 128), 256, GSMEM>>>(
        PChi, PClo, WThi, WTlo, nullptr, ehi, elo, KCP, HID, 1.f, nullptr);
    bf_gemm_nt<<<dim3(HID / 128, NB / 128), 256, GSMEM>>>(
        ehi, elo, W1Thi, W1Tlo, a1, nullptr, nullptr, HID, HID, 1.f, b1);
    ln_silu_fwd<4><<<NB, 256>>>(a1, g1, be1, xh1, rs1, nullptr, h1hi, h1lo);
    bf_gemm_nt<<<dim3(ZD / 128, NB / 128), 256, GSMEM>>>(
        h1hi, h1lo, W2Thi, W2Tlo, a2, nullptr, nullptr, HID, ZD, 1.f, b2);
    ln_silu_fwd<1><<<NB, 256>>>(a2, g2, be2, xh2, rs2, xout, nullptr, nullptr);

    // ---- backward ----
    ln_silu_bwd<1><<<NB, 256>>>(nullptr, xh2, rs2, g2, be2, nullptr, da2hi, da2lo);
    bf_gemm_nt<<<dim3(HID / 128, NB / 128), 256, GSMEM>>>(
        da2hi, da2lo, W2hi, W2lo, dh1, nullptr, nullptr, ZD, HID, 1.f, nullptr);
    ln_silu_bwd<4><<<NB, 256>>>(dh1, xh1, rs1, g1, be1, nullptr, da1hi, da1lo);
    bf_gemm_nt<<<dim3(HID / 128, NB / 128), 256, GSMEM>>>(
        da1hi, da1lo, W1hi, W1lo, nullptr, dehi, delo, HID, HID, 1.f, nullptr);
    bf_gemm_nt<<<dim3(KCP / 128, NB / 128), 256, GSMEM>>>(
        dehi, delo, WPhi, WPlo, dPC, nullptr, nullptr, HID, KCP, 1.f, nullptr);

    grad0<<<NB, 128, 128 * 129 * 4 + 512>>>(dPC, tin, yout);
    grad1<<<NB, 192>>>(dPC, tin, yout);
    grad2<<<NB, 160>>>(dPC, tin, yout);
}

// round 7
// speedup vs baseline: 4.3182x; 1.0576x over previous
#include <cuda_runtime.h>
#include <cuda_bf16.h>
#include <math.h>
#include <stdint.h>

#define NB   2048
#define DIMT 480
#define HID  1024
#define ZD   256
// packed symmetric pair counts
#define T0   8256
#define KP0  8256
#define T1   2080
#define KP1  2112
#define T2   528
#define KP2  640
#define KCP  11008      // KP0+KP1+KP2, multiple of 128
#define S1   8256
#define S2   10368

typedef __nv_bfloat16 bf16;

// ---------------- scratch pools ----------------
constexpr long NBKC = (long)NB * KCP;
constexpr long HKC  = (long)HID * KCP;
constexpr long HH   = (long)HID * HID;
constexpr long ZH   = (long)ZD * HID;
constexpr long NH   = (long)NB * HID;
constexpr long NZ   = (long)NB * ZD;

constexpr long B_PCHI = 0;
constexpr long B_PCLO = B_PCHI + NBKC;
constexpr long B_WTHI = B_PCLO + NBKC;   // packed-T [HID, KCP]
constexpr long B_WTLO = B_WTHI + HKC;
constexpr long B_WPHI = B_WTLO + HKC;    // packed   [KCP, HID]
constexpr long B_WPLO = B_WPHI + HKC;
constexpr long B_W1THI= B_WPLO + HKC;
constexpr long B_W1TLO= B_W1THI + HH;
constexpr long B_W1HI = B_W1TLO + HH;
constexpr long B_W1LO = B_W1HI + HH;
constexpr long B_W2THI= B_W1LO + HH;
constexpr long B_W2TLO= B_W2THI + ZH;
constexpr long B_W2HI = B_W2TLO + ZH;
constexpr long B_W2LO = B_W2HI + ZH;
constexpr long B_EHI  = B_W2LO + ZH;
constexpr long B_ELO  = B_EHI + NH;
constexpr long B_H1HI = B_ELO + NH;
constexpr long B_H1LO = B_H1HI + NH;
constexpr long B_DA2HI= B_H1LO + NH;
constexpr long B_DA2LO= B_DA2HI + NZ;
constexpr long B_DA1HI= B_DA2LO + NZ;
constexpr long B_DA1LO= B_DA1HI + NH;
constexpr long B_DEHI = B_DA1LO + NH;
constexpr long B_DELO = B_DEHI + NH;
constexpr long B_TOT  = B_DELO + NH;

constexpr long F_DPC  = 0;
constexpr long F_A1   = F_DPC + NBKC;
constexpr long F_XH1  = F_A1  + NH;
constexpr long F_A2   = F_XH1 + NH;
constexpr long F_XH2  = F_A2  + NZ;
constexpr long F_DH1  = F_XH2 + NZ;
constexpr long F_RS1  = F_DH1 + NH;
constexpr long F_RS2  = F_RS1 + NB;
constexpr long F_TOT  = F_RS2 + NB;

__device__ bf16     g_hbuf[B_TOT];
__device__ float    g_fbuf[F_TOT];
__device__ uint32_t g_uv[KCP];

// ---------------- helpers ----------------
__device__ __forceinline__ uint32_t smem_u32(const void* p) {
    uint32_t a;
    asm("{ .reg .u64 t; cvta.to.shared.u64 t, %1; cvt.u32.u64 %0, t; }" : "=r"(a) : "l"(p));
    return a;
}
__device__ __forceinline__ void ldsm4(uint32_t* r, uint32_t a) {
    asm volatile("ldmatrix.sync.aligned.m8n8.x4.shared.b16 {%0,%1,%2,%3},[%4];"
                 : "=r"(r[0]), "=r"(r[1]), "=r"(r[2]), "=r"(r[3]) : "r"(a));
}
__device__ __forceinline__ void mma_bf16(float* d, const uint32_t* a, const uint32_t* b) {
    asm volatile("mma.sync.aligned.m16n8k16.row.col.f32.bf16.bf16.f32 "
                 "{%0,%1,%2,%3},{%4,%5,%6,%7},{%8,%9},{%0,%1,%2,%3};"
                 : "+f"(d[0]), "+f"(d[1]), "+f"(d[2]), "+f"(d[3])
                 : "r"(a[0]), "r"(a[1]), "r"(a[2]), "r"(a[3]), "r"(b[0]), "r"(b[1]));
}
#define CPA(dst, src) asm volatile("cp.async.cg.shared.global [%0], [%1], 16;" :: "r"(dst), "l"(src) : "memory")
#define CPCOMMIT()    asm volatile("cp.async.commit_group;" ::: "memory")
#define CPWAIT1()     asm volatile("cp.async.wait_group 1;" ::: "memory")

__device__ __forceinline__ void split2(float v, bf16& h, bf16& l) {
    h = __float2bfloat16(v);
    l = __float2bfloat16(v - __bfloat162float(h));
}

// ---------------- pair LUT ----------------
__global__ void uv_init() {
    int p = blockIdx.x * 256 + threadIdx.x;
    if (p >= KCP) return;
    int n, lp, T;
    if (p < S1)      { n = 128; lp = p;      T = T0; }
    else if (p < S2) { n = 64;  lp = p - S1; T = T1; }
    else             { n = 32;  lp = p - S2; T = T2; }
    if (lp >= T) { g_uv[p] = 0u; return; }
    float tn = 2.f * n + 1.f;
    int u = (int)((tn - sqrtf(tn * tn - 8.f * lp)) * 0.5f);
    if (u < 0) u = 0; if (u > n - 1) u = n - 1;
    while (u > 0 && u * n - u * (u - 1) / 2 > lp) u--;
    while (u < n - 1 && (u + 1) * n - (u + 1) * u / 2 <= lp) u++;
    int v = u + (lp - (u * n - u * (u - 1) / 2));
    g_uv[p] = ((uint32_t)u << 16) | (uint32_t)v;
}

// ---------------- bf16 split NT GEMM: 512 threads, 16 warps, 32x32 warp tiles ----------------
#define TILEB 16384
#define STG   (4 * TILEB)
#define GSMEM (3 * STG + 1024)

__global__ __launch_bounds__(512, 1) void bf_gemm_nt(
    const bf16* __restrict__ Ahi, const bf16* __restrict__ Alo,
    const bf16* __restrict__ Bhi, const bf16* __restrict__ Blo,
    float* __restrict__ C, bf16* __restrict__ Chi, bf16* __restrict__ Clo,
    int K, long ldc, float alpha, const float* __restrict__ bias)
{
    extern __shared__ char smem[];
    const uint32_t st0 = (smem_u32(smem) + 1023) & ~1023u;
    const int tid = threadIdx.x, wid = tid >> 5, lane = tid & 31;
    const int wm = wid >> 2, wn = wid & 3;          // 4x4 warps, 32x32 tiles
    const long bm = (long)blockIdx.y * 128, bn = (long)blockIdx.x * 128;

    // cp.async slots: 8 chunks/thread/stage (4 tiles x 2)
    const bf16* gp[8];
    uint32_t so[8];
    #pragma unroll
    for (int t = 0; t < 8; t++) {
        int q = tid + (t & 1) * 512;            // 0..1023
        int r = q >> 3, c = q & 7;
        int tile = t >> 1;                      // 0=Ahi 1=Alo 2=Bhi 3=Blo
        const bf16* base = (tile == 0) ? Ahi : (tile == 1) ? Alo : (tile == 2) ? Bhi : Blo;
        long row = (tile < 2 ? bm : bn) + r;
        gp[t] = base + row * K + c * 8;
        so[t] = st0 + tile * TILEB + ((r * 128 + c * 16) ^ ((r & 7) << 4));
    }
    const int nk = K >> 6;

    #pragma unroll
    for (int p = 0; p < 2; p++) {
        #pragma unroll
        for (int t = 0; t < 8; t++) CPA(so[t] + p * STG, gp[t] + (long)p * 64);
        CPCOMMIT();
    }

    float acc[2][4][4];
    #pragma unroll
    for (int a = 0; a < 2; a++)
        #pragma unroll
        for (int b = 0; b < 4; b++)
            #pragma unroll
            for (int c = 0; c < 4; c++) acc[a][b][c] = 0.f;

    const int lr = lane & 15, lc = lane >> 4;
    const uint32_t xa = (lr & 7) << 4;
    const uint32_t arow = (wm * 32 + lr) * 128 + lc * 16;
    const uint32_t brow = (wn * 32 + lr) * 128 + lc * 16;

    for (int i = 0; i < nk; i++) {
        CPWAIT1();
        __syncthreads();
        if (i + 2 < nk) {
            const uint32_t sst = ((i + 2) % 3) * STG;
            #pragma unroll
            for (int t = 0; t < 8; t++) CPA(so[t] + sst, gp[t] + (long)(i + 2) * 64);
        }
        CPCOMMIT();

        const uint32_t sa = st0 + (i % 3) * STG;
        #pragma unroll
        for (int kk = 0; kk < 4; kk++) {
            uint32_t af[2][4], al[2][4], bf_[4][2], bl[4][2];
            #pragma unroll
            for (int mi = 0; mi < 2; mi++) {
                uint32_t off = (arow + mi * 2048 + kk * 32) ^ xa;
                ldsm4(af[mi], sa + off);
                ldsm4(al[mi], sa + TILEB + off);
            }
            #pragma unroll
            for (int pi = 0; pi < 2; pi++) {
                uint32_t off = (brow + pi * 2048 + kk * 32) ^ xa;
                uint32_t t0[4], t1[4];
                ldsm4(t0, sa + 2 * TILEB + off);
                ldsm4(t1, sa + 3 * TILEB + off);
                bf_[2 * pi][0] = t0[0]; bf_[2 * pi + 1][0] = t0[1];
                bf_[2 * pi][1] = t0[2]; bf_[2 * pi + 1][1] = t0[3];
                bl[2 * pi][0] = t1[0]; bl[2 * pi + 1][0] = t1[1];
                bl[2 * pi][1] = t1[2]; bl[2 * pi + 1][1] = t1[3];
            }
            #pragma unroll
            for (int mi = 0; mi < 2; mi++)
                #pragma unroll
                for (int ni = 0; ni < 4; ni++) {
                    mma_bf16(acc[mi][ni], af[mi], bf_[ni]);
                    mma_bf16(acc[mi][ni], af[mi], bl[ni]);
                    mma_bf16(acc[mi][ni], al[mi], bf_[ni]);
                }
        }
    }

    const int g = lane >> 2, tg = lane & 3;
    #pragma unroll
    for (int mi = 0; mi < 2; mi++) {
        #pragma unroll
        for (int ni = 0; ni < 4; ni++) {
            long m0 = bm + wm * 32 + mi * 16 + g;
            long n0 = bn + wn * 32 + ni * 8 + tg * 2;
            float v00 = alpha * acc[mi][ni][0], v01 = alpha * acc[mi][ni][1];
            float v10 = alpha * acc[mi][ni][2], v11 = alpha * acc[mi][ni][3];
            if (bias) {
                float bb0 = bias[n0], bb1 = bias[n0 + 1];
                v00 += bb0; v01 += bb1; v10 += bb0; v11 += bb1;
            }
            if (C) {
                *(float2*)(C + m0 * ldc + n0) = make_float2(v00, v01);
                *(float2*)(C + (m0 + 8) * ldc + n0) = make_float2(v10, v11);
            }
            if (Chi) {
                bf16 h0, l0, h1, l1;
                split2(v00, h0, l0); split2(v01, h1, l1);
                *(__nv_bfloat162*)(Chi + m0 * ldc + n0) = __nv_bfloat162(h0, h1);
                *(__nv_bfloat162*)(Clo + m0 * ldc + n0) = __nv_bfloat162(l0, l1);
                split2(v10, h0, l0); split2(v11, h1, l1);
                *(__nv_bfloat162*)(Chi + (m0 + 8) * ldc + n0) = __nv_bfloat162(h0, h1);
                *(__nv_bfloat162*)(Clo + (m0 + 8) * ldc + n0) = __nv_bfloat162(l0, l1);
            }
        }
    }
}

// ---------------- packed weight prep ----------------
__global__ void pack_nt(const float* __restrict__ w, bf16* __restrict__ dhi,
                        bf16* __restrict__ dlo, int n, int T, int KP, long kbase, float s)
{
    long idx = (long)blockIdx.x * 256 + threadIdx.x;
    if (idx >= (long)KP * HID) return;
    int p = (int)(idx / HID), h = (int)(idx % HID);
    float val = 0.f;
    if (p < T) {
        uint32_t uv = g_uv[kbase + p];
        int u = uv >> 16, v = uv & 0xffff;
        val = w[((long)u * n + v) * HID + h];
        if (u != v) val += w[((long)v * n + u) * HID + h];
        val *= s;
    }
    bf16 hh, ll; split2(val, hh, ll);
    long o = (kbase + p) * HID + h;
    dhi[o] = hh; dlo[o] = ll;
}

__global__ __launch_bounds__(256) void pack_t(
    const float* __restrict__ w, bf16* __restrict__ dhi, bf16* __restrict__ dlo,
    int n, int T, int KP, long kbase, float s)
{
    __shared__ float sv[32][33];
    int pb = blockIdx.x * 32, hb = blockIdx.y * 32;
    int tx = threadIdx.x & 31, ty = threadIdx.x >> 5;
    #pragma unroll
    for (int i = 0; i < 32; i += 8) {
        int pp = pb + ty + i;
        float val = 0.f;
        if (pp < T) {
            uint32_t uv = g_uv[kbase + pp];
            int u = uv >> 16, v = uv & 0xffff;
            val = w[((long)u * n + v) * HID + hb + tx];
            if (u != v) val += w[((long)v * n + u) * HID + hb + tx];
            val *= s;
        }
        sv[ty + i][tx] = val;
    }
    __syncthreads();
    #pragma unroll
    for (int i = 0; i < 32; i += 8) {
        float val = sv[tx][ty + i];
        bf16 hh, ll; split2(val, hh, ll);
        long o = (long)(hb + ty + i) * KCP + kbase + pb + tx;
        dhi[o] = hh; dlo[o] = ll;
    }
}

__global__ __launch_bounds__(256) void tsc(
    const float* __restrict__ src, bf16* __restrict__ dhi, bf16* __restrict__ dlo,
    int R, int C, long ldd)
{
    __shared__ float t[32][33];
    int bx = blockIdx.x * 32, by = blockIdx.y * 32;
    int tx = threadIdx.x & 31, ty = threadIdx.x >> 5;
    #pragma unroll
    for (int i = 0; i < 32; i += 8)
        t[ty + i][tx] = src[(long)(by + ty + i) * C + bx + tx];
    __syncthreads();
    #pragma unroll
    for (int i = 0; i < 32; i += 8) {
        bf16 h, l; split2(t[tx][ty + i], h, l);
        long o = (long)(bx + ty + i) * ldd + by + tx;
        dhi[o] = h; dlo[o] = l;
    }
}
__global__ void sconv(const float* __restrict__ src, bf16* __restrict__ dhi,
                      bf16* __restrict__ dlo, long n)
{
    long i = (long)blockIdx.x * 256 + threadIdx.x;
    if (i < n) {
        bf16 h, l; split2(src[i], h, l);
        dhi[i] = h; dlo[i] = l;
    }
}

// ---------------- packed pairwise products ----------------
__global__ void build_Pp(const float* __restrict__ t, bf16* __restrict__ Ph,
                         bf16* __restrict__ Pl, int nm, int xoff, int T, int KP, long kbase)
{
    long idx = (long)blockIdx.x * 256 + threadIdx.x;
    if (idx >= (long)NB * KP) return;
    int b = (int)(idx / KP), p = (int)(idx % KP);
    float val = 0.f;
    if (p < T) {
        uint32_t uv = g_uv[kbase + p];
        int u = uv >> 16, v = uv & 0xffff;
        const float* r = t + (long)b * DIMT + xoff;
        for (int m = 0; m < nm; m++) val += r[u * nm + m] * r[v * nm + m];
    }
    bf16 hh, ll; split2(val, hh, ll);
    long o = (long)b * KCP + kbase + p;
    Ph[o] = hh; Pl[o] = ll;
}

// ---------------- block reduce ----------------
__device__ __forceinline__ float blockReduceSum(float val) {
    __shared__ float sh[8];
    int lane = threadIdx.x & 31, w = threadIdx.x >> 5;
    #pragma unroll
    for (int o = 16; o > 0; o >>= 1) val += __shfl_down_sync(0xffffffffu, val, o);
    __syncthreads();
    if (lane == 0) sh[w] = val;
    __syncthreads();
    float r = 0.f;
    if (threadIdx.x == 0) {
        int nw = blockDim.x >> 5;
        for (int i = 0; i < nw; i++) r += sh[i];
    }
    return r;
}

// ---------------- LayerNorm + SiLU forward ----------------
template<int PER>
__global__ __launch_bounds__(256) void ln_silu_fwd(
    const float* __restrict__ a, const float* __restrict__ gam, const float* __restrict__ bet,
    float* __restrict__ xh, float* __restrict__ rstd,
    float* __restrict__ h, bf16* __restrict__ hhi, bf16* __restrict__ hlo)
{
    const int D = PER * 256;
    int b = blockIdx.x, tid = threadIdx.x;
    const float* row = a + (long)b * D;
    float v[PER];
    float s = 0.f;
    #pragma unroll
    for (int i = 0; i < PER; i++) { v[i] = row[tid + (i << 8)]; s += v[i]; }
    s = blockReduceSum(s);
    __shared__ float bc;
    if (tid == 0) bc = s * (1.f / D);
    __syncthreads();
    float mu = bc;
    float q = 0.f;
    #pragma unroll
    for (int i = 0; i < PER; i++) { float d = v[i] - mu; q += d * d; }
    q = blockReduceSum(q);
    if (tid == 0) { float r = rsqrtf(q * (1.f / D) + 1e-6f); bc = r; rstd[b] = r; }
    __syncthreads();
    float r = bc;
    #pragma unroll
    for (int i = 0; i < PER; i++) {
        int c = tid + (i << 8);
        float x = (v[i] - mu) * r;
        xh[(long)b * D + c] = x;
        float z = x * gam[c] + bet[c];
        float sg = 1.f / (1.f + expf(-z));
        float hv = z * sg;
        if (h) h[(long)b * D + c] = hv;
        if (hhi) {
            bf16 hi, lo; split2(hv, hi, lo);
            hhi[(long)b * D + c] = hi; hlo[(long)b * D + c] = lo;
        }
    }
}

// ---------------- (SiLU + LN) backward ----------------
template<int PER>
__global__ __launch_bounds__(256) void ln_silu_bwd(
    const float* __restrict__ dh, const float* __restrict__ xhv_, const float* __restrict__ rstd,
    const float* __restrict__ gam, const float* __restrict__ bet,
    float* __restrict__ da, bf16* __restrict__ dahi, bf16* __restrict__ dalo)
{
    const int D = PER * 256;
    int b = blockIdx.x, tid = threadIdx.x;
    float xh[PER], dxh[PER];
    float s1 = 0.f, s2 = 0.f;
    #pragma unroll
    for (int i = 0; i < PER; i++) {
        int c = tid + (i << 8);
        float x = xhv_[(long)b * D + c];
        float z = x * gam[c] + bet[c];
        float sg = 1.f / (1.f + expf(-z));
        float ds = sg * (1.f + z * (1.f - sg));
        float up = dh ? dh[(long)b * D + c] : 1.f;
        float dx = up * ds * gam[c];
        xh[i] = x; dxh[i] = dx;
        s1 += dx; s2 += dx * x;
    }
    __shared__ float m1s, m2s;
    float t1 = blockReduceSum(s1);
    if (tid == 0) m1s = t1 * (1.f / D);
    float t2 = blockReduceSum(s2);
    if (tid == 0) m2s = t2 * (1.f / D);
    __syncthreads();
    float m1 = m1s, m2 = m2s, r = rstd[b];
    #pragma unroll
    for (int i = 0; i < PER; i++) {
        int c = tid + (i << 8);
        float dv = r * (dxh[i] - m1 - xh[i] * m2);
        if (da) da[(long)b * D + c] = dv;
        if (dahi) {
            bf16 hi, lo; split2(dv, hi, lo);
            dahi[(long)b * D + c] = hi; dalo[(long)b * D + c] = lo;
        }
    }
}

// ---------------- packed quadratic-form gradients -> y ----------------
__global__ __launch_bounds__(128) void grad0(const float* __restrict__ dPc,
                                             const float* __restrict__ t, float* __restrict__ y)
{
    extern __shared__ float Ts[];   // 128*129 + 128
    float* xs = Ts + 128 * 129;
    int b = blockIdx.x, tid = threadIdx.x;
    xs[tid] = t[(long)b * DIMT + tid];
    const float* P = dPc + (long)b * KCP;
    for (int i = tid; i < T0; i += 128) {
        uint32_t uv = g_uv[i];
        int u = uv >> 16, v = uv & 0xffff;
        float val = P[i];
        Ts[u * 129 + v] = val;
        Ts[v * 129 + u] = (u == v) ? 2.f * val : val;
    }
    __syncthreads();
    float s = 0.f;
    #pragma unroll 8
    for (int v = 0; v < 128; v++) s += Ts[tid * 129 + v] * xs[v];
    y[(long)b * DIMT + tid] = s;
}

__global__ __launch_bounds__(192) void grad1(const float* __restrict__ dPc,
                                             const float* __restrict__ t, float* __restrict__ y)
{
    __shared__ float Ts[64][65];
    __shared__ float xs[192];
    int b = blockIdx.x, tid = threadIdx.x;
    xs[tid] = t[(long)b * DIMT + 128 + tid];
    const float* P = dPc + (long)b * KCP + S1;
    for (int i = tid; i < T1; i += 192) {
        uint32_t uv = g_uv[S1 + i];
        int u = uv >> 16, v = uv & 0xffff;
        float val = P[i];
        Ts[u][v] = val;
        Ts[v][u] = (u == v) ? 2.f * val : val;
    }
    __syncthreads();
    int u = tid / 3, m = tid - u * 3;
    float s = 0.f;
    #pragma unroll 8
    for (int v = 0; v < 64; v++) s += Ts[u][v] * xs[v * 3 + m];
    y[(long)b * DIMT + 128 + tid] = s;
}

__global__ __launch_bounds__(160) void grad2(const float* __restrict__ dPc,
                                             const float* __restrict__ t, float* __restrict__ y)
{
    __shared__ float Ts[32][33];
    __shared__ float xs[160];
    int b = blockIdx.x, tid = threadIdx.x;
    xs[tid] = t[(long)b * DIMT + 320 + tid];
    const float* P = dPc + (long)b * KCP + S2;
    for (int i = tid; i < T2; i += 160) {
        uint32_t uv = g_uv[S2 + i];
        int u = uv >> 16, v = uv & 0xffff;
        float val = P[i];
        Ts[u][v] = val;
        Ts[v][u] = (u == v) ? 2.f * val : val;
    }
    __syncthreads();
    int u = tid / 5, m = tid - u * 5;
    float s = 0.f;
    #pragma unroll 8
    for (int v = 0; v < 32; v++) s += Ts[u][v] * xs[v * 5 + m];
    y[(long)b * DIMT + 320 + tid] = s;
}

// ---------------- launch ----------------
extern "C" void kernel_launch(void* const* d_in, const int* in_sizes, int n_in,
                              void* d_out, int out_size)
{
    const float* tin = (const float*)d_in[0];
    const float* w0  = (const float*)d_in[1];
    const float* w1  = (const float*)d_in[2];
    const float* w2  = (const float*)d_in[3];
    const float* W1  = (const float*)d_in[4];
    const float* b1  = (const float*)d_in[5];
    const float* g1  = (const float*)d_in[6];
    const float* be1 = (const float*)d_in[7];
    const float* W2  = (const float*)d_in[8];
    const float* b2  = (const float*)d_in[9];
    const float* g2  = (const float*)d_in[10];
    const float* be2 = (const float*)d_in[11];

    float* out  = (float*)d_out;
    float* xout = out;
    float* yout = out + (long)NB * ZD;

    bf16* hb = nullptr; float* fb = nullptr;
    cudaGetSymbolAddress((void**)&hb, g_hbuf);
    cudaGetSymbolAddress((void**)&fb, g_fbuf);

    bf16 *PChi = hb + B_PCHI, *PClo = hb + B_PCLO;
    bf16 *WThi = hb + B_WTHI, *WTlo = hb + B_WTLO;
    bf16 *WPhi = hb + B_WPHI, *WPlo = hb + B_WPLO;
    bf16 *W1Thi= hb + B_W1THI,*W1Tlo= hb + B_W1TLO;
    bf16 *W1hi = hb + B_W1HI, *W1lo = hb + B_W1LO;
    bf16 *W2Thi= hb + B_W2THI,*W2Tlo= hb + B_W2TLO;
    bf16 *W2hi = hb + B_W2HI, *W2lo = hb + B_W2LO;
    bf16 *ehi  = hb + B_EHI,  *elo  = hb + B_ELO;
    bf16 *h1hi = hb + B_H1HI, *h1lo = hb + B_H1LO;
    bf16 *da2hi= hb + B_DA2HI,*da2lo= hb + B_DA2LO;
    bf16 *da1hi= hb + B_DA1HI,*da1lo= hb + B_DA1LO;
    bf16 *dehi = hb + B_DEHI, *delo = hb + B_DELO;

    float *dPC = fb + F_DPC, *a1 = fb + F_A1, *xh1 = fb + F_XH1;
    float *a2  = fb + F_A2,  *xh2= fb + F_XH2, *dh1 = fb + F_DH1;
    float *rs1 = fb + F_RS1, *rs2= fb + F_RS2;

    const float s0 = 1.0f / sqrtf(21504.0f);
    const float s1 = s0 / sqrtf(3.0f);
    const float s2 = s0 / sqrtf(5.0f);

    cudaFuncSetAttribute(bf_gemm_nt, cudaFuncAttributeMaxDynamicSharedMemorySize, GSMEM);
    cudaFuncSetAttribute(grad0, cudaFuncAttributeMaxDynamicSharedMemorySize, 128 * 129 * 4 + 512);

    // ---- prep ----
    uv_init<<<(KCP + 255) / 256, 256>>>();
    pack_t<<<dim3(KP0 / 32, HID / 32), 256>>>(w0, WThi, WTlo, 128, T0, KP0, 0, s0);
    pack_t<<<dim3(KP1 / 32, HID / 32), 256>>>(w1, WThi, WTlo, 64, T1, KP1, S1, s1);
    pack_t<<<dim3(KP2 / 32, HID / 32), 256>>>(w2, WThi, WTlo, 32, T2, KP2, S2, s2);
    pack_nt<<<(int)(((long)KP0 * HID + 255) / 256), 256>>>(w0, WPhi, WPlo, 128, T0, KP0, 0, s0);
    pack_nt<<<(int)(((long)KP1 * HID + 255) / 256), 256>>>(w1, WPhi, WPlo, 64, T1, KP1, S1, s1);
    pack_nt<<<(int)(((long)KP2 * HID + 255) / 256), 256>>>(w2, WPhi, WPlo, 32, T2, KP2, S2, s2);
    tsc<<<dim3(HID / 32, HID / 32), 256>>>(W1, W1Thi, W1Tlo, HID, HID, HID);
    tsc<<<dim3(ZD / 32, HID / 32), 256>>>(W2, W2Thi, W2Tlo, HID, ZD, HID);
    sconv<<<(int)((HH + 255) / 256), 256>>>(W1, W1hi, W1lo, HH);
    sconv<<<(int)((ZH + 255) / 256), 256>>>(W2, W2hi, W2lo, ZH);
    build_Pp<<<(int)(((long)NB * KP0 + 255) / 256), 256>>>(tin, PChi, PClo, 1, 0, T0, KP0, 0);
    build_Pp<<<(int)(((long)NB * KP1 + 255) / 256), 256>>>(tin, PChi, PClo, 3, 128, T1, KP1, S1);
    build_Pp<<<(int)(((long)NB * KP2 + 255) / 256), 256>>>(tin, PChi, PClo, 5, 320, T2, KP2, S2);

    // ---- forward ----
    bf_gemm_nt<<<dim3(HID / 128, NB / 128), 512, GSMEM>>>(
        PChi, PClo, WThi, WTlo, nullptr, ehi, elo, KCP, HID, 1.f, nullptr);
    bf_gemm_nt<<<dim3(HID / 128, NB / 128), 512, GSMEM>>>(
        ehi, elo, W1Thi, W1Tlo, a1, nullptr, nullptr, HID, HID, 1.f, b1);
    ln_silu_fwd<4><<<NB, 256>>>(a1, g1, be1, xh1, rs1, nullptr, h1hi, h1lo);
    bf_gemm_nt<<<dim3(ZD / 128, NB / 128), 512, GSMEM>>>(
        h1hi, h1lo, W2Thi, W2Tlo, a2, nullptr, nullptr, HID, ZD, 1.f, b2);
    ln_silu_fwd<1><<<NB, 256>>>(a2, g2, be2, xh2, rs2, xout, nullptr, nullptr);

    // ---- backward ----
    ln_silu_bwd<1><<<NB, 256>>>(nullptr, xh2, rs2, g2, be2, nullptr, da2hi, da2lo);
    bf_gemm_nt<<<dim3(HID / 128, NB / 128), 512, GSMEM>>>(
        da2hi, da2lo, W2hi, W2lo, dh1, nullptr, nullptr, ZD, HID, 1.f, nullptr);
    ln_silu_bwd<4><<<NB, 256>>>(dh1, xh1, rs1, g1, be1, nullptr, da1hi, da1lo);
    bf_gemm_nt<<<dim3(HID / 128, NB / 128), 512, GSMEM>>>(
        da1hi, da1lo, W1hi, W1lo, nullptr, dehi, delo, HID, HID, 1.f, nullptr);
    bf_gemm_nt<<<dim3(KCP / 128, NB / 128), 512, GSMEM>>>(
        dehi, delo, WPhi, WPlo, dPC, nullptr, nullptr, HID, KCP, 1.f, nullptr);

    grad0<<<NB, 128, 128 * 129 * 4 + 512>>>(dPC, tin, yout);
    grad1<<<NB, 192>>>(dPC, tin, yout);
    grad2<<<NB, 160>>>(dPC, tin, yout);
}

// round 8
// speedup vs baseline: 5.7148x; 1.3234x over previous
#include <cuda_runtime.h>
#include <cuda_fp16.h>
#include <math.h>
#include <stdint.h>

#define NB   2048
#define DIMT 480
#define HID  1024
#define ZD   256
// packed symmetric pair counts
#define T0   8256
#define KP0  8256
#define T1   2080
#define KP1  2112
#define T2   528
#define KP2  640
#define KCP  11008
#define S1   8256
#define S2   10368

typedef __half h16;

// ---------------- scratch pools ----------------
constexpr long NBKC = (long)NB * KCP;
constexpr long HKC  = (long)HID * KCP;
constexpr long HH   = (long)HID * HID;
constexpr long ZH   = (long)ZD * HID;
constexpr long NH   = (long)NB * HID;
constexpr long NZ   = (long)NB * ZD;

constexpr long B_PC   = 0;               // single fp16
constexpr long B_WTHI = B_PC   + NBKC;
constexpr long B_WTLO = B_WTHI + HKC;
constexpr long B_WPHI = B_WTLO + HKC;
constexpr long B_WPLO = B_WPHI + HKC;
constexpr long B_W1THI= B_WPLO + HKC;
constexpr long B_W1TLO= B_W1THI + HH;
constexpr long B_W1HI = B_W1TLO + HH;
constexpr long B_W1LO = B_W1HI + HH;
constexpr long B_W2THI= B_W1LO + HH;
constexpr long B_W2TLO= B_W2THI + ZH;
constexpr long B_W2HI = B_W2TLO + ZH;
constexpr long B_W2LO = B_W2HI + ZH;
constexpr long B_EH   = B_W2LO + ZH;
constexpr long B_H1H  = B_EH   + NH;
constexpr long B_DA2H = B_H1H  + NH;
constexpr long B_DA1H = B_DA2H + NZ;
constexpr long B_DEH  = B_DA1H + NH;
constexpr long B_TOT  = B_DEH  + NH;

constexpr long F_DPC  = 0;
constexpr long F_A1   = F_DPC + NBKC;
constexpr long F_XH1  = F_A1  + NH;
constexpr long F_A2   = F_XH1 + NH;
constexpr long F_XH2  = F_A2  + NZ;
constexpr long F_DH1  = F_XH2 + NZ;
constexpr long F_RS1  = F_DH1 + NH;
constexpr long F_RS2  = F_RS1 + NB;
constexpr long F_TOT  = F_RS2 + NB;

__device__ h16      g_hbuf[B_TOT];
__device__ float    g_fbuf[F_TOT];
__device__ uint32_t g_uv[KCP];

// ---------------- helpers ----------------
__device__ __forceinline__ uint32_t smem_u32(const void* p) {
    uint32_t a;
    asm("{ .reg .u64 t; cvta.to.shared.u64 t, %1; cvt.u32.u64 %0, t; }" : "=r"(a) : "l"(p));
    return a;
}
__device__ __forceinline__ void ldsm4(uint32_t* r, uint32_t a) {
    asm volatile("ldmatrix.sync.aligned.m8n8.x4.shared.b16 {%0,%1,%2,%3},[%4];"
                 : "=r"(r[0]), "=r"(r[1]), "=r"(r[2]), "=r"(r[3]) : "r"(a));
}
__device__ __forceinline__ void mma_f16(float* d, const uint32_t* a, const uint32_t* b) {
    asm volatile("mma.sync.aligned.m16n8k16.row.col.f32.f16.f16.f32 "
                 "{%0,%1,%2,%3},{%4,%5,%6,%7},{%8,%9},{%0,%1,%2,%3};"
                 : "+f"(d[0]), "+f"(d[1]), "+f"(d[2]), "+f"(d[3])
                 : "r"(a[0]), "r"(a[1]), "r"(a[2]), "r"(a[3]), "r"(b[0]), "r"(b[1]));
}
#define CPA(dst, src) asm volatile("cp.async.cg.shared.global [%0], [%1], 16;" :: "r"(dst), "l"(src) : "memory")
#define CPCOMMIT()    asm volatile("cp.async.commit_group;" ::: "memory")
#define CPWAIT1()     asm volatile("cp.async.wait_group 1;" ::: "memory")

// weight split: B = hi + (lo/2048); lo pre-scaled by 2048 to stay normal-range
__device__ __forceinline__ void splith(float v, h16& h, h16& l) {
    h = __float2half(v);
    l = __float2half((v - __half2float(h)) * 2048.f);
}

// ---------------- pair LUT ----------------
__global__ void uv_init() {
    int p = blockIdx.x * 256 + threadIdx.x;
    if (p >= KCP) return;
    int n, lp, T;
    if (p < S1)      { n = 128; lp = p;      T = T0; }
    else if (p < S2) { n = 64;  lp = p - S1; T = T1; }
    else             { n = 32;  lp = p - S2; T = T2; }
    if (lp >= T) { g_uv[p] = 0u; return; }
    float tn = 2.f * n + 1.f;
    int u = (int)((tn - sqrtf(tn * tn - 8.f * lp)) * 0.5f);
    if (u < 0) u = 0; if (u > n - 1) u = n - 1;
    while (u > 0 && u * n - u * (u - 1) / 2 > lp) u--;
    while (u < n - 1 && (u + 1) * n - (u + 1) * u / 2 <= lp) u++;
    int v = u + (lp - (u * n - u * (u - 1) / 2));
    g_uv[p] = ((uint32_t)u << 16) | (uint32_t)v;
}

// ---------------- fp16 2-mma NT GEMM: 512 threads, 32x32 warp tiles ----------------
// C[m,n] = alpha * sum_k A[m,k]*(Bhi[n,k]+Blo[n,k]/2048) (+bias[n])
#define TILEH 16384          // 128x64 fp16 tile
#define STGH  (3 * TILEH)    // A, Bhi, Blo
#define GSMEM (3 * STGH + 1024)

__global__ __launch_bounds__(512, 1) void h_gemm_nt(
    const h16* __restrict__ A, const h16* __restrict__ Bhi, const h16* __restrict__ Blo,
    float* __restrict__ C, h16* __restrict__ Ch,
    int K, long ldc, float alpha, const float* __restrict__ bias)
{
    extern __shared__ char smem[];
    const uint32_t st0 = (smem_u32(smem) + 1023) & ~1023u;
    const int tid = threadIdx.x, wid = tid >> 5, lane = tid & 31;
    const int wm = wid >> 2, wn = wid & 3;
    const long bm = (long)blockIdx.y * 128, bn = (long)blockIdx.x * 128;

    const h16* gp[6];
    uint32_t so[6];
    #pragma unroll
    for (int t = 0; t < 6; t++) {
        int q = tid + (t & 1) * 512;
        int r = q >> 3, c = q & 7;
        int tile = t >> 1;                  // 0=A 1=Bhi 2=Blo
        const h16* base = (tile == 0) ? A : (tile == 1) ? Bhi : Blo;
        long row = (tile == 0 ? bm : bn) + r;
        gp[t] = base + row * K + c * 8;
        so[t] = st0 + tile * TILEH + ((r * 128 + c * 16) ^ ((r & 7) << 4));
    }
    const int nk = K >> 6;

    #pragma unroll
    for (int p = 0; p < 2; p++) {
        #pragma unroll
        for (int t = 0; t < 6; t++) CPA(so[t] + p * STGH, gp[t] + (long)p * 64);
        CPCOMMIT();
    }

    float ac1[2][4][4], ac2[2][4][4];
    #pragma unroll
    for (int a = 0; a < 2; a++)
        #pragma unroll
        for (int b = 0; b < 4; b++)
            #pragma unroll
            for (int c = 0; c < 4; c++) { ac1[a][b][c] = 0.f; ac2[a][b][c] = 0.f; }

    const int lr = lane & 15, lc = lane >> 4;
    const uint32_t xa = (lr & 7) << 4;
    const uint32_t arow = (wm * 32 + lr) * 128 + lc * 16;
    const uint32_t brow = (wn * 32 + lr) * 128 + lc * 16;

    for (int i = 0; i < nk; i++) {
        CPWAIT1();
        __syncthreads();
        if (i + 2 < nk) {
            const uint32_t sst = ((i + 2) % 3) * STGH;
            #pragma unroll
            for (int t = 0; t < 6; t++) CPA(so[t] + sst, gp[t] + (long)(i + 2) * 64);
        }
        CPCOMMIT();

        const uint32_t sa = st0 + (i % 3) * STGH;
        #pragma unroll
        for (int kk = 0; kk < 4; kk++) {
            uint32_t af[2][4], bh[4][2], bl[4][2];
            #pragma unroll
            for (int mi = 0; mi < 2; mi++)
                ldsm4(af[mi], sa + ((arow + mi * 2048 + kk * 32) ^ xa));
            #pragma unroll
            for (int pi = 0; pi < 2; pi++) {
                uint32_t off = (brow + pi * 2048 + kk * 32) ^ xa;
                uint32_t t0[4], t1[4];
                ldsm4(t0, sa + TILEH + off);
                ldsm4(t1, sa + 2 * TILEH + off);
                bh[2 * pi][0] = t0[0]; bh[2 * pi + 1][0] = t0[1];
                bh[2 * pi][1] = t0[2]; bh[2 * pi + 1][1] = t0[3];
                bl[2 * pi][0] = t1[0]; bl[2 * pi + 1][0] = t1[1];
                bl[2 * pi][1] = t1[2]; bl[2 * pi + 1][1] = t1[3];
            }
            #pragma unroll
            for (int mi = 0; mi < 2; mi++)
                #pragma unroll
                for (int ni = 0; ni < 4; ni++) {
                    mma_f16(ac1[mi][ni], af[mi], bh[ni]);
                    mma_f16(ac2[mi][ni], af[mi], bl[ni]);
                }
        }
    }

    const int g = lane >> 2, tg = lane & 3;
    const float inv = 1.f / 2048.f;
    #pragma unroll
    for (int mi = 0; mi < 2; mi++) {
        #pragma unroll
        for (int ni = 0; ni < 4; ni++) {
            long m0 = bm + wm * 32 + mi * 16 + g;
            long n0 = bn + wn * 32 + ni * 8 + tg * 2;
            float v00 = alpha * (ac1[mi][ni][0] + ac2[mi][ni][0] * inv);
            float v01 = alpha * (ac1[mi][ni][1] + ac2[mi][ni][1] * inv);
            float v10 = alpha * (ac1[mi][ni][2] + ac2[mi][ni][2] * inv);
            float v11 = alpha * (ac1[mi][ni][3] + ac2[mi][ni][3] * inv);
            if (bias) {
                float bb0 = bias[n0], bb1 = bias[n0 + 1];
                v00 += bb0; v01 += bb1; v10 += bb0; v11 += bb1;
            }
            if (C) {
                *(float2*)(C + m0 * ldc + n0) = make_float2(v00, v01);
                *(float2*)(C + (m0 + 8) * ldc + n0) = make_float2(v10, v11);
            }
            if (Ch) {
                *(__half2*)(Ch + m0 * ldc + n0) = __floats2half2_rn(v00, v01);
                *(__half2*)(Ch + (m0 + 8) * ldc + n0) = __floats2half2_rn(v10, v11);
            }
        }
    }
}

// ---------------- packed weight prep ----------------
__global__ void pack_nt(const float* __restrict__ w, h16* __restrict__ dhi,
                        h16* __restrict__ dlo, int n, int T, int KP, long kbase, float s)
{
    long idx = (long)blockIdx.x * 256 + threadIdx.x;
    if (idx >= (long)KP * HID) return;
    int p = (int)(idx / HID), h = (int)(idx % HID);
    float val = 0.f;
    if (p < T) {
        uint32_t uv = g_uv[kbase + p];
        int u = uv >> 16, v = uv & 0xffff;
        val = w[((long)u * n + v) * HID + h];
        if (u != v) val += w[((long)v * n + u) * HID + h];
        val *= s;
    }
    h16 hh, ll; splith(val, hh, ll);
    long o = (kbase + p) * HID + h;
    dhi[o] = hh; dlo[o] = ll;
}

__global__ __launch_bounds__(256) void pack_t(
    const float* __restrict__ w, h16* __restrict__ dhi, h16* __restrict__ dlo,
    int n, int T, int KP, long kbase, float s)
{
    __shared__ float sv[32][33];
    int pb = blockIdx.x * 32, hb = blockIdx.y * 32;
    int tx = threadIdx.x & 31, ty = threadIdx.x >> 5;
    #pragma unroll
    for (int i = 0; i < 32; i += 8) {
        int pp = pb + ty + i;
        float val = 0.f;
        if (pp < T) {
            uint32_t uv = g_uv[kbase + pp];
            int u = uv >> 16, v = uv & 0xffff;
            val = w[((long)u * n + v) * HID + hb + tx];
            if (u != v) val += w[((long)v * n + u) * HID + hb + tx];
            val *= s;
        }
        sv[ty + i][tx] = val;
    }
    __syncthreads();
    #pragma unroll
    for (int i = 0; i < 32; i += 8) {
        float val = sv[tx][ty + i];
        h16 hh, ll; splith(val, hh, ll);
        long o = (long)(hb + ty + i) * KCP + kbase + pb + tx;
        dhi[o] = hh; dlo[o] = ll;
    }
}

__global__ __launch_bounds__(256) void tsc(
    const float* __restrict__ src, h16* __restrict__ dhi, h16* __restrict__ dlo,
    int R, int C, long ldd)
{
    __shared__ float t[32][33];
    int bx = blockIdx.x * 32, by = blockIdx.y * 32;
    int tx = threadIdx.x & 31, ty = threadIdx.x >> 5;
    #pragma unroll
    for (int i = 0; i < 32; i += 8)
        t[ty + i][tx] = src[(long)(by + ty + i) * C + bx + tx];
    __syncthreads();
    #pragma unroll
    for (int i = 0; i < 32; i += 8) {
        h16 h, l; splith(t[tx][ty + i], h, l);
        long o = (long)(bx + ty + i) * ldd + by + tx;
        dhi[o] = h; dlo[o] = l;
    }
}
__global__ void sconv(const float* __restrict__ src, h16* __restrict__ dhi,
                      h16* __restrict__ dlo, long n)
{
    long i = (long)blockIdx.x * 256 + threadIdx.x;
    if (i < n) {
        h16 h, l; splith(src[i], h, l);
        dhi[i] = h; dlo[i] = l;
    }
}

// ---------------- packed pairwise products (single fp16) ----------------
__global__ void build_Pp(const float* __restrict__ t, h16* __restrict__ Ph,
                         int nm, int xoff, int T, int KP, long kbase)
{
    long idx = (long)blockIdx.x * 256 + threadIdx.x;
    if (idx >= (long)NB * KP) return;
    int b = (int)(idx / KP), p = (int)(idx % KP);
    float val = 0.f;
    if (p < T) {
        uint32_t uv = g_uv[kbase + p];
        int u = uv >> 16, v = uv & 0xffff;
        const float* r = t + (long)b * DIMT + xoff;
        for (int m = 0; m < nm; m++) val += r[u * nm + m] * r[v * nm + m];
    }
    Ph[(long)b * KCP + kbase + p] = __float2half(val);
}

// ---------------- block reduce ----------------
__device__ __forceinline__ float blockReduceSum(float val) {
    __shared__ float sh[8];
    int lane = threadIdx.x & 31, w = threadIdx.x >> 5;
    #pragma unroll
    for (int o = 16; o > 0; o >>= 1) val += __shfl_down_sync(0xffffffffu, val, o);
    __syncthreads();
    if (lane == 0) sh[w] = val;
    __syncthreads();
    float r = 0.f;
    if (threadIdx.x == 0) {
        int nw = blockDim.x >> 5;
        for (int i = 0; i < nw; i++) r += sh[i];
    }
    return r;
}

// ---------------- LayerNorm + SiLU forward ----------------
template<int PER>
__global__ __launch_bounds__(256) void ln_silu_fwd(
    const float* __restrict__ a, const float* __restrict__ gam, const float* __restrict__ bet,
    float* __restrict__ xh, float* __restrict__ rstd,
    float* __restrict__ h, h16* __restrict__ hh)
{
    const int D = PER * 256;
    int b = blockIdx.x, tid = threadIdx.x;
    const float* row = a + (long)b * D;
    float v[PER];
    float s = 0.f;
    #pragma unroll
    for (int i = 0; i < PER; i++) { v[i] = row[tid + (i << 8)]; s += v[i]; }
    s = blockReduceSum(s);
    __shared__ float bc;
    if (tid == 0) bc = s * (1.f / D);
    __syncthreads();
    float mu = bc;
    float q = 0.f;
    #pragma unroll
    for (int i = 0; i < PER; i++) { float d = v[i] - mu; q += d * d; }
    q = blockReduceSum(q);
    if (tid == 0) { float r = rsqrtf(q * (1.f / D) + 1e-6f); bc = r; rstd[b] = r; }
    __syncthreads();
    float r = bc;
    #pragma unroll
    for (int i = 0; i < PER; i++) {
        int c = tid + (i << 8);
        float x = (v[i] - mu) * r;
        xh[(long)b * D + c] = x;
        float z = x * gam[c] + bet[c];
        float sg = 1.f / (1.f + expf(-z));
        float hv = z * sg;
        if (h) h[(long)b * D + c] = hv;
        if (hh) hh[(long)b * D + c] = __float2half(hv);
    }
}

// ---------------- (SiLU + LN) backward ----------------
template<int PER>
__global__ __launch_bounds__(256) void ln_silu_bwd(
    const float* __restrict__ dh, const float* __restrict__ xhv_, const float* __restrict__ rstd,
    const float* __restrict__ gam, const float* __restrict__ bet,
    float* __restrict__ da, h16* __restrict__ dah)
{
    const int D = PER * 256;
    int b = blockIdx.x, tid = threadIdx.x;
    float xh[PER], dxh[PER];
    float s1 = 0.f, s2 = 0.f;
    #pragma unroll
    for (int i = 0; i < PER; i++) {
        int c = tid + (i << 8);
        float x = xhv_[(long)b * D + c];
        float z = x * gam[c] + bet[c];
        float sg = 1.f / (1.f + expf(-z));
        float ds = sg * (1.f + z * (1.f - sg));
        float up = dh ? dh[(long)b * D + c] : 1.f;
        float dx = up * ds * gam[c];
        xh[i] = x; dxh[i] = dx;
        s1 += dx; s2 += dx * x;
    }
    __shared__ float m1s, m2s;
    float t1 = blockReduceSum(s1);
    if (tid == 0) m1s = t1 * (1.f / D);
    float t2 = blockReduceSum(s2);
    if (tid == 0) m2s = t2 * (1.f / D);
    __syncthreads();
    float m1 = m1s, m2 = m2s, r = rstd[b];
    #pragma unroll
    for (int i = 0; i < PER; i++) {
        int c = tid + (i << 8);
        float dv = r * (dxh[i] - m1 - xh[i] * m2);
        if (da) da[(long)b * D + c] = dv;
        if (dah) dah[(long)b * D + c] = __float2half(dv);
    }
}

// ---------------- packed quadratic-form gradients -> y ----------------
__global__ __launch_bounds__(128) void grad0(const float* __restrict__ dPc,
                                             const float* __restrict__ t, float* __restrict__ y)
{
    extern __shared__ float Ts[];   // 128*129 + 128
    float* xs = Ts + 128 * 129;
    int b = blockIdx.x, tid = threadIdx.x;
    xs[tid] = t[(long)b * DIMT + tid];
    const float* P = dPc + (long)b * KCP;
    for (int i = tid; i < T0; i += 128) {
        uint32_t uv = g_uv[i];
        int u = uv >> 16, v = uv & 0xffff;
        float val = P[i];
        Ts[u * 129 + v] = val;
        Ts[v * 129 + u] = (u == v) ? 2.f * val : val;
    }
    __syncthreads();
    float s = 0.f;
    #pragma unroll 8
    for (int v = 0; v < 128; v++) s += Ts[tid * 129 + v] * xs[v];
    y[(long)b * DIMT + tid] = s;
}

__global__ __launch_bounds__(192) void grad1(const float* __restrict__ dPc,
                                             const float* __restrict__ t, float* __restrict__ y)
{
    __shared__ float Ts[64][65];
    __shared__ float xs[192];
    int b = blockIdx.x, tid = threadIdx.x;
    xs[tid] = t[(long)b * DIMT + 128 + tid];
    const float* P = dPc + (long)b * KCP + S1;
    for (int i = tid; i < T1; i += 192) {
        uint32_t uv = g_uv[S1 + i];
        int u = uv >> 16, v = uv & 0xffff;
        float val = P[i];
        Ts[u][v] = val;
        Ts[v][u] = (u == v) ? 2.f * val : val;
    }
    __syncthreads();
    int u = tid / 3, m = tid - u * 3;
    float s = 0.f;
    #pragma unroll 8
    for (int v = 0; v < 64; v++) s += Ts[u][v] * xs[v * 3 + m];
    y[(long)b * DIMT + 128 + tid] = s;
}

__global__ __launch_bounds__(160) void grad2(const float* __restrict__ dPc,
                                             const float* __restrict__ t, float* __restrict__ y)
{
    __shared__ float Ts[32][33];
    __shared__ float xs[160];
    int b = blockIdx.x, tid = threadIdx.x;
    xs[tid] = t[(long)b * DIMT + 320 + tid];
    const float* P = dPc + (long)b * KCP + S2;
    for (int i = tid; i < T2; i += 160) {
        uint32_t uv = g_uv[S2 + i];
        int u = uv >> 16, v = uv & 0xffff;
        float val = P[i];
        Ts[u][v] = val;
        Ts[v][u] = (u == v) ? 2.f * val : val;
    }
    __syncthreads();
    int u = tid / 5, m = tid - u * 5;
    float s = 0.f;
    #pragma unroll 8
    for (int v = 0; v < 32; v++) s += Ts[u][v] * xs[v * 5 + m];
    y[(long)b * DIMT + 320 + tid] = s;
}

// ---------------- launch ----------------
extern "C" void kernel_launch(void* const* d_in, const int* in_sizes, int n_in,
                              void* d_out, int out_size)
{
    const float* tin = (const float*)d_in[0];
    const float* w0  = (const float*)d_in[1];
    const float* w1  = (const float*)d_in[2];
    const float* w2  = (const float*)d_in[3];
    const float* W1  = (const float*)d_in[4];
    const float* b1  = (const float*)d_in[5];
    const float* g1  = (const float*)d_in[6];
    const float* be1 = (const float*)d_in[7];
    const float* W2  = (const float*)d_in[8];
    const float* b2  = (const float*)d_in[9];
    const float* g2  = (const float*)d_in[10];
    const float* be2 = (const float*)d_in[11];

    float* out  = (float*)d_out;
    float* xout = out;
    float* yout = out + (long)NB * ZD;

    h16* hb = nullptr; float* fb = nullptr;
    cudaGetSymbolAddress((void**)&hb, g_hbuf);
    cudaGetSymbolAddress((void**)&fb, g_fbuf);

    h16 *PC   = hb + B_PC;
    h16 *WThi = hb + B_WTHI, *WTlo = hb + B_WTLO;
    h16 *WPhi = hb + B_WPHI, *WPlo = hb + B_WPLO;
    h16 *W1Thi= hb + B_W1THI,*W1Tlo= hb + B_W1TLO;
    h16 *W1hi = hb + B_W1HI, *W1lo = hb + B_W1LO;
    h16 *W2Thi= hb + B_W2THI,*W2Tlo= hb + B_W2TLO;
    h16 *W2hi = hb + B_W2HI, *W2lo = hb + B_W2LO;
    h16 *eh   = hb + B_EH;
    h16 *h1h  = hb + B_H1H;
    h16 *da2h = hb + B_DA2H;
    h16 *da1h = hb + B_DA1H;
    h16 *deh  = hb + B_DEH;

    float *dPC = fb + F_DPC, *a1 = fb + F_A1, *xh1 = fb + F_XH1;
    float *a2  = fb + F_A2,  *xh2= fb + F_XH2, *dh1 = fb + F_DH1;
    float *rs1 = fb + F_RS1, *rs2= fb + F_RS2;

    const float s0 = 1.0f / sqrtf(21504.0f);
    const float s1 = s0 / sqrtf(3.0f);
    const float s2 = s0 / sqrtf(5.0f);

    cudaFuncSetAttribute(h_gemm_nt, cudaFuncAttributeMaxDynamicSharedMemorySize, GSMEM);
    cudaFuncSetAttribute(grad0, cudaFuncAttributeMaxDynamicSharedMemorySize, 128 * 129 * 4 + 512);

    // ---- prep ----
    uv_init<<<(KCP + 255) / 256, 256>>>();
    pack_t<<<dim3(KP0 / 32, HID / 32), 256>>>(w0, WThi, WTlo, 128, T0, KP0, 0, s0);
    pack_t<<<dim3(KP1 / 32, HID / 32), 256>>>(w1, WThi, WTlo, 64, T1, KP1, S1, s1);
    pack_t<<<dim3(KP2 / 32, HID / 32), 256>>>(w2, WThi, WTlo, 32, T2, KP2, S2, s2);
    pack_nt<<<(int)(((long)KP0 * HID + 255) / 256), 256>>>(w0, WPhi, WPlo, 128, T0, KP0, 0, s0);
    pack_nt<<<(int)(((long)KP1 * HID + 255) / 256), 256>>>(w1, WPhi, WPlo, 64, T1, KP1, S1, s1);
    pack_nt<<<(int)(((long)KP2 * HID + 255) / 256), 256>>>(w2, WPhi, WPlo, 32, T2, KP2, S2, s2);
    tsc<<<dim3(HID / 32, HID / 32), 256>>>(W1, W1Thi, W1Tlo, HID, HID, HID);
    tsc<<<dim3(ZD / 32, HID / 32), 256>>>(W2, W2Thi, W2Tlo, HID, ZD, HID);
    sconv<<<(int)((HH + 255) / 256), 256>>>(W1, W1hi, W1lo, HH);
    sconv<<<(int)((ZH + 255) / 256), 256>>>(W2, W2hi, W2lo, ZH);
    build_Pp<<<(int)(((long)NB * KP0 + 255) / 256), 256>>>(tin, PC, 1, 0, T0, KP0, 0);
    build_Pp<<<(int)(((long)NB * KP1 + 255) / 256), 256>>>(tin, PC, 3, 128, T1, KP1, S1);
    build_Pp<<<(int)(((long)NB * KP2 + 255) / 256), 256>>>(tin, PC, 5, 320, T2, KP2, S2);

    // ---- forward ----
    h_gemm_nt<<<dim3(HID / 128, NB / 128), 512, GSMEM>>>(
        PC, WThi, WTlo, nullptr, eh, KCP, HID, 1.f, nullptr);
    h_gemm_nt<<<dim3(HID / 128, NB / 128), 512, GSMEM>>>(
        eh, W1Thi, W1Tlo, a1, nullptr, HID, HID, 1.f, b1);
    ln_silu_fwd<4><<<NB, 256>>>(a1, g1, be1, xh1, rs1, nullptr, h1h);
    h_gemm_nt<<<dim3(ZD / 128, NB / 128), 512, GSMEM>>>(
        h1h, W2Thi, W2Tlo, a2, nullptr, HID, ZD, 1.f, b2);
    ln_silu_fwd<1><<<NB, 256>>>(a2, g2, be2, xh2, rs2, xout, nullptr);

    // ---- backward ----
    ln_silu_bwd<1><<<NB, 256>>>(nullptr, xh2, rs2, g2, be2, nullptr, da2h);
    h_gemm_nt<<<dim3(HID / 128, NB / 128), 512, GSMEM>>>(
        da2h, W2hi, W2lo, dh1, nullptr, ZD, HID, 1.f, nullptr);
    ln_silu_bwd<4><<<NB, 256>>>(dh1, xh1, rs1, g1, be1, nullptr, da1h);
    h_gemm_nt<<<dim3(HID / 128, NB / 128), 512, GSMEM>>>(
        da1h, W1hi, W1lo, nullptr, deh, HID, HID, 1.f, nullptr);
    h_gemm_nt<<<dim3(KCP / 128, NB / 128), 512, GSMEM>>>(
        deh, WPhi, WPlo, dPC, nullptr, HID, KCP, 1.f, nullptr);

    grad0<<<NB, 128, 128 * 129 * 4 + 512>>>(dPC, tin, yout);
    grad1<<<NB, 192>>>(dPC, tin, yout);
    grad2<<<NB, 160>>>(dPC, tin, yout);
}

// round 9
// speedup vs baseline: 5.9738x; 1.0453x over previous
#include <cuda_runtime.h>
#include <cuda_fp16.h>
#include <math.h>
#include <stdint.h>

#define NB   2048
#define DIMT 480
#define HID  1024
#define ZD   256
#define T0   8256
#define KP0  8256
#define T1   2080
#define KP1  2112
#define T2   528
#define KP2  640
#define KCP  11008
#define S1   8256
#define S2   10368

typedef __half h16;

// ---------------- scratch pools ----------------
constexpr long NBKC = (long)NB * KCP;
constexpr long HKC  = (long)HID * KCP;
constexpr long HH   = (long)HID * HID;
constexpr long ZH   = (long)ZD * HID;
constexpr long NH   = (long)NB * HID;
constexpr long NZ   = (long)NB * ZD;

constexpr long B_PC   = 0;
constexpr long B_WTHI = B_PC   + NBKC;
constexpr long B_WTLO = B_WTHI + HKC;
constexpr long B_WPHI = B_WTLO + HKC;
constexpr long B_WPLO = B_WPHI + HKC;
constexpr long B_W1THI= B_WPLO + HKC;
constexpr long B_W1TLO= B_W1THI + HH;
constexpr long B_W1HI = B_W1TLO + HH;
constexpr long B_W1LO = B_W1HI + HH;
constexpr long B_W2THI= B_W1LO + HH;
constexpr long B_W2TLO= B_W2THI + ZH;
constexpr long B_W2HI = B_W2TLO + ZH;
constexpr long B_W2LO = B_W2HI + ZH;
constexpr long B_EH   = B_W2LO + ZH;
constexpr long B_H1H  = B_EH   + NH;
constexpr long B_DA2H = B_H1H  + NH;
constexpr long B_DA1H = B_DA2H + NZ;
constexpr long B_DEH  = B_DA1H + NH;
constexpr long B_TOT  = B_DEH  + NH;

constexpr long F_DPC  = 0;
constexpr long F_A1   = F_DPC + NBKC;
constexpr long F_XH1  = F_A1  + NH;
constexpr long F_A2   = F_XH1 + NH;
constexpr long F_DH1  = F_A2  + NZ;
constexpr long F_RS1  = F_DH1 + NH;
constexpr long F_TOT  = F_RS1 + NB;

__device__ h16      g_hbuf[B_TOT];
__device__ float    g_fbuf[F_TOT];
__device__ uint32_t g_uv[KCP];

// ---------------- helpers ----------------
__device__ __forceinline__ uint32_t smem_u32(const void* p) {
    uint32_t a;
    asm("{ .reg .u64 t; cvta.to.shared.u64 t, %1; cvt.u32.u64 %0, t; }" : "=r"(a) : "l"(p));
    return a;
}
__device__ __forceinline__ void ldsm4(uint32_t* r, uint32_t a) {
    asm volatile("ldmatrix.sync.aligned.m8n8.x4.shared.b16 {%0,%1,%2,%3},[%4];"
                 : "=r"(r[0]), "=r"(r[1]), "=r"(r[2]), "=r"(r[3]) : "r"(a));
}
__device__ __forceinline__ void mma_f16(float* d, const uint32_t* a, const uint32_t* b) {
    asm volatile("mma.sync.aligned.m16n8k16.row.col.f32.f16.f16.f32 "
                 "{%0,%1,%2,%3},{%4,%5,%6,%7},{%8,%9},{%0,%1,%2,%3};"
                 : "+f"(d[0]), "+f"(d[1]), "+f"(d[2]), "+f"(d[3])
                 : "r"(a[0]), "r"(a[1]), "r"(a[2]), "r"(a[3]), "r"(b[0]), "r"(b[1]));
}
#define CPA(dst, src) asm volatile("cp.async.cg.shared.global [%0], [%1], 16;" :: "r"(dst), "l"(src) : "memory")
#define CPCOMMIT()    asm volatile("cp.async.commit_group;" ::: "memory")
#define CPWAIT1()     asm volatile("cp.async.wait_group 1;" ::: "memory")

__device__ __forceinline__ void splith(float v, h16& h, h16& l) {
    h = __float2half(v);
    l = __float2half((v - __half2float(h)) * 2048.f);
}

// ---------------- pair LUT ----------------
__global__ void uv_init() {
    int p = blockIdx.x * 256 + threadIdx.x;
    if (p >= KCP) return;
    int n, lp, T;
    if (p < S1)      { n = 128; lp = p;      T = T0; }
    else if (p < S2) { n = 64;  lp = p - S1; T = T1; }
    else             { n = 32;  lp = p - S2; T = T2; }
    if (lp >= T) { g_uv[p] = 0u; return; }
    float tn = 2.f * n + 1.f;
    int u = (int)((tn - sqrtf(tn * tn - 8.f * lp)) * 0.5f);
    if (u < 0) u = 0; if (u > n - 1) u = n - 1;
    while (u > 0 && u * n - u * (u - 1) / 2 > lp) u--;
    while (u < n - 1 && (u + 1) * n - (u + 1) * u / 2 <= lp) u++;
    int v = u + (lp - (u * n - u * (u - 1) / 2));
    g_uv[p] = ((uint32_t)u << 16) | (uint32_t)v;
}

// ---------------- fp16 2-mma NT GEMM: 512 threads, 32x32 warp tiles ----------------
#define TILEH 16384
#define STGH  (3 * TILEH)
#define GSMEM (3 * STGH + 1024)

__global__ __launch_bounds__(512, 1) void h_gemm_nt(
    const h16* __restrict__ A, const h16* __restrict__ Bhi, const h16* __restrict__ Blo,
    float* __restrict__ C, h16* __restrict__ Ch,
    int K, long ldc, float alpha, const float* __restrict__ bias)
{
    extern __shared__ char smem[];
    const uint32_t st0 = (smem_u32(smem) + 1023) & ~1023u;
    const int tid = threadIdx.x, wid = tid >> 5, lane = tid & 31;
    const int wm = wid >> 2, wn = wid & 3;
    const long bm = (long)blockIdx.y * 128, bn = (long)blockIdx.x * 128;

    const h16* gp[6];
    uint32_t so[6];
    #pragma unroll
    for (int t = 0; t < 6; t++) {
        int q = tid + (t & 1) * 512;
        int r = q >> 3, c = q & 7;
        int tile = t >> 1;
        const h16* base = (tile == 0) ? A : (tile == 1) ? Bhi : Blo;
        long row = (tile == 0 ? bm : bn) + r;
        gp[t] = base + row * K + c * 8;
        so[t] = st0 + tile * TILEH + ((r * 128 + c * 16) ^ ((r & 7) << 4));
    }
    const int nk = K >> 6;

    #pragma unroll
    for (int p = 0; p < 2; p++) {
        #pragma unroll
        for (int t = 0; t < 6; t++) CPA(so[t] + p * STGH, gp[t] + (long)p * 64);
        CPCOMMIT();
    }

    float ac1[2][4][4], ac2[2][4][4];
    #pragma unroll
    for (int a = 0; a < 2; a++)
        #pragma unroll
        for (int b = 0; b < 4; b++)
            #pragma unroll
            for (int c = 0; c < 4; c++) { ac1[a][b][c] = 0.f; ac2[a][b][c] = 0.f; }

    const int lr = lane & 15, lc = lane >> 4;
    const uint32_t xa = (lr & 7) << 4;
    const uint32_t arow = (wm * 32 + lr) * 128 + lc * 16;
    const uint32_t brow = (wn * 32 + lr) * 128 + lc * 16;

    for (int i = 0; i < nk; i++) {
        CPWAIT1();
        __syncthreads();
        if (i + 2 < nk) {
            const uint32_t sst = ((i + 2) % 3) * STGH;
            #pragma unroll
            for (int t = 0; t < 6; t++) CPA(so[t] + sst, gp[t] + (long)(i + 2) * 64);
        }
        CPCOMMIT();

        const uint32_t sa = st0 + (i % 3) * STGH;
        #pragma unroll
        for (int kk = 0; kk < 4; kk++) {
            uint32_t af[2][4], bh[4][2], bl[4][2];
            #pragma unroll
            for (int mi = 0; mi < 2; mi++)
                ldsm4(af[mi], sa + ((arow + mi * 2048 + kk * 32) ^ xa));
            #pragma unroll
            for (int pi = 0; pi < 2; pi++) {
                uint32_t off = (brow + pi * 2048 + kk * 32) ^ xa;
                uint32_t t0[4], t1[4];
                ldsm4(t0, sa + TILEH + off);
                ldsm4(t1, sa + 2 * TILEH + off);
                bh[2 * pi][0] = t0[0]; bh[2 * pi + 1][0] = t0[1];
                bh[2 * pi][1] = t0[2]; bh[2 * pi + 1][1] = t0[3];
                bl[2 * pi][0] = t1[0]; bl[2 * pi + 1][0] = t1[1];
                bl[2 * pi][1] = t1[2]; bl[2 * pi + 1][1] = t1[3];
            }
            #pragma unroll
            for (int mi = 0; mi < 2; mi++)
                #pragma unroll
                for (int ni = 0; ni < 4; ni++) {
                    mma_f16(ac1[mi][ni], af[mi], bh[ni]);
                    mma_f16(ac2[mi][ni], af[mi], bl[ni]);
                }
        }
    }

    const int g = lane >> 2, tg = lane & 3;
    const float inv = 1.f / 2048.f;
    #pragma unroll
    for (int mi = 0; mi < 2; mi++) {
        #pragma unroll
        for (int ni = 0; ni < 4; ni++) {
            long m0 = bm + wm * 32 + mi * 16 + g;
            long n0 = bn + wn * 32 + ni * 8 + tg * 2;
            float v00 = alpha * (ac1[mi][ni][0] + ac2[mi][ni][0] * inv);
            float v01 = alpha * (ac1[mi][ni][1] + ac2[mi][ni][1] * inv);
            float v10 = alpha * (ac1[mi][ni][2] + ac2[mi][ni][2] * inv);
            float v11 = alpha * (ac1[mi][ni][3] + ac2[mi][ni][3] * inv);
            if (bias) {
                float bb0 = bias[n0], bb1 = bias[n0 + 1];
                v00 += bb0; v01 += bb1; v10 += bb0; v11 += bb1;
            }
            if (C) {
                *(float2*)(C + m0 * ldc + n0) = make_float2(v00, v01);
                *(float2*)(C + (m0 + 8) * ldc + n0) = make_float2(v10, v11);
            }
            if (Ch) {
                *(__half2*)(Ch + m0 * ldc + n0) = __floats2half2_rn(v00, v01);
                *(__half2*)(Ch + (m0 + 8) * ldc + n0) = __floats2half2_rn(v10, v11);
            }
        }
    }
}

// ---------------- merged prep kernels ----------------
// pack_t_all: grid (258+66+20, 32)
__global__ __launch_bounds__(256) void pack_t_all(
    const float* __restrict__ w0, const float* __restrict__ w1, const float* __restrict__ w2,
    h16* __restrict__ dhi, h16* __restrict__ dlo, float sc0, float sc1, float sc2)
{
    __shared__ float sv[32][33];
    int bx = blockIdx.x;
    const float* w; int n, T; long kbase; float s;
    int pb;
    if (bx < 258)      { w = w0; n = 128; T = T0; kbase = 0;  s = sc0; pb = bx * 32; }
    else if (bx < 324) { w = w1; n = 64;  T = T1; kbase = S1; s = sc1; pb = (bx - 258) * 32; }
    else               { w = w2; n = 32;  T = T2; kbase = S2; s = sc2; pb = (bx - 324) * 32; }
    int hb = blockIdx.y * 32;
    int tx = threadIdx.x & 31, ty = threadIdx.x >> 5;
    #pragma unroll
    for (int i = 0; i < 32; i += 8) {
        int pp = pb + ty + i;
        float val = 0.f;
        if (pp < T) {
            uint32_t uv = g_uv[kbase + pp];
            int u = uv >> 16, v = uv & 0xffff;
            val = w[((long)u * n + v) * HID + hb + tx];
            if (u != v) val += w[((long)v * n + u) * HID + hb + tx];
            val *= s;
        }
        sv[ty + i][tx] = val;
    }
    __syncthreads();
    #pragma unroll
    for (int i = 0; i < 32; i += 8) {
        float val = sv[tx][ty + i];
        h16 hh, ll; splith(val, hh, ll);
        long o = (long)(hb + ty + i) * KCP + kbase + pb + tx;
        dhi[o] = hh; dlo[o] = ll;
    }
}

// pack_nt_all: linear over KCP*HID
__global__ void pack_nt_all(
    const float* __restrict__ w0, const float* __restrict__ w1, const float* __restrict__ w2,
    h16* __restrict__ dhi, h16* __restrict__ dlo, float sc0, float sc1, float sc2)
{
    long idx = (long)blockIdx.x * 256 + threadIdx.x;
    if (idx >= (long)KCP * HID) return;
    int p = (int)(idx / HID), h = (int)(idx % HID);
    const float* w; int n, T, lp; float s;
    if (p < KP0)     { w = w0; n = 128; T = T0; lp = p;      s = sc0; }
    else if (p < S2) { w = w1; n = 64;  T = T1; lp = p - S1; s = sc1; }
    else             { w = w2; n = 32;  T = T2; lp = p - S2; s = sc2; }
    float val = 0.f;
    if (lp < T) {
        uint32_t uv = g_uv[p];
        int u = uv >> 16, v = uv & 0xffff;
        val = w[((long)u * n + v) * HID + h];
        if (u != v) val += w[((long)v * n + u) * HID + h];
        val *= s;
    }
    h16 hh, ll; splith(val, hh, ll);
    dhi[(long)p * HID + h] = hh; dlo[(long)p * HID + h] = ll;
}

// dense_all: tsc W1 (1024) | tsc W2 (256) | sconv W1 (4096) | sconv W2 (1024)
__global__ __launch_bounds__(256) void dense_all(
    const float* __restrict__ W1, const float* __restrict__ W2,
    h16* __restrict__ W1Thi, h16* __restrict__ W1Tlo,
    h16* __restrict__ W2Thi, h16* __restrict__ W2Tlo,
    h16* __restrict__ W1hi, h16* __restrict__ W1lo,
    h16* __restrict__ W2hi, h16* __restrict__ W2lo)
{
    __shared__ float t[32][33];
    long lin = blockIdx.x;
    if (lin < 1024 + 256) {
        const float* src; h16 *dhi, *dlo; int C; long ldd; int gx, gy;
        if (lin < 1024) { src = W1; dhi = W1Thi; dlo = W1Tlo; C = HID; ldd = HID; gx = (int)(lin % 32); gy = (int)(lin / 32); }
        else { long l = lin - 1024; src = W2; dhi = W2Thi; dlo = W2Tlo; C = ZD; ldd = HID; gx = (int)(l % 8); gy = (int)(l / 8); }
        int bx = gx * 32, by = gy * 32;
        int tx = threadIdx.x & 31, ty = threadIdx.x >> 5;
        #pragma unroll
        for (int i = 0; i < 32; i += 8)
            t[ty + i][tx] = src[(long)(by + ty + i) * C + bx + tx];
        __syncthreads();
        #pragma unroll
        for (int i = 0; i < 32; i += 8) {
            h16 h, l; splith(t[tx][ty + i], h, l);
            long o = (long)(bx + ty + i) * ldd + by + tx;
            dhi[o] = h; dlo[o] = l;
        }
    } else if (lin < 1024 + 256 + 4096) {
        long i = (lin - 1280) * 256 + threadIdx.x;
        if (i < HH) { h16 h, l; splith(W1[i], h, l); W1hi[i] = h; W1lo[i] = l; }
    } else {
        long i = (lin - 5376) * 256 + threadIdx.x;
        if (i < ZH) { h16 h, l; splith(W2[i], h, l); W2hi[i] = h; W2lo[i] = l; }
    }
}

// build_Pp_all: linear over NB*KCP
__global__ void build_Pp_all(const float* __restrict__ t, h16* __restrict__ Ph)
{
    long idx = (long)blockIdx.x * 256 + threadIdx.x;
    if (idx >= (long)NB * KCP) return;
    int b = (int)(idx / KCP), p = (int)(idx % KCP);
    int nm, xoff, T, lp;
    if (p < KP0)     { nm = 1; xoff = 0;   T = T0; lp = p; }
    else if (p < S2) { nm = 3; xoff = 128; T = T1; lp = p - S1; }
    else             { nm = 5; xoff = 320; T = T2; lp = p - S2; }
    float val = 0.f;
    if (lp < T) {
        uint32_t uv = g_uv[p];
        int u = uv >> 16, v = uv & 0xffff;
        const float* r = t + (long)b * DIMT + xoff;
        for (int m = 0; m < nm; m++) val += r[u * nm + m] * r[v * nm + m];
    }
    Ph[idx] = __float2half(val);
}

// ---------------- block reduce ----------------
__device__ __forceinline__ float blockReduceSum(float val) {
    __shared__ float sh[8];
    int lane = threadIdx.x & 31, w = threadIdx.x >> 5;
    #pragma unroll
    for (int o = 16; o > 0; o >>= 1) val += __shfl_down_sync(0xffffffffu, val, o);
    __syncthreads();
    if (lane == 0) sh[w] = val;
    __syncthreads();
    float r = 0.f;
    if (threadIdx.x == 0) {
        int nw = blockDim.x >> 5;
        for (int i = 0; i < nw; i++) r += sh[i];
    }
    return r;
}

// ---------------- LayerNorm + SiLU forward (layer 1) ----------------
__global__ __launch_bounds__(256) void ln_silu_fwd4(
    const float* __restrict__ a, const float* __restrict__ gam, const float* __restrict__ bet,
    float* __restrict__ xh, float* __restrict__ rstd, h16* __restrict__ hh)
{
    const int D = 1024;
    int b = blockIdx.x, tid = threadIdx.x;
    const float* row = a + (long)b * D;
    float v[4];
    float s = 0.f;
    #pragma unroll
    for (int i = 0; i < 4; i++) { v[i] = row[tid + (i << 8)]; s += v[i]; }
    s = blockReduceSum(s);
    __shared__ float bc;
    if (tid == 0) bc = s * (1.f / D);
    __syncthreads();
    float mu = bc;
    float q = 0.f;
    #pragma unroll
    for (int i = 0; i < 4; i++) { float d = v[i] - mu; q += d * d; }
    q = blockReduceSum(q);
    if (tid == 0) { float r = rsqrtf(q * (1.f / D) + 1e-6f); bc = r; rstd[b] = r; }
    __syncthreads();
    float r = bc;
    #pragma unroll
    for (int i = 0; i < 4; i++) {
        int c = tid + (i << 8);
        float x = (v[i] - mu) * r;
        xh[(long)b * D + c] = x;
        float z = x * gam[c] + bet[c];
        float sg = 1.f / (1.f + expf(-z));
        hh[(long)b * D + c] = __float2half(z * sg);
    }
}

// ---------------- fused LN2 fwd + bwd (layer 2, upstream ones) ----------------
__global__ __launch_bounds__(256) void ln2_fused(
    const float* __restrict__ a, const float* __restrict__ gam, const float* __restrict__ bet,
    float* __restrict__ xout, h16* __restrict__ dah)
{
    const int D = 256;
    int b = blockIdx.x, tid = threadIdx.x;
    float v = a[(long)b * D + tid];
    float s = blockReduceSum(v);
    __shared__ float bc;
    if (tid == 0) bc = s * (1.f / D);
    __syncthreads();
    float mu = bc;
    float d = v - mu;
    float q = blockReduceSum(d * d);
    if (tid == 0) bc = rsqrtf(q * (1.f / D) + 1e-6f);
    __syncthreads();
    float r = bc;
    float x = (v - mu) * r;
    float z = x * gam[tid] + bet[tid];
    float sg = 1.f / (1.f + expf(-z));
    xout[(long)b * D + tid] = z * sg;
    // backward with upstream = 1
    float ds = sg * (1.f + z * (1.f - sg));
    float dx = ds * gam[tid];
    float t1 = blockReduceSum(dx);
    __shared__ float m1s, m2s;
    if (tid == 0) m1s = t1 * (1.f / D);
    float t2 = blockReduceSum(dx * x);
    if (tid == 0) m2s = t2 * (1.f / D);
    __syncthreads();
    dah[(long)b * D + tid] = __float2half(r * (dx - m1s - x * m2s));
}

// ---------------- (SiLU + LN) backward (layer 1) ----------------
__global__ __launch_bounds__(256) void ln_silu_bwd4(
    const float* __restrict__ dh, const float* __restrict__ xhv_, const float* __restrict__ rstd,
    const float* __restrict__ gam, const float* __restrict__ bet, h16* __restrict__ dah)
{
    const int D = 1024;
    int b = blockIdx.x, tid = threadIdx.x;
    float xh[4], dxh[4];
    float s1 = 0.f, s2 = 0.f;
    #pragma unroll
    for (int i = 0; i < 4; i++) {
        int c = tid + (i << 8);
        float x = xhv_[(long)b * D + c];
        float z = x * gam[c] + bet[c];
        float sg = 1.f / (1.f + expf(-z));
        float ds = sg * (1.f + z * (1.f - sg));
        float dx = dh[(long)b * D + c] * ds * gam[c];
        xh[i] = x; dxh[i] = dx;
        s1 += dx; s2 += dx * x;
    }
    __shared__ float m1s, m2s;
    float t1 = blockReduceSum(s1);
    if (tid == 0) m1s = t1 * (1.f / D);
    float t2 = blockReduceSum(s2);
    if (tid == 0) m2s = t2 * (1.f / D);
    __syncthreads();
    float m1 = m1s, m2 = m2s, r = rstd[b];
    #pragma unroll
    for (int i = 0; i < 4; i++) {
        int c = tid + (i << 8);
        dah[(long)b * D + c] = __float2half(r * (dxh[i] - m1 - xh[i] * m2));
    }
}

// ---------------- merged packed quadratic-form gradients -> y ----------------
// blocks [0,2048) grad0 | [2048,4096) grad1 | [4096,6144) grad2 ; 192 threads
__global__ __launch_bounds__(192) void grad_all(const float* __restrict__ dPc,
                                                const float* __restrict__ t, float* __restrict__ y)
{
    extern __shared__ float Ts[];
    int tid = threadIdx.x;
    if (blockIdx.x < 2048) {
        int b = blockIdx.x;
        float* xs = Ts + 128 * 129;
        if (tid < 128) xs[tid] = t[(long)b * DIMT + tid];
        const float* P = dPc + (long)b * KCP;
        for (int i = tid; i < T0; i += 192) {
            uint32_t uv = g_uv[i];
            int u = uv >> 16, v = uv & 0xffff;
            float val = P[i];
            Ts[u * 129 + v] = val;
            Ts[v * 129 + u] = (u == v) ? 2.f * val : val;
        }
        __syncthreads();
        if (tid < 128) {
            float s = 0.f;
            #pragma unroll 8
            for (int v = 0; v < 128; v++) s += Ts[tid * 129 + v] * xs[v];
            y[(long)b * DIMT + tid] = s;
        }
    } else if (blockIdx.x < 4096) {
        int b = blockIdx.x - 2048;
        float* xs = Ts + 64 * 65;
        xs[tid] = t[(long)b * DIMT + 128 + tid];
        const float* P = dPc + (long)b * KCP + S1;
        for (int i = tid; i < T1; i += 192) {
            uint32_t uv = g_uv[S1 + i];
            int u = uv >> 16, v = uv & 0xffff;
            float val = P[i];
            Ts[u * 65 + v] = val;
            Ts[v * 65 + u] = (u == v) ? 2.f * val : val;
        }
        __syncthreads();
        int u = tid / 3, m = tid - u * 3;
        float s = 0.f;
        #pragma unroll 8
        for (int v = 0; v < 64; v++) s += Ts[u * 65 + v] * xs[v * 3 + m];
        y[(long)b * DIMT + 128 + tid] = s;
    } else {
        int b = blockIdx.x - 4096;
        float* xs = Ts + 32 * 33;
        if (tid < 160) xs[tid] = t[(long)b * DIMT + 320 + tid];
        const float* P = dPc + (long)b * KCP + S2;
        for (int i = tid; i < T2; i += 192) {
            uint32_t uv = g_uv[S2 + i];
            int u = uv >> 16, v = uv & 0xffff;
            float val = P[i];
            Ts[u * 33 + v] = val;
            Ts[v * 33 + u] = (u == v) ? 2.f * val : val;
        }
        __syncthreads();
        if (tid < 160) {
            int u = tid / 5, m = tid - u * 5;
            float s = 0.f;
            #pragma unroll 8
            for (int v = 0; v < 32; v++) s += Ts[u * 33 + v] * xs[v * 5 + m];
            y[(long)b * DIMT + 320 + tid] = s;
        }
    }
}

// ---------------- launch ----------------
extern "C" void kernel_launch(void* const* d_in, const int* in_sizes, int n_in,
                              void* d_out, int out_size)
{
    const float* tin = (const float*)d_in[0];
    const float* w0  = (const float*)d_in[1];
    const float* w1  = (const float*)d_in[2];
    const float* w2  = (const float*)d_in[3];
    const float* W1  = (const float*)d_in[4];
    const float* b1  = (const float*)d_in[5];
    const float* g1  = (const float*)d_in[6];
    const float* be1 = (const float*)d_in[7];
    const float* W2  = (const float*)d_in[8];
    const float* b2  = (const float*)d_in[9];
    const float* g2  = (const float*)d_in[10];
    const float* be2 = (const float*)d_in[11];

    float* out  = (float*)d_out;
    float* xout = out;
    float* yout = out + (long)NB * ZD;

    h16* hb = nullptr; float* fb = nullptr;
    cudaGetSymbolAddress((void**)&hb, g_hbuf);
    cudaGetSymbolAddress((void**)&fb, g_fbuf);

    h16 *PC   = hb + B_PC;
    h16 *WThi = hb + B_WTHI, *WTlo = hb + B_WTLO;
    h16 *WPhi = hb + B_WPHI, *WPlo = hb + B_WPLO;
    h16 *W1Thi= hb + B_W1THI,*W1Tlo= hb + B_W1TLO;
    h16 *W1hi = hb + B_W1HI, *W1lo = hb + B_W1LO;
    h16 *W2Thi= hb + B_W2THI,*W2Tlo= hb + B_W2TLO;
    h16 *W2hi = hb + B_W2HI, *W2lo = hb + B_W2LO;
    h16 *eh   = hb + B_EH;
    h16 *h1h  = hb + B_H1H;
    h16 *da2h = hb + B_DA2H;
    h16 *da1h = hb + B_DA1H;
    h16 *deh  = hb + B_DEH;

    float *dPC = fb + F_DPC, *a1 = fb + F_A1, *xh1 = fb + F_XH1;
    float *a2  = fb + F_A2,  *dh1 = fb + F_DH1, *rs1 = fb + F_RS1;

    const float s0 = 1.0f / sqrtf(21504.0f);
    const float s1 = s0 / sqrtf(3.0f);
    const float s2 = s0 / sqrtf(5.0f);

    cudaFuncSetAttribute(h_gemm_nt, cudaFuncAttributeMaxDynamicSharedMemorySize, GSMEM);
    cudaFuncSetAttribute(grad_all, cudaFuncAttributeMaxDynamicSharedMemorySize, 128 * 129 * 4 + 768);

    // ---- prep (5 launches, so launch #6 = e-GEMM for ncu -s 5 -c 1) ----
    uv_init<<<(KCP + 255) / 256, 256>>>();
    pack_t_all<<<dim3(344, HID / 32), 256>>>(w0, w1, w2, WThi, WTlo, s0, s1, s2);
    pack_nt_all<<<(int)(((long)KCP * HID + 255) / 256), 256>>>(w0, w1, w2, WPhi, WPlo, s0, s1, s2);
    dense_all<<<6400, 256>>>(W1, W2, W1Thi, W1Tlo, W2Thi, W2Tlo, W1hi, W1lo, W2hi, W2lo);
    build_Pp_all<<<(int)(((long)NB * KCP + 255) / 256), 256>>>(tin, PC);

    // ---- forward ----
    h_gemm_nt<<<dim3(HID / 128, NB / 128), 512, GSMEM>>>(
        PC, WThi, WTlo, nullptr, eh, KCP, HID, 1.f, nullptr);
    h_gemm_nt<<<dim3(HID / 128, NB / 128), 512, GSMEM>>>(
        eh, W1Thi, W1Tlo, a1, nullptr, HID, HID, 1.f, b1);
    ln_silu_fwd4<<<NB, 256>>>(a1, g1, be1, xh1, rs1, h1h);
    h_gemm_nt<<<dim3(ZD / 128, NB / 128), 512, GSMEM>>>(
        h1h, W2Thi, W2Tlo, a2, nullptr, HID, ZD, 1.f, b2);
    ln2_fused<<<NB, 256>>>(a2, g2, be2, xout, da2h);

    // ---- backward ----
    h_gemm_nt<<<dim3(HID / 128, NB / 128), 512, GSMEM>>>(
        da2h, W2hi, W2lo, dh1, nullptr, ZD, HID, 1.f, nullptr);
    ln_silu_bwd4<<<NB, 256>>>(dh1, xh1, rs1, g1, be1, da1h);
    h_gemm_nt<<<dim3(HID / 128, NB / 128), 512, GSMEM>>>(
        da1h, W1hi, W1lo, nullptr, deh, HID, HID, 1.f, nullptr);
    h_gemm_nt<<<dim3(KCP / 128, NB / 128), 512, GSMEM>>>(
        deh, WPhi, WPlo, dPC, nullptr, HID, KCP, 1.f, nullptr);

    grad_all<<<6144, 192, 128 * 129 * 4 + 768>>>(dPC, tin, yout);
}

// round 10
// speedup vs baseline: 6.2870x; 1.0524x over previous
#include <cuda_runtime.h>
#include <cuda_fp16.h>
#include <math.h>
#include <stdint.h>

#define NB   2048
#define DIMT 480
#define HID  1024
#define ZD   256
#define T0   8256
#define KP0  8256
#define T1   2080
#define KP1  2112
#define T2   528
#define KP2  640
#define KCP  11008
#define S1   8256
#define S2   10368

typedef __half h16;

// ---------------- scratch pools ----------------
constexpr long NBKC = (long)NB * KCP;
constexpr long HKC  = (long)HID * KCP;
constexpr long HH   = (long)HID * HID;
constexpr long ZH   = (long)ZD * HID;
constexpr long NH   = (long)NB * HID;
constexpr long NZ   = (long)NB * ZD;

constexpr long B_PC   = 0;
constexpr long B_WTHI = B_PC   + NBKC;
constexpr long B_WTLO = B_WTHI + HKC;
constexpr long B_WPHI = B_WTLO + HKC;
constexpr long B_WPLO = B_WPHI + HKC;
constexpr long B_W1THI= B_WPLO + HKC;
constexpr long B_W1TLO= B_W1THI + HH;
constexpr long B_W1HI = B_W1TLO + HH;
constexpr long B_W1LO = B_W1HI + HH;
constexpr long B_W2THI= B_W1LO + HH;
constexpr long B_W2TLO= B_W2THI + ZH;
constexpr long B_W2HI = B_W2TLO + ZH;
constexpr long B_W2LO = B_W2HI + ZH;
constexpr long B_EH   = B_W2LO + ZH;
constexpr long B_H1H  = B_EH   + NH;
constexpr long B_DA2H = B_H1H  + NH;
constexpr long B_DA1H = B_DA2H + NZ;
constexpr long B_DEH  = B_DA1H + NH;
constexpr long B_TOT  = B_DEH  + NH;

constexpr long F_DPC  = 0;
constexpr long F_A1   = F_DPC + NBKC;
constexpr long F_XH1  = F_A1  + NH;
constexpr long F_A2   = F_XH1 + NH;
constexpr long F_DH1  = F_A2  + NZ;
constexpr long F_RS1  = F_DH1 + NH;
constexpr long F_TOT  = F_RS1 + NB;

__device__ h16      g_hbuf[B_TOT];
__device__ float    g_fbuf[F_TOT];
__device__ uint32_t g_uv[KCP];

// ---------------- helpers ----------------
__device__ __forceinline__ uint32_t smem_u32(const void* p) {
    uint32_t a;
    asm("{ .reg .u64 t; cvta.to.shared.u64 t, %1; cvt.u32.u64 %0, t; }" : "=r"(a) : "l"(p));
    return a;
}
__device__ __forceinline__ void ldsm4(uint32_t* r, uint32_t a) {
    asm volatile("ldmatrix.sync.aligned.m8n8.x4.shared.b16 {%0,%1,%2,%3},[%4];"
                 : "=r"(r[0]), "=r"(r[1]), "=r"(r[2]), "=r"(r[3]) : "r"(a));
}
__device__ __forceinline__ void mma_f16(float* d, const uint32_t* a, const uint32_t* b) {
    asm volatile("mma.sync.aligned.m16n8k16.row.col.f32.f16.f16.f32 "
                 "{%0,%1,%2,%3},{%4,%5,%6,%7},{%8,%9},{%0,%1,%2,%3};"
                 : "+f"(d[0]), "+f"(d[1]), "+f"(d[2]), "+f"(d[3])
                 : "r"(a[0]), "r"(a[1]), "r"(a[2]), "r"(a[3]), "r"(b[0]), "r"(b[1]));
}
#define CPA(dst, src) asm volatile("cp.async.cg.shared.global [%0], [%1], 16;" :: "r"(dst), "l"(src) : "memory")
#define CPCOMMIT()    asm volatile("cp.async.commit_group;" ::: "memory")
#define CPWAIT0()     asm volatile("cp.async.wait_group 0;" ::: "memory")

__device__ __forceinline__ void splith(float v, h16& h, h16& l) {
    h = __float2half(v);
    l = __float2half((v - __half2float(h)) * 2048.f);
}

// ---------------- pair LUT ----------------
__global__ void uv_init() {
    int p = blockIdx.x * 256 + threadIdx.x;
    if (p >= KCP) return;
    int n, lp, T;
    if (p < S1)      { n = 128; lp = p;      T = T0; }
    else if (p < S2) { n = 64;  lp = p - S1; T = T1; }
    else             { n = 32;  lp = p - S2; T = T2; }
    if (lp >= T) { g_uv[p] = 0u; return; }
    float tn = 2.f * n + 1.f;
    int u = (int)((tn - sqrtf(tn * tn - 8.f * lp)) * 0.5f);
    if (u < 0) u = 0; if (u > n - 1) u = n - 1;
    while (u > 0 && u * n - u * (u - 1) / 2 > lp) u--;
    while (u < n - 1 && (u + 1) * n - (u + 1) * u / 2 <= lp) u++;
    int v = u + (lp - (u * n - u * (u - 1) / 2));
    g_uv[p] = ((uint32_t)u << 16) | (uint32_t)v;
}

// ---------------- fp16 2-mma NT GEMM: BK=128, 2-stage, 512 threads ----------------
#define TILEH 32768          // 128 rows x 256 B
#define STGH  (3 * TILEH)    // A, Bhi, Blo = 96 KB
#define GSMEM (2 * STGH + 1024)

__global__ __launch_bounds__(512, 1) void h_gemm_nt(
    const h16* __restrict__ A, const h16* __restrict__ Bhi, const h16* __restrict__ Blo,
    float* __restrict__ C, h16* __restrict__ Ch,
    int K, long ldc, float alpha, const float* __restrict__ bias)
{
    extern __shared__ char smem[];
    const uint32_t st0 = (smem_u32(smem) + 1023) & ~1023u;
    const int tid = threadIdx.x, wid = tid >> 5, lane = tid & 31;
    const int wm = wid >> 2, wn = wid & 3;
    const long bm = (long)blockIdx.y * 128, bn = (long)blockIdx.x * 128;

    // 12 chunks of 16B per thread per stage (3 tiles x 4)
    const h16* gp[12];
    uint32_t so[12];
    #pragma unroll
    for (int t = 0; t < 12; t++) {
        int q = tid + (t & 3) * 512;        // 0..2047
        int r = q >> 4, c = q & 15;         // 128 rows x 16 chunks
        int tile = t >> 2;                  // 0=A 1=Bhi 2=Blo
        const h16* base = (tile == 0) ? A : (tile == 1) ? Bhi : Blo;
        long row = (tile == 0 ? bm : bn) + r;
        gp[t] = base + row * K + c * 8;
        so[t] = st0 + tile * TILEH + ((r * 256 + c * 16) ^ ((r & 7) << 4));
    }
    const int nk = K >> 7;

    // prologue: ktile 0 -> stage 0
    #pragma unroll
    for (int t = 0; t < 12; t++) CPA(so[t], gp[t]);
    CPCOMMIT();

    float ac1[2][4][4], ac2[2][4][4];
    #pragma unroll
    for (int a = 0; a < 2; a++)
        #pragma unroll
        for (int b = 0; b < 4; b++)
            #pragma unroll
            for (int c = 0; c < 4; c++) { ac1[a][b][c] = 0.f; ac2[a][b][c] = 0.f; }

    const int lr = lane & 15, lc = lane >> 4;
    const uint32_t xa = (lr & 7) << 4;
    const uint32_t arow = (wm * 32 + lr) * 256 + lc * 16;
    const uint32_t brow = (wn * 32 + lr) * 256 + lc * 16;

    for (int i = 0; i < nk; i++) {
        CPWAIT0();
        __syncthreads();
        if (i + 1 < nk) {
            const uint32_t sst = ((i + 1) & 1) * STGH;
            #pragma unroll
            for (int t = 0; t < 12; t++) CPA(so[t] + sst, gp[t] + (long)(i + 1) * 128);
            CPCOMMIT();
        }

        const uint32_t sa = st0 + (i & 1) * STGH;
        #pragma unroll
        for (int kk = 0; kk < 8; kk++) {
            uint32_t af[2][4], bh[4][2], bl[4][2];
            #pragma unroll
            for (int mi = 0; mi < 2; mi++)
                ldsm4(af[mi], sa + ((arow + mi * 4096 + kk * 32) ^ xa));
            #pragma unroll
            for (int pi = 0; pi < 2; pi++) {
                uint32_t off = (brow + pi * 4096 + kk * 32) ^ xa;
                uint32_t t0[4], t1[4];
                ldsm4(t0, sa + TILEH + off);
                ldsm4(t1, sa + 2 * TILEH + off);
                bh[2 * pi][0] = t0[0]; bh[2 * pi + 1][0] = t0[1];
                bh[2 * pi][1] = t0[2]; bh[2 * pi + 1][1] = t0[3];
                bl[2 * pi][0] = t1[0]; bl[2 * pi + 1][0] = t1[1];
                bl[2 * pi][1] = t1[2]; bl[2 * pi + 1][1] = t1[3];
            }
            #pragma unroll
            for (int mi = 0; mi < 2; mi++)
                #pragma unroll
                for (int ni = 0; ni < 4; ni++) {
                    mma_f16(ac1[mi][ni], af[mi], bh[ni]);
                    mma_f16(ac2[mi][ni], af[mi], bl[ni]);
                }
        }
    }

    const int g = lane >> 2, tg = lane & 3;
    const float inv = 1.f / 2048.f;
    #pragma unroll
    for (int mi = 0; mi < 2; mi++) {
        #pragma unroll
        for (int ni = 0; ni < 4; ni++) {
            long m0 = bm + wm * 32 + mi * 16 + g;
            long n0 = bn + wn * 32 + ni * 8 + tg * 2;
            float v00 = alpha * (ac1[mi][ni][0] + ac2[mi][ni][0] * inv);
            float v01 = alpha * (ac1[mi][ni][1] + ac2[mi][ni][1] * inv);
            float v10 = alpha * (ac1[mi][ni][2] + ac2[mi][ni][2] * inv);
            float v11 = alpha * (ac1[mi][ni][3] + ac2[mi][ni][3] * inv);
            if (bias) {
                float bb0 = bias[n0], bb1 = bias[n0 + 1];
                v00 += bb0; v01 += bb1; v10 += bb0; v11 += bb1;
            }
            if (C) {
                *(float2*)(C + m0 * ldc + n0) = make_float2(v00, v01);
                *(float2*)(C + (m0 + 8) * ldc + n0) = make_float2(v10, v11);
            }
            if (Ch) {
                *(__half2*)(Ch + m0 * ldc + n0) = __floats2half2_rn(v00, v01);
                *(__half2*)(Ch + (m0 + 8) * ldc + n0) = __floats2half2_rn(v10, v11);
            }
        }
    }
}

// ---------------- merged packing (both layouts, one read of w) ----------------
__global__ __launch_bounds__(256) void pack_both(
    const float* __restrict__ w0, const float* __restrict__ w1, const float* __restrict__ w2,
    h16* __restrict__ thi, h16* __restrict__ tlo,
    h16* __restrict__ phi, h16* __restrict__ plo,
    float sc0, float sc1, float sc2)
{
    __shared__ float sv[32][33];
    int bx = blockIdx.x;
    const float* w; int n, T; long kbase; float s;
    int pb;
    if (bx < 258)      { w = w0; n = 128; T = T0; kbase = 0;  s = sc0; pb = bx * 32; }
    else if (bx < 324) { w = w1; n = 64;  T = T1; kbase = S1; s = sc1; pb = (bx - 258) * 32; }
    else               { w = w2; n = 32;  T = T2; kbase = S2; s = sc2; pb = (bx - 324) * 32; }
    int hb = blockIdx.y * 32;
    int tx = threadIdx.x & 31, ty = threadIdx.x >> 5;
    #pragma unroll
    for (int i = 0; i < 32; i += 8) {
        int pp = pb + ty + i;
        float val = 0.f;
        if (pp < T) {
            uint32_t uv = g_uv[kbase + pp];
            int u = uv >> 16, v = uv & 0xffff;
            val = w[((long)u * n + v) * HID + hb + tx];
            if (u != v) val += w[((long)v * n + u) * HID + hb + tx];
            val *= s;
        }
        sv[ty + i][tx] = val;
        h16 hh, ll; splith(val, hh, ll);
        long o = (kbase + pp) * (long)HID + hb + tx;
        phi[o] = hh; plo[o] = ll;
    }
    __syncthreads();
    #pragma unroll
    for (int i = 0; i < 32; i += 8) {
        float val = sv[tx][ty + i];
        h16 hh, ll; splith(val, hh, ll);
        long o = (long)(hb + ty + i) * KCP + kbase + pb + tx;
        thi[o] = hh; tlo[o] = ll;
    }
}

// dense_all: tsc W1 (1024) | tsc W2 (256) | sconv W1 (4096) | sconv W2 (1024)
__global__ __launch_bounds__(256) void dense_all(
    const float* __restrict__ W1, const float* __restrict__ W2,
    h16* __restrict__ W1Thi, h16* __restrict__ W1Tlo,
    h16* __restrict__ W2Thi, h16* __restrict__ W2Tlo,
    h16* __restrict__ W1hi, h16* __restrict__ W1lo,
    h16* __restrict__ W2hi, h16* __restrict__ W2lo)
{
    __shared__ float t[32][33];
    long lin = blockIdx.x;
    if (lin < 1024 + 256) {
        const float* src; h16 *dhi, *dlo; int C; long ldd; int gx, gy;
        if (lin < 1024) { src = W1; dhi = W1Thi; dlo = W1Tlo; C = HID; ldd = HID; gx = (int)(lin % 32); gy = (int)(lin / 32); }
        else { long l = lin - 1024; src = W2; dhi = W2Thi; dlo = W2Tlo; C = ZD; ldd = HID; gx = (int)(l % 8); gy = (int)(l / 8); }
        int bx = gx * 32, by = gy * 32;
        int tx = threadIdx.x & 31, ty = threadIdx.x >> 5;
        #pragma unroll
        for (int i = 0; i < 32; i += 8)
            t[ty + i][tx] = src[(long)(by + ty + i) * C + bx + tx];
        __syncthreads();
        #pragma unroll
        for (int i = 0; i < 32; i += 8) {
            h16 h, l; splith(t[tx][ty + i], h, l);
            long o = (long)(bx + ty + i) * ldd + by + tx;
            dhi[o] = h; dlo[o] = l;
        }
    } else if (lin < 1024 + 256 + 4096) {
        long i = (lin - 1280) * 256 + threadIdx.x;
        if (i < HH) { h16 h, l; splith(W1[i], h, l); W1hi[i] = h; W1lo[i] = l; }
    } else {
        long i = (lin - 5376) * 256 + threadIdx.x;
        if (i < ZH) { h16 h, l; splith(W2[i], h, l); W2hi[i] = h; W2lo[i] = l; }
    }
}

// build_Pp_all: linear over NB*KCP
__global__ void build_Pp_all(const float* __restrict__ t, h16* __restrict__ Ph)
{
    long idx = (long)blockIdx.x * 256 + threadIdx.x;
    if (idx >= (long)NB * KCP) return;
    int b = (int)(idx / KCP), p = (int)(idx % KCP);
    int nm, xoff, T, lp;
    if (p < KP0)     { nm = 1; xoff = 0;   T = T0; lp = p; }
    else if (p < S2) { nm = 3; xoff = 128; T = T1; lp = p - S1; }
    else             { nm = 5; xoff = 320; T = T2; lp = p - S2; }
    float val = 0.f;
    if (lp < T) {
        uint32_t uv = g_uv[p];
        int u = uv >> 16, v = uv & 0xffff;
        const float* r = t + (long)b * DIMT + xoff;
        for (int m = 0; m < nm; m++) val += r[u * nm + m] * r[v * nm + m];
    }
    Ph[idx] = __float2half(val);
}

// ---------------- block reduce ----------------
__device__ __forceinline__ float blockReduceSum(float val) {
    __shared__ float sh[8];
    int lane = threadIdx.x & 31, w = threadIdx.x >> 5;
    #pragma unroll
    for (int o = 16; o > 0; o >>= 1) val += __shfl_down_sync(0xffffffffu, val, o);
    __syncthreads();
    if (lane == 0) sh[w] = val;
    __syncthreads();
    float r = 0.f;
    if (threadIdx.x == 0) {
        int nw = blockDim.x >> 5;
        for (int i = 0; i < nw; i++) r += sh[i];
    }
    return r;
}

// ---------------- LayerNorm + SiLU forward (layer 1) ----------------
__global__ __launch_bounds__(256) void ln_silu_fwd4(
    const float* __restrict__ a, const float* __restrict__ gam, const float* __restrict__ bet,
    float* __restrict__ xh, float* __restrict__ rstd, h16* __restrict__ hh)
{
    const int D = 1024;
    int b = blockIdx.x, tid = threadIdx.x;
    const float* row = a + (long)b * D;
    float v[4];
    float s = 0.f;
    #pragma unroll
    for (int i = 0; i < 4; i++) { v[i] = row[tid + (i << 8)]; s += v[i]; }
    s = blockReduceSum(s);
    __shared__ float bc;
    if (tid == 0) bc = s * (1.f / D);
    __syncthreads();
    float mu = bc;
    float q = 0.f;
    #pragma unroll
    for (int i = 0; i < 4; i++) { float d = v[i] - mu; q += d * d; }
    q = blockReduceSum(q);
    if (tid == 0) { float r = rsqrtf(q * (1.f / D) + 1e-6f); bc = r; rstd[b] = r; }
    __syncthreads();
    float r = bc;
    #pragma unroll
    for (int i = 0; i < 4; i++) {
        int c = tid + (i << 8);
        float x = (v[i] - mu) * r;
        xh[(long)b * D + c] = x;
        float z = x * gam[c] + bet[c];
        float sg = 1.f / (1.f + expf(-z));
        hh[(long)b * D + c] = __float2half(z * sg);
    }
}

// ---------------- fused LN2 fwd + bwd (layer 2, upstream ones) ----------------
__global__ __launch_bounds__(256) void ln2_fused(
    const float* __restrict__ a, const float* __restrict__ gam, const float* __restrict__ bet,
    float* __restrict__ xout, h16* __restrict__ dah)
{
    const int D = 256;
    int b = blockIdx.x, tid = threadIdx.x;
    float v = a[(long)b * D + tid];
    float s = blockReduceSum(v);
    __shared__ float bc;
    if (tid == 0) bc = s * (1.f / D);
    __syncthreads();
    float mu = bc;
    float d = v - mu;
    float q = blockReduceSum(d * d);
    if (tid == 0) bc = rsqrtf(q * (1.f / D) + 1e-6f);
    __syncthreads();
    float r = bc;
    float x = (v - mu) * r;
    float z = x * gam[tid] + bet[tid];
    float sg = 1.f / (1.f + expf(-z));
    xout[(long)b * D + tid] = z * sg;
    float ds = sg * (1.f + z * (1.f - sg));
    float dx = ds * gam[tid];
    float t1 = blockReduceSum(dx);
    __shared__ float m1s, m2s;
    if (tid == 0) m1s = t1 * (1.f / D);
    float t2 = blockReduceSum(dx * x);
    if (tid == 0) m2s = t2 * (1.f / D);
    __syncthreads();
    dah[(long)b * D + tid] = __float2half(r * (dx - m1s - x * m2s));
}

// ---------------- (SiLU + LN) backward (layer 1) ----------------
__global__ __launch_bounds__(256) void ln_silu_bwd4(
    const float* __restrict__ dh, const float* __restrict__ xhv_, const float* __restrict__ rstd,
    const float* __restrict__ gam, const float* __restrict__ bet, h16* __restrict__ dah)
{
    const int D = 1024;
    int b = blockIdx.x, tid = threadIdx.x;
    float xh[4], dxh[4];
    float s1 = 0.f, s2 = 0.f;
    #pragma unroll
    for (int i = 0; i < 4; i++) {
        int c = tid + (i << 8);
        float x = xhv_[(long)b * D + c];
        float z = x * gam[c] + bet[c];
        float sg = 1.f / (1.f + expf(-z));
        float ds = sg * (1.f + z * (1.f - sg));
        float dx = dh[(long)b * D + c] * ds * gam[c];
        xh[i] = x; dxh[i] = dx;
        s1 += dx; s2 += dx * x;
    }
    __shared__ float m1s, m2s;
    float t1 = blockReduceSum(s1);
    if (tid == 0) m1s = t1 * (1.f / D);
    float t2 = blockReduceSum(s2);
    if (tid == 0) m2s = t2 * (1.f / D);
    __syncthreads();
    float m1 = m1s, m2 = m2s, r = rstd[b];
    #pragma unroll
    for (int i = 0; i < 4; i++) {
        int c = tid + (i << 8);
        dah[(long)b * D + c] = __float2half(r * (dxh[i] - m1 - xh[i] * m2));
    }
}

// ---------------- merged packed quadratic-form gradients -> y ----------------
__global__ __launch_bounds__(192) void grad_all(const float* __restrict__ dPc,
                                                const float* __restrict__ t, float* __restrict__ y)
{
    extern __shared__ float Ts[];
    int tid = threadIdx.x;
    if (blockIdx.x < 2048) {
        int b = blockIdx.x;
        float* xs = Ts + 128 * 129;
        if (tid < 128) xs[tid] = t[(long)b * DIMT + tid];
        const float* P = dPc + (long)b * KCP;
        for (int i = tid; i < T0; i += 192) {
            uint32_t uv = g_uv[i];
            int u = uv >> 16, v = uv & 0xffff;
            float val = P[i];
            Ts[u * 129 + v] = val;
            Ts[v * 129 + u] = (u == v) ? 2.f * val : val;
        }
        __syncthreads();
        if (tid < 128) {
            float s = 0.f;
            #pragma unroll 8
            for (int v = 0; v < 128; v++) s += Ts[tid * 129 + v] * xs[v];
            y[(long)b * DIMT + tid] = s;
        }
    } else if (blockIdx.x < 4096) {
        int b = blockIdx.x - 2048;
        float* xs = Ts + 64 * 65;
        xs[tid] = t[(long)b * DIMT + 128 + tid];
        const float* P = dPc + (long)b * KCP + S1;
        for (int i = tid; i < T1; i += 192) {
            uint32_t uv = g_uv[S1 + i];
            int u = uv >> 16, v = uv & 0xffff;
            float val = P[i];
            Ts[u * 65 + v] = val;
            Ts[v * 65 + u] = (u == v) ? 2.f * val : val;
        }
        __syncthreads();
        int u = tid / 3, m = tid - u * 3;
        float s = 0.f;
        #pragma unroll 8
        for (int v = 0; v < 64; v++) s += Ts[u * 65 + v] * xs[v * 3 + m];
        y[(long)b * DIMT + 128 + tid] = s;
    } else {
        int b = blockIdx.x - 4096;
        float* xs = Ts + 32 * 33;
        if (tid < 160) xs[tid] = t[(long)b * DIMT + 320 + tid];
        const float* P = dPc + (long)b * KCP + S2;
        for (int i = tid; i < T2; i += 192) {
            uint32_t uv = g_uv[S2 + i];
            int u = uv >> 16, v = uv & 0xffff;
            float val = P[i];
            Ts[u * 33 + v] = val;
            Ts[v * 33 + u] = (u == v) ? 2.f * val : val;
        }
        __syncthreads();
        if (tid < 160) {
            int u = tid / 5, m = tid - u * 5;
            float s = 0.f;
            #pragma unroll 8
            for (int v = 0; v < 32; v++) s += Ts[u * 33 + v] * xs[v * 5 + m];
            y[(long)b * DIMT + 320 + tid] = s;
        }
    }
}

// ---------------- launch ----------------
extern "C" void kernel_launch(void* const* d_in, const int* in_sizes, int n_in,
                              void* d_out, int out_size)
{
    const float* tin = (const float*)d_in[0];
    const float* w0  = (const float*)d_in[1];
    const float* w1  = (const float*)d_in[2];
    const float* w2  = (const float*)d_in[3];
    const float* W1  = (const float*)d_in[4];
    const float* b1  = (const float*)d_in[5];
    const float* g1  = (const float*)d_in[6];
    const float* be1 = (const float*)d_in[7];
    const float* W2  = (const float*)d_in[8];
    const float* b2  = (const float*)d_in[9];
    const float* g2  = (const float*)d_in[10];
    const float* be2 = (const float*)d_in[11];

    float* out  = (float*)d_out;
    float* xout = out;
    float* yout = out + (long)NB * ZD;

    h16* hb = nullptr; float* fb = nullptr;
    cudaGetSymbolAddress((void**)&hb, g_hbuf);
    cudaGetSymbolAddress((void**)&fb, g_fbuf);

    h16 *PC   = hb + B_PC;
    h16 *WThi = hb + B_WTHI, *WTlo = hb + B_WTLO;
    h16 *WPhi = hb + B_WPHI, *WPlo = hb + B_WPLO;
    h16 *W1Thi= hb + B_W1THI,*W1Tlo= hb + B_W1TLO;
    h16 *W1hi = hb + B_W1HI, *W1lo = hb + B_W1LO;
    h16 *W2Thi= hb + B_W2THI,*W2Tlo= hb + B_W2TLO;
    h16 *W2hi = hb + B_W2HI, *W2lo = hb + B_W2LO;
    h16 *eh   = hb + B_EH;
    h16 *h1h  = hb + B_H1H;
    h16 *da2h = hb + B_DA2H;
    h16 *da1h = hb + B_DA1H;
    h16 *deh  = hb + B_DEH;

    float *dPC = fb + F_DPC, *a1 = fb + F_A1, *xh1 = fb + F_XH1;
    float *a2  = fb + F_A2,  *dh1 = fb + F_DH1, *rs1 = fb + F_RS1;

    const float s0 = 1.0f / sqrtf(21504.0f);
    const float s1 = s0 / sqrtf(3.0f);
    const float s2 = s0 / sqrtf(5.0f);

    cudaFuncSetAttribute(h_gemm_nt, cudaFuncAttributeMaxDynamicSharedMemorySize, GSMEM);
    cudaFuncSetAttribute(grad_all, cudaFuncAttributeMaxDynamicSharedMemorySize, 128 * 129 * 4 + 768);

    // ---- prep ----
    uv_init<<<(KCP + 255) / 256, 256>>>();
    pack_both<<<dim3(344, HID / 32), 256>>>(w0, w1, w2, WThi, WTlo, WPhi, WPlo, s0, s1, s2);
    dense_all<<<6400, 256>>>(W1, W2, W1Thi, W1Tlo, W2Thi, W2Tlo, W1hi, W1lo, W2hi, W2lo);
    build_Pp_all<<<(int)(((long)NB * KCP + 255) / 256), 256>>>(tin, PC);

    // ---- forward ----
    h_gemm_nt<<<dim3(HID / 128, NB / 128), 512, GSMEM>>>(
        PC, WThi, WTlo, nullptr, eh, KCP, HID, 1.f, nullptr);
    h_gemm_nt<<<dim3(HID / 128, NB / 128), 512, GSMEM>>>(
        eh, W1Thi, W1Tlo, a1, nullptr, HID, HID, 1.f, b1);
    ln_silu_fwd4<<<NB, 256>>>(a1, g1, be1, xh1, rs1, h1h);
    h_gemm_nt<<<dim3(ZD / 128, NB / 128), 512, GSMEM>>>(
        h1h, W2Thi, W2Tlo, a2, nullptr, HID, ZD, 1.f, b2);
    ln2_fused<<<NB, 256>>>(a2, g2, be2, xout, da2h);

    // ---- backward ----
    h_gemm_nt<<<dim3(HID / 128, NB / 128), 512, GSMEM>>>(
        da2h, W2hi, W2lo, dh1, nullptr, ZD, HID, 1.f, nullptr);
    ln_silu_bwd4<<<NB, 256>>>(dh1, xh1, rs1, g1, be1, da1h);
    h_gemm_nt<<<dim3(HID / 128, NB / 128), 512, GSMEM>>>(
        da1h, W1hi, W1lo, nullptr, deh, HID, HID, 1.f, nullptr);
    h_gemm_nt<<<dim3(KCP / 128, NB / 128), 512, GSMEM>>>(
        deh, WPhi, WPlo, dPC, nullptr, HID, KCP, 1.f, nullptr);

    grad_all<<<6144, 192, 128 * 129 * 4 + 768>>>(dPC, tin, yout);
}

// round 11
// speedup vs baseline: 6.6827x; 1.0629x over previous
#include <cuda_runtime.h>
#include <cuda_fp16.h>
#include <math.h>
#include <stdint.h>

#define NB   2048
#define DIMT 480
#define HID  1024
#define ZD   256
#define T0   8256
#define KP0  8256
#define T1   2080
#define KP1  2112
#define T2   528
#define KP2  640
#define KCP  11008
#define S1   8256
#define S2   10368

typedef __half h16;

// ---------------- scratch pools ----------------
constexpr long NBKC = (long)NB * KCP;
constexpr long HKC  = (long)HID * KCP;
constexpr long HH   = (long)HID * HID;
constexpr long ZH   = (long)ZD * HID;
constexpr long NH   = (long)NB * HID;
constexpr long NZ   = (long)NB * ZD;

constexpr long B_PC   = 0;
constexpr long B_WTHI = B_PC   + NBKC;
constexpr long B_WTLO = B_WTHI + HKC;
constexpr long B_WPHI = B_WTLO + HKC;
constexpr long B_WPLO = B_WPHI + HKC;
constexpr long B_W1THI= B_WPLO + HKC;
constexpr long B_W1TLO= B_W1THI + HH;
constexpr long B_W1HI = B_W1TLO + HH;
constexpr long B_W1LO = B_W1HI + HH;
constexpr long B_W2THI= B_W1LO + HH;
constexpr long B_W2TLO= B_W2THI + ZH;
constexpr long B_W2HI = B_W2TLO + ZH;
constexpr long B_W2LO = B_W2HI + ZH;
constexpr long B_EH   = B_W2LO + ZH;
constexpr long B_H1H  = B_EH   + NH;
constexpr long B_DA2H = B_H1H  + NH;
constexpr long B_DA1H = B_DA2H + NZ;
constexpr long B_DEH  = B_DA1H + NH;
constexpr long B_TOT  = B_DEH  + NH;

constexpr long F_DPC  = 0;
constexpr long F_A1   = F_DPC + NBKC;
constexpr long F_XH1  = F_A1  + NH;
constexpr long F_A2   = F_XH1 + NH;
constexpr long F_DH1  = F_A2  + NZ;
constexpr long F_RS1  = F_DH1 + NH;
constexpr long F_TOT  = F_RS1 + NB;

__device__ h16      g_hbuf[B_TOT];
__device__ float    g_fbuf[F_TOT];
__device__ uint32_t g_uv[KCP];

// ---------------- helpers ----------------
__device__ __forceinline__ uint32_t smem_u32(const void* p) {
    uint32_t a;
    asm("{ .reg .u64 t; cvta.to.shared.u64 t, %1; cvt.u32.u64 %0, t; }" : "=r"(a) : "l"(p));
    return a;
}
__device__ __forceinline__ void ldsm4(uint32_t* r, uint32_t a) {
    asm volatile("ldmatrix.sync.aligned.m8n8.x4.shared.b16 {%0,%1,%2,%3},[%4];"
                 : "=r"(r[0]), "=r"(r[1]), "=r"(r[2]), "=r"(r[3]) : "r"(a));
}
__device__ __forceinline__ void mma_f16(float* d, const uint32_t* a, const uint32_t* b) {
    asm volatile("mma.sync.aligned.m16n8k16.row.col.f32.f16.f16.f32 "
                 "{%0,%1,%2,%3},{%4,%5,%6,%7},{%8,%9},{%0,%1,%2,%3};"
                 : "+f"(d[0]), "+f"(d[1]), "+f"(d[2]), "+f"(d[3])
                 : "r"(a[0]), "r"(a[1]), "r"(a[2]), "r"(a[3]), "r"(b[0]), "r"(b[1]));
}
#define CPA(dst, src) asm volatile("cp.async.cg.shared.global [%0], [%1], 16;" :: "r"(dst), "l"(src) : "memory")
#define CPCOMMIT()    asm volatile("cp.async.commit_group;" ::: "memory")
#define CPWAIT0()     asm volatile("cp.async.wait_group 0;" ::: "memory")

__device__ __forceinline__ void splith(float v, h16& h, h16& l) {
    h = __float2half(v);
    l = __float2half((v - __half2float(h)) * 2048.f);
}

// ---------------- pair LUT ----------------
__global__ void uv_init() {
    int p = blockIdx.x * 256 + threadIdx.x;
    if (p >= KCP) return;
    int n, lp, T;
    if (p < S1)      { n = 128; lp = p;      T = T0; }
    else if (p < S2) { n = 64;  lp = p - S1; T = T1; }
    else             { n = 32;  lp = p - S2; T = T2; }
    if (lp >= T) { g_uv[p] = 0u; return; }
    float tn = 2.f * n + 1.f;
    int u = (int)((tn - sqrtf(tn * tn - 8.f * lp)) * 0.5f);
    if (u < 0) u = 0; if (u > n - 1) u = n - 1;
    while (u > 0 && u * n - u * (u - 1) / 2 > lp) u--;
    while (u < n - 1 && (u + 1) * n - (u + 1) * u / 2 <= lp) u++;
    int v = u + (lp - (u * n - u * (u - 1) / 2));
    g_uv[p] = ((uint32_t)u << 16) | (uint32_t)v;
}

// ---------------- fp16 2-mma NT GEMM: BK=128, 2-stage, 512 threads ----------------
#define TILEH 32768          // 128 rows x 256 B
#define STGH  (3 * TILEH)    // A, Bhi, Blo = 96 KB
#define GSMEM (2 * STGH + 1024)

__global__ __launch_bounds__(512, 1) void h_gemm_nt(
    const h16* __restrict__ A, const h16* __restrict__ Bhi, const h16* __restrict__ Blo,
    float* __restrict__ C, h16* __restrict__ Ch,
    int K, long ldc, float alpha, const float* __restrict__ bias)
{
    extern __shared__ char smem[];
    const uint32_t st0 = (smem_u32(smem) + 1023) & ~1023u;
    const int tid = threadIdx.x, wid = tid >> 5, lane = tid & 31;
    const int wm = wid >> 2, wn = wid & 3;
    const long bm = (long)blockIdx.y * 128, bn = (long)blockIdx.x * 128;

    const h16* gp[12];
    uint32_t so[12];
    #pragma unroll
    for (int t = 0; t < 12; t++) {
        int q = tid + (t & 3) * 512;
        int r = q >> 4, c = q & 15;
        int tile = t >> 2;
        const h16* base = (tile == 0) ? A : (tile == 1) ? Bhi : Blo;
        long row = (tile == 0 ? bm : bn) + r;
        gp[t] = base + row * K + c * 8;
        so[t] = st0 + tile * TILEH + ((r * 256 + c * 16) ^ ((r & 7) << 4));
    }
    const int nk = K >> 7;

    #pragma unroll
    for (int t = 0; t < 12; t++) CPA(so[t], gp[t]);
    CPCOMMIT();

    float ac1[2][4][4], ac2[2][4][4];
    #pragma unroll
    for (int a = 0; a < 2; a++)
        #pragma unroll
        for (int b = 0; b < 4; b++)
            #pragma unroll
            for (int c = 0; c < 4; c++) { ac1[a][b][c] = 0.f; ac2[a][b][c] = 0.f; }

    const int lr = lane & 15, lc = lane >> 4;
    const uint32_t xa = (lr & 7) << 4;
    const uint32_t arow = (wm * 32 + lr) * 256 + lc * 16;
    const uint32_t brow = (wn * 32 + lr) * 256 + lc * 16;

    for (int i = 0; i < nk; i++) {
        CPWAIT0();
        __syncthreads();
        if (i + 1 < nk) {
            const uint32_t sst = ((i + 1) & 1) * STGH;
            #pragma unroll
            for (int t = 0; t < 12; t++) CPA(so[t] + sst, gp[t] + (long)(i + 1) * 128);
            CPCOMMIT();
        }

        const uint32_t sa = st0 + (i & 1) * STGH;
        #pragma unroll
        for (int kk = 0; kk < 8; kk++) {
            uint32_t af[2][4], bh[4][2], bl[4][2];
            #pragma unroll
            for (int mi = 0; mi < 2; mi++)
                ldsm4(af[mi], sa + ((arow + mi * 4096 + kk * 32) ^ xa));
            #pragma unroll
            for (int pi = 0; pi < 2; pi++) {
                uint32_t off = (brow + pi * 4096 + kk * 32) ^ xa;
                uint32_t t0[4], t1[4];
                ldsm4(t0, sa + TILEH + off);
                ldsm4(t1, sa + 2 * TILEH + off);
                bh[2 * pi][0] = t0[0]; bh[2 * pi + 1][0] = t0[1];
                bh[2 * pi][1] = t0[2]; bh[2 * pi + 1][1] = t0[3];
                bl[2 * pi][0] = t1[0]; bl[2 * pi + 1][0] = t1[1];
                bl[2 * pi][1] = t1[2]; bl[2 * pi + 1][1] = t1[3];
            }
            #pragma unroll
            for (int mi = 0; mi < 2; mi++)
                #pragma unroll
                for (int ni = 0; ni < 4; ni++) {
                    mma_f16(ac1[mi][ni], af[mi], bh[ni]);
                    mma_f16(ac2[mi][ni], af[mi], bl[ni]);
                }
        }
    }

    const int g = lane >> 2, tg = lane & 3;
    const float inv = 1.f / 2048.f;
    #pragma unroll
    for (int mi = 0; mi < 2; mi++) {
        #pragma unroll
        for (int ni = 0; ni < 4; ni++) {
            long m0 = bm + wm * 32 + mi * 16 + g;
            long n0 = bn + wn * 32 + ni * 8 + tg * 2;
            float v00 = alpha * (ac1[mi][ni][0] + ac2[mi][ni][0] * inv);
            float v01 = alpha * (ac1[mi][ni][1] + ac2[mi][ni][1] * inv);
            float v10 = alpha * (ac1[mi][ni][2] + ac2[mi][ni][2] * inv);
            float v11 = alpha * (ac1[mi][ni][3] + ac2[mi][ni][3] * inv);
            if (bias) {
                float bb0 = bias[n0], bb1 = bias[n0 + 1];
                v00 += bb0; v01 += bb1; v10 += bb0; v11 += bb1;
            }
            if (C) {
                *(float2*)(C + m0 * ldc + n0) = make_float2(v00, v01);
                *(float2*)(C + (m0 + 8) * ldc + n0) = make_float2(v10, v11);
            }
            if (Ch) {
                *(__half2*)(Ch + m0 * ldc + n0) = __floats2half2_rn(v00, v01);
                *(__half2*)(Ch + (m0 + 8) * ldc + n0) = __floats2half2_rn(v10, v11);
            }
        }
    }
}

// ---------------- merged packing (both layouts, one read of w) ----------------
__global__ __launch_bounds__(256) void pack_both(
    const float* __restrict__ w0, const float* __restrict__ w1, const float* __restrict__ w2,
    h16* __restrict__ thi, h16* __restrict__ tlo,
    h16* __restrict__ phi, h16* __restrict__ plo,
    float sc0, float sc1, float sc2)
{
    __shared__ float sv[32][33];
    int bx = blockIdx.x;
    const float* w; int n, T; long kbase; float s;
    int pb;
    if (bx < 258)      { w = w0; n = 128; T = T0; kbase = 0;  s = sc0; pb = bx * 32; }
    else if (bx < 324) { w = w1; n = 64;  T = T1; kbase = S1; s = sc1; pb = (bx - 258) * 32; }
    else               { w = w2; n = 32;  T = T2; kbase = S2; s = sc2; pb = (bx - 324) * 32; }
    int hb = blockIdx.y * 32;
    int tx = threadIdx.x & 31, ty = threadIdx.x >> 5;
    #pragma unroll
    for (int i = 0; i < 32; i += 8) {
        int pp = pb + ty + i;
        float val = 0.f;
        if (pp < T) {
            uint32_t uv = g_uv[kbase + pp];
            int u = uv >> 16, v = uv & 0xffff;
            val = w[((long)u * n + v) * HID + hb + tx];
            if (u != v) val += w[((long)v * n + u) * HID + hb + tx];
            val *= s;
        }
        sv[ty + i][tx] = val;
        h16 hh, ll; splith(val, hh, ll);
        long o = (kbase + pp) * (long)HID + hb + tx;
        phi[o] = hh; plo[o] = ll;
    }
    __syncthreads();
    #pragma unroll
    for (int i = 0; i < 32; i += 8) {
        float val = sv[tx][ty + i];
        h16 hh, ll; splith(val, hh, ll);
        long o = (long)(hb + ty + i) * KCP + kbase + pb + tx;
        thi[o] = hh; tlo[o] = ll;
    }
}

// dense_all: tsc W1 (1024) | tsc W2 (256) | sconv W1 (4096) | sconv W2 (1024)
__global__ __launch_bounds__(256) void dense_all(
    const float* __restrict__ W1, const float* __restrict__ W2,
    h16* __restrict__ W1Thi, h16* __restrict__ W1Tlo,
    h16* __restrict__ W2Thi, h16* __restrict__ W2Tlo,
    h16* __restrict__ W1hi, h16* __restrict__ W1lo,
    h16* __restrict__ W2hi, h16* __restrict__ W2lo)
{
    __shared__ float t[32][33];
    long lin = blockIdx.x;
    if (lin < 1024 + 256) {
        const float* src; h16 *dhi, *dlo; int C; long ldd; int gx, gy;
        if (lin < 1024) { src = W1; dhi = W1Thi; dlo = W1Tlo; C = HID; ldd = HID; gx = (int)(lin % 32); gy = (int)(lin / 32); }
        else { long l = lin - 1024; src = W2; dhi = W2Thi; dlo = W2Tlo; C = ZD; ldd = HID; gx = (int)(l % 8); gy = (int)(l / 8); }
        int bx = gx * 32, by = gy * 32;
        int tx = threadIdx.x & 31, ty = threadIdx.x >> 5;
        #pragma unroll
        for (int i = 0; i < 32; i += 8)
            t[ty + i][tx] = src[(long)(by + ty + i) * C + bx + tx];
        __syncthreads();
        #pragma unroll
        for (int i = 0; i < 32; i += 8) {
            h16 h, l; splith(t[tx][ty + i], h, l);
            long o = (long)(bx + ty + i) * ldd + by + tx;
            dhi[o] = h; dlo[o] = l;
        }
    } else if (lin < 1024 + 256 + 4096) {
        long i = (lin - 1280) * 256 + threadIdx.x;
        if (i < HH) { h16 h, l; splith(W1[i], h, l); W1hi[i] = h; W1lo[i] = l; }
    } else {
        long i = (lin - 5376) * 256 + threadIdx.x;
        if (i < ZH) { h16 h, l; splith(W2[i], h, l); W2hi[i] = h; W2lo[i] = l; }
    }
}

// ---------------- build_Pp v2: one block per batch row, t row in SMEM ----------------
__global__ __launch_bounds__(256) void build_Pp_v2(const float* __restrict__ t, h16* __restrict__ Ph)
{
    __shared__ float xs[DIMT];
    int b = blockIdx.x, tid = threadIdx.x;
    if (tid < DIMT) xs[tid] = t[(long)b * DIMT + tid];
    if (tid + 256 < DIMT) xs[tid + 256] = t[(long)b * DIMT + tid + 256];
    __syncthreads();
    h16* out = Ph + (long)b * KCP;
    // region 0: pairs of singles
    for (int p = tid; p < KP0; p += 256) {
        uint32_t uv = g_uv[p];
        int u = uv >> 16, v = uv & 0xffff;
        out[p] = __float2half(xs[u] * xs[v]);
    }
    // region 1: m=3
    for (int p = tid; p < KP1; p += 256) {
        float val = 0.f;
        if (p < T1) {
            uint32_t uv = g_uv[S1 + p];
            int u = uv >> 16, v = uv & 0xffff;
            const float* r = xs + 128;
            #pragma unroll
            for (int m = 0; m < 3; m++) val += r[u * 3 + m] * r[v * 3 + m];
        }
        out[S1 + p] = __float2half(val);
    }
    // region 2: m=5
    for (int p = tid; p < KP2; p += 256) {
        float val = 0.f;
        if (p < T2) {
            uint32_t uv = g_uv[S2 + p];
            int u = uv >> 16, v = uv & 0xffff;
            const float* r = xs + 320;
            #pragma unroll
            for (int m = 0; m < 5; m++) val += r[u * 5 + m] * r[v * 5 + m];
        }
        out[S2 + p] = __float2half(val);
    }
}

// ---------------- block reduce ----------------
__device__ __forceinline__ float blockReduceSum(float val) {
    __shared__ float sh[8];
    int lane = threadIdx.x & 31, w = threadIdx.x >> 5;
    #pragma unroll
    for (int o = 16; o > 0; o >>= 1) val += __shfl_down_sync(0xffffffffu, val, o);
    __syncthreads();
    if (lane == 0) sh[w] = val;
    __syncthreads();
    float r = 0.f;
    if (threadIdx.x == 0) {
        int nw = blockDim.x >> 5;
        for (int i = 0; i < nw; i++) r += sh[i];
    }
    return r;
}

// ---------------- LayerNorm + SiLU forward (layer 1) ----------------
__global__ __launch_bounds__(256) void ln_silu_fwd4(
    const float* __restrict__ a, const float* __restrict__ gam, const float* __restrict__ bet,
    float* __restrict__ xh, float* __restrict__ rstd, h16* __restrict__ hh)
{
    const int D = 1024;
    int b = blockIdx.x, tid = threadIdx.x;
    const float* row = a + (long)b * D;
    float v[4];
    float s = 0.f;
    #pragma unroll
    for (int i = 0; i < 4; i++) { v[i] = row[tid + (i << 8)]; s += v[i]; }
    s = blockReduceSum(s);
    __shared__ float bc;
    if (tid == 0) bc = s * (1.f / D);
    __syncthreads();
    float mu = bc;
    float q = 0.f;
    #pragma unroll
    for (int i = 0; i < 4; i++) { float d = v[i] - mu; q += d * d; }
    q = blockReduceSum(q);
    if (tid == 0) { float r = rsqrtf(q * (1.f / D) + 1e-6f); bc = r; rstd[b] = r; }
    __syncthreads();
    float r = bc;
    #pragma unroll
    for (int i = 0; i < 4; i++) {
        int c = tid + (i << 8);
        float x = (v[i] - mu) * r;
        xh[(long)b * D + c] = x;
        float z = x * gam[c] + bet[c];
        float sg = 1.f / (1.f + expf(-z));
        hh[(long)b * D + c] = __float2half(z * sg);
    }
}

// ---------------- fused LN2 fwd + bwd (layer 2, upstream ones) ----------------
__global__ __launch_bounds__(256) void ln2_fused(
    const float* __restrict__ a, const float* __restrict__ gam, const float* __restrict__ bet,
    float* __restrict__ xout, h16* __restrict__ dah)
{
    const int D = 256;
    int b = blockIdx.x, tid = threadIdx.x;
    float v = a[(long)b * D + tid];
    float s = blockReduceSum(v);
    __shared__ float bc;
    if (tid == 0) bc = s * (1.f / D);
    __syncthreads();
    float mu = bc;
    float d = v - mu;
    float q = blockReduceSum(d * d);
    if (tid == 0) bc = rsqrtf(q * (1.f / D) + 1e-6f);
    __syncthreads();
    float r = bc;
    float x = (v - mu) * r;
    float z = x * gam[tid] + bet[tid];
    float sg = 1.f / (1.f + expf(-z));
    xout[(long)b * D + tid] = z * sg;
    float ds = sg * (1.f + z * (1.f - sg));
    float dx = ds * gam[tid];
    float t1 = blockReduceSum(dx);
    __shared__ float m1s, m2s;
    if (tid == 0) m1s = t1 * (1.f / D);
    float t2 = blockReduceSum(dx * x);
    if (tid == 0) m2s = t2 * (1.f / D);
    __syncthreads();
    dah[(long)b * D + tid] = __float2half(r * (dx - m1s - x * m2s));
}

// ---------------- (SiLU + LN) backward (layer 1) ----------------
__global__ __launch_bounds__(256) void ln_silu_bwd4(
    const float* __restrict__ dh, const float* __restrict__ xhv_, const float* __restrict__ rstd,
    const float* __restrict__ gam, const float* __restrict__ bet, h16* __restrict__ dah)
{
    const int D = 1024;
    int b = blockIdx.x, tid = threadIdx.x;
    float xh[4], dxh[4];
    float s1 = 0.f, s2 = 0.f;
    #pragma unroll
    for (int i = 0; i < 4; i++) {
        int c = tid + (i << 8);
        float x = xhv_[(long)b * D + c];
        float z = x * gam[c] + bet[c];
        float sg = 1.f / (1.f + expf(-z));
        float ds = sg * (1.f + z * (1.f - sg));
        float dx = dh[(long)b * D + c] * ds * gam[c];
        xh[i] = x; dxh[i] = dx;
        s1 += dx; s2 += dx * x;
    }
    __shared__ float m1s, m2s;
    float t1 = blockReduceSum(s1);
    if (tid == 0) m1s = t1 * (1.f / D);
    float t2 = blockReduceSum(s2);
    if (tid == 0) m2s = t2 * (1.f / D);
    __syncthreads();
    float m1 = m1s, m2 = m2s, r = rstd[b];
    #pragma unroll
    for (int i = 0; i < 4; i++) {
        int c = tid + (i << 8);
        dah[(long)b * D + c] = __float2half(r * (dxh[i] - m1 - xh[i] * m2));
    }
}

// ---------------- merged packed quadratic-form gradients -> y ----------------
__global__ __launch_bounds__(192) void grad_all(const float* __restrict__ dPc,
                                                const float* __restrict__ t, float* __restrict__ y)
{
    extern __shared__ float Ts[];
    int tid = threadIdx.x;
    if (blockIdx.x < 2048) {
        int b = blockIdx.x;
        float* xs = Ts + 128 * 129;
        if (tid < 128) xs[tid] = t[(long)b * DIMT + tid];
        const float* P = dPc + (long)b * KCP;
        for (int i = tid; i < T0; i += 192) {
            uint32_t uv = g_uv[i];
            int u = uv >> 16, v = uv & 0xffff;
            float val = P[i];
            Ts[u * 129 + v] = val;
            Ts[v * 129 + u] = (u == v) ? 2.f * val : val;
        }
        __syncthreads();
        if (tid < 128) {
            float s = 0.f;
            #pragma unroll 8
            for (int v = 0; v < 128; v++) s += Ts[tid * 129 + v] * xs[v];
            y[(long)b * DIMT + tid] = s;
        }
    } else if (blockIdx.x < 4096) {
        int b = blockIdx.x - 2048;
        float* xs = Ts + 64 * 65;
        xs[tid] = t[(long)b * DIMT + 128 + tid];
        const float* P = dPc + (long)b * KCP + S1;
        for (int i = tid; i < T1; i += 192) {
            uint32_t uv = g_uv[S1 + i];
            int u = uv >> 16, v = uv & 0xffff;
            float val = P[i];
            Ts[u * 65 + v] = val;
            Ts[v * 65 + u] = (u == v) ? 2.f * val : val;
        }
        __syncthreads();
        int u = tid / 3, m = tid - u * 3;
        float s = 0.f;
        #pragma unroll 8
        for (int v = 0; v < 64; v++) s += Ts[u * 65 + v] * xs[v * 3 + m];
        y[(long)b * DIMT + 128 + tid] = s;
    } else {
        int b = blockIdx.x - 4096;
        float* xs = Ts + 32 * 33;
        if (tid < 160) xs[tid] = t[(long)b * DIMT + 320 + tid];
        const float* P = dPc + (long)b * KCP + S2;
        for (int i = tid; i < T2; i += 192) {
            uint32_t uv = g_uv[S2 + i];
            int u = uv >> 16, v = uv & 0xffff;
            float val = P[i];
            Ts[u * 33 + v] = val;
            Ts[v * 33 + u] = (u == v) ? 2.f * val : val;
        }
        __syncthreads();
        if (tid < 160) {
            int u = tid / 5, m = tid - u * 5;
            float s = 0.f;
            #pragma unroll 8
            for (int v = 0; v < 32; v++) s += Ts[u * 33 + v] * xs[v * 5 + m];
            y[(long)b * DIMT + 320 + tid] = s;
        }
    }
}

// ---------------- launch ----------------
extern "C" void kernel_launch(void* const* d_in, const int* in_sizes, int n_in,
                              void* d_out, int out_size)
{
    const float* tin = (const float*)d_in[0];
    const float* w0  = (const float*)d_in[1];
    const float* w1  = (const float*)d_in[2];
    const float* w2  = (const float*)d_in[3];
    const float* W1  = (const float*)d_in[4];
    const float* b1  = (const float*)d_in[5];
    const float* g1  = (const float*)d_in[6];
    const float* be1 = (const float*)d_in[7];
    const float* W2  = (const float*)d_in[8];
    const float* b2  = (const float*)d_in[9];
    const float* g2  = (const float*)d_in[10];
    const float* be2 = (const float*)d_in[11];

    float* out  = (float*)d_out;
    float* xout = out;
    float* yout = out + (long)NB * ZD;

    h16* hb = nullptr; float* fb = nullptr;
    cudaGetSymbolAddress((void**)&hb, g_hbuf);
    cudaGetSymbolAddress((void**)&fb, g_fbuf);

    h16 *PC   = hb + B_PC;
    h16 *WThi = hb + B_WTHI, *WTlo = hb + B_WTLO;
    h16 *WPhi = hb + B_WPHI, *WPlo = hb + B_WPLO;
    h16 *W1Thi= hb + B_W1THI,*W1Tlo= hb + B_W1TLO;
    h16 *W1hi = hb + B_W1HI, *W1lo = hb + B_W1LO;
    h16 *W2Thi= hb + B_W2THI,*W2Tlo= hb + B_W2TLO;
    h16 *W2hi = hb + B_W2HI, *W2lo = hb + B_W2LO;
    h16 *eh   = hb + B_EH;
    h16 *h1h  = hb + B_H1H;
    h16 *da2h = hb + B_DA2H;
    h16 *da1h = hb + B_DA1H;
    h16 *deh  = hb + B_DEH;

    float *dPC = fb + F_DPC, *a1 = fb + F_A1, *xh1 = fb + F_XH1;
    float *a2  = fb + F_A2,  *dh1 = fb + F_DH1, *rs1 = fb + F_RS1;

    const float s0 = 1.0f / sqrtf(21504.0f);
    const float s1 = s0 / sqrtf(3.0f);
    const float s2 = s0 / sqrtf(5.0f);

    cudaFuncSetAttribute(h_gemm_nt, cudaFuncAttributeMaxDynamicSharedMemorySize, GSMEM);
    cudaFuncSetAttribute(grad_all, cudaFuncAttributeMaxDynamicSharedMemorySize, 128 * 129 * 4 + 768);

    // ---- prep ----
    uv_init<<<(KCP + 255) / 256, 256>>>();
    pack_both<<<dim3(344, HID / 32), 256>>>(w0, w1, w2, WThi, WTlo, WPhi, WPlo, s0, s1, s2);
    dense_all<<<6400, 256>>>(W1, W2, W1Thi, W1Tlo, W2Thi, W2Tlo, W1hi, W1lo, W2hi, W2lo);
    build_Pp_v2<<<NB, 256>>>(tin, PC);

    // ---- forward ----
    h_gemm_nt<<<dim3(HID / 128, NB / 128), 512, GSMEM>>>(
        PC, WThi, WTlo, nullptr, eh, KCP, HID, 1.f, nullptr);
    h_gemm_nt<<<dim3(HID / 128, NB / 128), 512, GSMEM>>>(
        eh, W1Thi, W1Tlo, a1, nullptr, HID, HID, 1.f, b1);
    ln_silu_fwd4<<<NB, 256>>>(a1, g1, be1, xh1, rs1, h1h);
    h_gemm_nt<<<dim3(ZD / 128, NB / 128), 512, GSMEM>>>(
        h1h, W2Thi, W2Tlo, a2, nullptr, HID, ZD, 1.f, b2);
    ln2_fused<<<NB, 256>>>(a2, g2, be2, xout, da2h);

    // ---- backward ----
    h_gemm_nt<<<dim3(HID / 128, NB / 128), 512, GSMEM>>>(
        da2h, W2hi, W2lo, dh1, nullptr, ZD, HID, 1.f, nullptr);
    ln_silu_bwd4<<<NB, 256>>>(dh1, xh1, rs1, g1, be1, da1h);
    h_gemm_nt<<<dim3(HID / 128, NB / 128), 512, GSMEM>>>(
        da1h, W1hi, W1lo, nullptr, deh, HID, HID, 1.f, nullptr);
    h_gemm_nt<<<dim3(KCP / 128, NB / 128), 512, GSMEM>>>(
        deh, WPhi, WPlo, dPC, nullptr, HID, KCP, 1.f, nullptr);

    grad_all<<<6144, 192, 128 * 129 * 4 + 768>>>(dPC, tin, yout);
}

// round 12
// speedup vs baseline: 7.6204x; 1.1403x over previous
#include <cuda_runtime.h>
#include <cuda_fp16.h>
#include <math.h>
#include <stdint.h>

#define NB   2048
#define DIMT 480
#define HID  1024
#define ZD   256
#define T0   8256
#define KP0  8256
#define T1   2080
#define KP1  2112
#define T2   528
#define KP2  640
#define KCP  11008
#define S1   8256
#define S2   10368

typedef __half h16;

// ---------------- scratch pools ----------------
constexpr long NBKC = (long)NB * KCP;
constexpr long HKC  = (long)HID * KCP;
constexpr long HH   = (long)HID * HID;
constexpr long ZH   = (long)ZD * HID;
constexpr long NH   = (long)NB * HID;
constexpr long NZ   = (long)NB * ZD;

constexpr long B_PC   = 0;
constexpr long B_WTHI = B_PC   + NBKC;
constexpr long B_WTLO = B_WTHI + HKC;
constexpr long B_WPHI = B_WTLO + HKC;
constexpr long B_WPLO = B_WPHI + HKC;
constexpr long B_W1THI= B_WPLO + HKC;
constexpr long B_W1TLO= B_W1THI + HH;
constexpr long B_W1HI = B_W1TLO + HH;
constexpr long B_W1LO = B_W1HI + HH;
constexpr long B_W2THI= B_W1LO + HH;
constexpr long B_W2TLO= B_W2THI + ZH;
constexpr long B_W2HI = B_W2TLO + ZH;
constexpr long B_W2LO = B_W2HI + ZH;
constexpr long B_EH   = B_W2LO + ZH;
constexpr long B_H1H  = B_EH   + NH;
constexpr long B_DA2H = B_H1H  + NH;
constexpr long B_DA1H = B_DA2H + NZ;
constexpr long B_DEH  = B_DA1H + NH;
constexpr long B_TOT  = B_DEH  + NH;

constexpr long F_DPC  = 0;
constexpr long F_A1   = F_DPC + NBKC;
constexpr long F_XH1  = F_A1  + NH;
constexpr long F_A2   = F_XH1 + NH;
constexpr long F_DH1  = F_A2  + NZ;
constexpr long F_RS1  = F_DH1 + NH;
constexpr long F_TOT  = F_RS1 + NB;

__device__ h16      g_hbuf[B_TOT];
__device__ float    g_fbuf[F_TOT];
__device__ uint32_t g_uv[KCP];
__device__ uint32_t g_uvo[KCP];   // (u_elem_off << 16) | v_elem_off within xs[DIMT]

// ---------------- helpers ----------------
__device__ __forceinline__ uint32_t smem_u32(const void* p) {
    uint32_t a;
    asm("{ .reg .u64 t; cvta.to.shared.u64 t, %1; cvt.u32.u64 %0, t; }" : "=r"(a) : "l"(p));
    return a;
}
__device__ __forceinline__ void ldsm4(uint32_t* r, uint32_t a) {
    asm volatile("ldmatrix.sync.aligned.m8n8.x4.shared.b16 {%0,%1,%2,%3},[%4];"
                 : "=r"(r[0]), "=r"(r[1]), "=r"(r[2]), "=r"(r[3]) : "r"(a));
}
__device__ __forceinline__ void mma_f16(float* d, const uint32_t* a, const uint32_t* b) {
    asm volatile("mma.sync.aligned.m16n8k16.row.col.f32.f16.f16.f32 "
                 "{%0,%1,%2,%3},{%4,%5,%6,%7},{%8,%9},{%0,%1,%2,%3};"
                 : "+f"(d[0]), "+f"(d[1]), "+f"(d[2]), "+f"(d[3])
                 : "r"(a[0]), "r"(a[1]), "r"(a[2]), "r"(a[3]), "r"(b[0]), "r"(b[1]));
}
#define CPA(dst, src) asm volatile("cp.async.cg.shared.global [%0], [%1], 16;" :: "r"(dst), "l"(src) : "memory")
#define CPCOMMIT()    asm volatile("cp.async.commit_group;" ::: "memory")
#define CPWAIT0()     asm volatile("cp.async.wait_group 0;" ::: "memory")

__device__ __forceinline__ void splith(float v, h16& h, h16& l) {
    h = __float2half(v);
    l = __float2half((v - __half2float(h)) * 2048.f);
}

// ---------------- pair LUTs ----------------
__global__ void uv_init() {
    int p = blockIdx.x * 256 + threadIdx.x;
    if (p >= KCP) return;
    int n, lp, T, nm, xoff;
    if (p < S1)      { n = 128; lp = p;      T = T0; nm = 1; xoff = 0; }
    else if (p < S2) { n = 64;  lp = p - S1; T = T1; nm = 3; xoff = 128; }
    else             { n = 32;  lp = p - S2; T = T2; nm = 5; xoff = 320; }
    if (lp >= T) { g_uv[p] = 0u; g_uvo[p] = 0xFFFFFFFFu; return; }
    float tn = 2.f * n + 1.f;
    int u = (int)((tn - sqrtf(tn * tn - 8.f * lp)) * 0.5f);
    if (u < 0) u = 0; if (u > n - 1) u = n - 1;
    while (u > 0 && u * n - u * (u - 1) / 2 > lp) u--;
    while (u < n - 1 && (u + 1) * n - (u + 1) * u / 2 <= lp) u++;
    int v = u + (lp - (u * n - u * (u - 1) / 2));
    g_uv[p]  = ((uint32_t)u << 16) | (uint32_t)v;
    g_uvo[p] = ((uint32_t)(xoff + u * nm) << 16) | (uint32_t)(xoff + v * nm);
}

// ---------------- fp16 NT GEMM: BK=128, 2-stage, 512 threads ----------------
// LO=true : C = alpha * A·(Bhi + Blo/2048)   (2 mma)
// LO=false: C = alpha * A·Bhi                (1 mma, Blo ignored/not loaded)
#define TILEH 32768          // 128 rows x 256 B
#define STGH  (3 * TILEH)    // A, Bhi, Blo = 96 KB (layout fixed for both variants)
#define GSMEM (2 * STGH + 1024)

template<bool LO>
__global__ __launch_bounds__(512, 1) void h_gemm_nt(
    const h16* __restrict__ A, const h16* __restrict__ Bhi, const h16* __restrict__ Blo,
    float* __restrict__ C, h16* __restrict__ Ch,
    int K, long ldc, float alpha, const float* __restrict__ bias)
{
    extern __shared__ char smem[];
    const uint32_t st0 = (smem_u32(smem) + 1023) & ~1023u;
    const int tid = threadIdx.x, wid = tid >> 5, lane = tid & 31;
    const int wm = wid >> 2, wn = wid & 3;
    const long bm = (long)blockIdx.y * 128, bn = (long)blockIdx.x * 128;

    constexpr int NCH = LO ? 12 : 8;     // 16B chunks per thread per stage
    const h16* gp[NCH];
    uint32_t so[NCH];
    #pragma unroll
    for (int t = 0; t < NCH; t++) {
        int q = tid + (t & 3) * 512;
        int r = q >> 4, c = q & 15;
        int tile = t >> 2;                  // 0=A 1=Bhi 2=Blo
        const h16* base = (tile == 0) ? A : (tile == 1) ? Bhi : Blo;
        long row = (tile == 0 ? bm : bn) + r;
        gp[t] = base + row * K + c * 8;
        so[t] = st0 + tile * TILEH + ((r * 256 + c * 16) ^ ((r & 7) << 4));
    }
    const int nk = K >> 7;

    #pragma unroll
    for (int t = 0; t < NCH; t++) CPA(so[t], gp[t]);
    CPCOMMIT();

    float ac1[2][4][4], ac2[2][4][4];
    #pragma unroll
    for (int a = 0; a < 2; a++)
        #pragma unroll
        for (int b = 0; b < 4; b++)
            #pragma unroll
            for (int c = 0; c < 4; c++) { ac1[a][b][c] = 0.f; if (LO) ac2[a][b][c] = 0.f; }

    const int lr = lane & 15, lc = lane >> 4;
    const uint32_t xa = (lr & 7) << 4;
    const uint32_t arow = (wm * 32 + lr) * 256 + lc * 16;
    const uint32_t brow = (wn * 32 + lr) * 256 + lc * 16;

    for (int i = 0; i < nk; i++) {
        CPWAIT0();
        __syncthreads();
        if (i + 1 < nk) {
            const uint32_t sst = ((i + 1) & 1) * STGH;
            #pragma unroll
            for (int t = 0; t < NCH; t++) CPA(so[t] + sst, gp[t] + (long)(i + 1) * 128);
            CPCOMMIT();
        }

        const uint32_t sa = st0 + (i & 1) * STGH;
        #pragma unroll
        for (int kk = 0; kk < 8; kk++) {
            uint32_t af[2][4], bh[4][2], bl[4][2];
            #pragma unroll
            for (int mi = 0; mi < 2; mi++)
                ldsm4(af[mi], sa + ((arow + mi * 4096 + kk * 32) ^ xa));
            #pragma unroll
            for (int pi = 0; pi < 2; pi++) {
                uint32_t off = (brow + pi * 4096 + kk * 32) ^ xa;
                uint32_t t0[4];
                ldsm4(t0, sa + TILEH + off);
                bh[2 * pi][0] = t0[0]; bh[2 * pi + 1][0] = t0[1];
                bh[2 * pi][1] = t0[2]; bh[2 * pi + 1][1] = t0[3];
                if (LO) {
                    uint32_t t1[4];
                    ldsm4(t1, sa + 2 * TILEH + off);
                    bl[2 * pi][0] = t1[0]; bl[2 * pi + 1][0] = t1[1];
                    bl[2 * pi][1] = t1[2]; bl[2 * pi + 1][1] = t1[3];
                }
            }
            #pragma unroll
            for (int mi = 0; mi < 2; mi++)
                #pragma unroll
                for (int ni = 0; ni < 4; ni++) {
                    mma_f16(ac1[mi][ni], af[mi], bh[ni]);
                    if (LO) mma_f16(ac2[mi][ni], af[mi], bl[ni]);
                }
        }
    }

    const int g = lane >> 2, tg = lane & 3;
    const float inv = 1.f / 2048.f;
    #pragma unroll
    for (int mi = 0; mi < 2; mi++) {
        #pragma unroll
        for (int ni = 0; ni < 4; ni++) {
            long m0 = bm + wm * 32 + mi * 16 + g;
            long n0 = bn + wn * 32 + ni * 8 + tg * 2;
            float v00, v01, v10, v11;
            if (LO) {
                v00 = alpha * (ac1[mi][ni][0] + ac2[mi][ni][0] * inv);
                v01 = alpha * (ac1[mi][ni][1] + ac2[mi][ni][1] * inv);
                v10 = alpha * (ac1[mi][ni][2] + ac2[mi][ni][2] * inv);
                v11 = alpha * (ac1[mi][ni][3] + ac2[mi][ni][3] * inv);
            } else {
                v00 = alpha * ac1[mi][ni][0];
                v01 = alpha * ac1[mi][ni][1];
                v10 = alpha * ac1[mi][ni][2];
                v11 = alpha * ac1[mi][ni][3];
            }
            if (bias) {
                float bb0 = bias[n0], bb1 = bias[n0 + 1];
                v00 += bb0; v01 += bb1; v10 += bb0; v11 += bb1;
            }
            if (C) {
                *(float2*)(C + m0 * ldc + n0) = make_float2(v00, v01);
                *(float2*)(C + (m0 + 8) * ldc + n0) = make_float2(v10, v11);
            }
            if (Ch) {
                *(__half2*)(Ch + m0 * ldc + n0) = __floats2half2_rn(v00, v01);
                *(__half2*)(Ch + (m0 + 8) * ldc + n0) = __floats2half2_rn(v10, v11);
            }
        }
    }
}

// ---------------- merged packing (both layouts, one read of w) ----------------
__global__ __launch_bounds__(256) void pack_both(
    const float* __restrict__ w0, const float* __restrict__ w1, const float* __restrict__ w2,
    h16* __restrict__ thi, h16* __restrict__ tlo,
    h16* __restrict__ phi, h16* __restrict__ plo,
    float sc0, float sc1, float sc2)
{
    __shared__ float sv[32][33];
    int bx = blockIdx.x;
    const float* w; int n, T; long kbase; float s;
    int pb;
    if (bx < 258)      { w = w0; n = 128; T = T0; kbase = 0;  s = sc0; pb = bx * 32; }
    else if (bx < 324) { w = w1; n = 64;  T = T1; kbase = S1; s = sc1; pb = (bx - 258) * 32; }
    else               { w = w2; n = 32;  T = T2; kbase = S2; s = sc2; pb = (bx - 324) * 32; }
    int hb = blockIdx.y * 32;
    int tx = threadIdx.x & 31, ty = threadIdx.x >> 5;
    #pragma unroll
    for (int i = 0; i < 32; i += 8) {
        int pp = pb + ty + i;
        float val = 0.f;
        if (pp < T) {
            uint32_t uv = g_uv[kbase + pp];
            int u = uv >> 16, v = uv & 0xffff;
            val = w[((long)u * n + v) * HID + hb + tx];
            if (u != v) val += w[((long)v * n + u) * HID + hb + tx];
            val *= s;
        }
        sv[ty + i][tx] = val;
        h16 hh, ll; splith(val, hh, ll);
        long o = (kbase + pp) * (long)HID + hb + tx;
        phi[o] = hh; plo[o] = ll;
    }
    __syncthreads();
    #pragma unroll
    for (int i = 0; i < 32; i += 8) {
        float val = sv[tx][ty + i];
        h16 hh, ll; splith(val, hh, ll);
        long o = (long)(hb + ty + i) * KCP + kbase + pb + tx;
        thi[o] = hh; tlo[o] = ll;
    }
}

// dense_all: tsc W1 (1024) | tsc W2 (256) | sconv W1 (4096) | sconv W2 (1024)
__global__ __launch_bounds__(256) void dense_all(
    const float* __restrict__ W1, const float* __restrict__ W2,
    h16* __restrict__ W1Thi, h16* __restrict__ W1Tlo,
    h16* __restrict__ W2Thi, h16* __restrict__ W2Tlo,
    h16* __restrict__ W1hi, h16* __restrict__ W1lo,
    h16* __restrict__ W2hi, h16* __restrict__ W2lo)
{
    __shared__ float t[32][33];
    long lin = blockIdx.x;
    if (lin < 1024 + 256) {
        const float* src; h16 *dhi, *dlo; int C; long ldd; int gx, gy;
        if (lin < 1024) { src = W1; dhi = W1Thi; dlo = W1Tlo; C = HID; ldd = HID; gx = (int)(lin % 32); gy = (int)(lin / 32); }
        else { long l = lin - 1024; src = W2; dhi = W2Thi; dlo = W2Tlo; C = ZD; ldd = HID; gx = (int)(l % 8); gy = (int)(l / 8); }
        int bx = gx * 32, by = gy * 32;
        int tx = threadIdx.x & 31, ty = threadIdx.x >> 5;
        #pragma unroll
        for (int i = 0; i < 32; i += 8)
            t[ty + i][tx] = src[(long)(by + ty + i) * C + bx + tx];
        __syncthreads();
        #pragma unroll
        for (int i = 0; i < 32; i += 8) {
            h16 h, l; splith(t[tx][ty + i], h, l);
            long o = (long)(bx + ty + i) * ldd + by + tx;
            dhi[o] = h; dlo[o] = l;
        }
    } else if (lin < 1024 + 256 + 4096) {
        long i = (lin - 1280) * 256 + threadIdx.x;
        if (i < HH) { h16 h, l; splith(W1[i], h, l); W1hi[i] = h; W1lo[i] = l; }
    } else {
        long i = (lin - 5376) * 256 + threadIdx.x;
        if (i < ZH) { h16 h, l; splith(W2[i], h, l); W2hi[i] = h; W2lo[i] = l; }
    }
}

// ---------------- build_Pp v3: per-row SMEM + offset LUT ----------------
__global__ __launch_bounds__(256) void build_Pp_v3(const float* __restrict__ t, h16* __restrict__ Ph)
{
    __shared__ float xs[DIMT];
    int b = blockIdx.x, tid = threadIdx.x;
    if (tid < DIMT) xs[tid] = t[(long)b * DIMT + tid];
    if (tid + 256 < DIMT) xs[tid + 256] = t[(long)b * DIMT + tid + 256];
    __syncthreads();
    h16* out = Ph + (long)b * KCP;
    for (int p = tid; p < KP0; p += 256) {
        uint32_t o = g_uvo[p];
        out[p] = __float2half(xs[o >> 16] * xs[o & 0xffff]);
    }
    for (int p = S1 + tid; p < S1 + KP1; p += 256) {
        uint32_t o = g_uvo[p];
        float val = 0.f;
        if (o != 0xFFFFFFFFu) {
            int uo = o >> 16, vo = o & 0xffff;
            #pragma unroll
            for (int m = 0; m < 3; m++) val += xs[uo + m] * xs[vo + m];
        }
        out[p] = __float2half(val);
    }
    for (int p = S2 + tid; p < S2 + KP2; p += 256) {
        uint32_t o = g_uvo[p];
        float val = 0.f;
        if (o != 0xFFFFFFFFu) {
            int uo = o >> 16, vo = o & 0xffff;
            #pragma unroll
            for (int m = 0; m < 5; m++) val += xs[uo + m] * xs[vo + m];
        }
        out[p] = __float2half(val);
    }
}

// ---------------- block reduce ----------------
__device__ __forceinline__ float blockReduceSum(float val) {
    __shared__ float sh[8];
    int lane = threadIdx.x & 31, w = threadIdx.x >> 5;
    #pragma unroll
    for (int o = 16; o > 0; o >>= 1) val += __shfl_down_sync(0xffffffffu, val, o);
    __syncthreads();
    if (lane == 0) sh[w] = val;
    __syncthreads();
    float r = 0.f;
    if (threadIdx.x == 0) {
        int nw = blockDim.x >> 5;
        for (int i = 0; i < nw; i++) r += sh[i];
    }
    return r;
}

// ---------------- LayerNorm + SiLU forward (layer 1) ----------------
__global__ __launch_bounds__(256) void ln_silu_fwd4(
    const float* __restrict__ a, const float* __restrict__ gam, const float* __restrict__ bet,
    float* __restrict__ xh, float* __restrict__ rstd, h16* __restrict__ hh)
{
    const int D = 1024;
    int b = blockIdx.x, tid = threadIdx.x;
    const float* row = a + (long)b * D;
    float v[4];
    float s = 0.f;
    #pragma unroll
    for (int i = 0; i < 4; i++) { v[i] = row[tid + (i << 8)]; s += v[i]; }
    s = blockReduceSum(s);
    __shared__ float bc;
    if (tid == 0) bc = s * (1.f / D);
    __syncthreads();
    float mu = bc;
    float q = 0.f;
    #pragma unroll
    for (int i = 0; i < 4; i++) { float d = v[i] - mu; q += d * d; }
    q = blockReduceSum(q);
    if (tid == 0) { float r = rsqrtf(q * (1.f / D) + 1e-6f); bc = r; rstd[b] = r; }
    __syncthreads();
    float r = bc;
    #pragma unroll
    for (int i = 0; i < 4; i++) {
        int c = tid + (i << 8);
        float x = (v[i] - mu) * r;
        xh[(long)b * D + c] = x;
        float z = x * gam[c] + bet[c];
        float sg = 1.f / (1.f + expf(-z));
        hh[(long)b * D + c] = __float2half(z * sg);
    }
}

// ---------------- fused LN2 fwd + bwd (layer 2, upstream ones) ----------------
__global__ __launch_bounds__(256) void ln2_fused(
    const float* __restrict__ a, const float* __restrict__ gam, const float* __restrict__ bet,
    float* __restrict__ xout, h16* __restrict__ dah)
{
    const int D = 256;
    int b = blockIdx.x, tid = threadIdx.x;
    float v = a[(long)b * D + tid];
    float s = blockReduceSum(v);
    __shared__ float bc;
    if (tid == 0) bc = s * (1.f / D);
    __syncthreads();
    float mu = bc;
    float d = v - mu;
    float q = blockReduceSum(d * d);
    if (tid == 0) bc = rsqrtf(q * (1.f / D) + 1e-6f);
    __syncthreads();
    float r = bc;
    float x = (v - mu) * r;
    float z = x * gam[tid] + bet[tid];
    float sg = 1.f / (1.f + expf(-z));
    xout[(long)b * D + tid] = z * sg;
    float ds = sg * (1.f + z * (1.f - sg));
    float dx = ds * gam[tid];
    float t1 = blockReduceSum(dx);
    __shared__ float m1s, m2s;
    if (tid == 0) m1s = t1 * (1.f / D);
    float t2 = blockReduceSum(dx * x);
    if (tid == 0) m2s = t2 * (1.f / D);
    __syncthreads();
    dah[(long)b * D + tid] = __float2half(r * (dx - m1s - x * m2s));
}

// ---------------- (SiLU + LN) backward (layer 1) ----------------
__global__ __launch_bounds__(256) void ln_silu_bwd4(
    const float* __restrict__ dh, const float* __restrict__ xhv_, const float* __restrict__ rstd,
    const float* __restrict__ gam, const float* __restrict__ bet, h16* __restrict__ dah)
{
    const int D = 1024;
    int b = blockIdx.x, tid = threadIdx.x;
    float xh[4], dxh[4];
    float s1 = 0.f, s2 = 0.f;
    #pragma unroll
    for (int i = 0; i < 4; i++) {
        int c = tid + (i << 8);
        float x = xhv_[(long)b * D + c];
        float z = x * gam[c] + bet[c];
        float sg = 1.f / (1.f + expf(-z));
        float ds = sg * (1.f + z * (1.f - sg));
        float dx = dh[(long)b * D + c] * ds * gam[c];
        xh[i] = x; dxh[i] = dx;
        s1 += dx; s2 += dx * x;
    }
    __shared__ float m1s, m2s;
    float t1 = blockReduceSum(s1);
    if (tid == 0) m1s = t1 * (1.f / D);
    float t2 = blockReduceSum(s2);
    if (tid == 0) m2s = t2 * (1.f / D);
    __syncthreads();
    float m1 = m1s, m2 = m2s, r = rstd[b];
    #pragma unroll
    for (int i = 0; i < 4; i++) {
        int c = tid + (i << 8);
        dah[(long)b * D + c] = __float2half(r * (dxh[i] - m1 - xh[i] * m2));
    }
}

// ---------------- merged packed quadratic-form gradients -> y ----------------
__global__ __launch_bounds__(192) void grad_all(const float* __restrict__ dPc,
                                                const float* __restrict__ t, float* __restrict__ y)
{
    extern __shared__ float Ts[];
    int tid = threadIdx.x;
    if (blockIdx.x < 2048) {
        int b = blockIdx.x;
        float* xs = Ts + 128 * 129;
        if (tid < 128) xs[tid] = t[(long)b * DIMT + tid];
        const float* P = dPc + (long)b * KCP;
        for (int i = tid; i < T0; i += 192) {
            uint32_t uv = g_uv[i];
            int u = uv >> 16, v = uv & 0xffff;
            float val = P[i];
            Ts[u * 129 + v] = val;
            Ts[v * 129 + u] = (u == v) ? 2.f * val : val;
        }
        __syncthreads();
        if (tid < 128) {
            float s = 0.f;
            #pragma unroll 8
            for (int v = 0; v < 128; v++) s += Ts[tid * 129 + v] * xs[v];
            y[(long)b * DIMT + tid] = s;
        }
    } else if (blockIdx.x < 4096) {
        int b = blockIdx.x - 2048;
        float* xs = Ts + 64 * 65;
        xs[tid] = t[(long)b * DIMT + 128 + tid];
        const float* P = dPc + (long)b * KCP + S1;
        for (int i = tid; i < T1; i += 192) {
            uint32_t uv = g_uv[S1 + i];
            int u = uv >> 16, v = uv & 0xffff;
            float val = P[i];
            Ts[u * 65 + v] = val;
            Ts[v * 65 + u] = (u == v) ? 2.f * val : val;
        }
        __syncthreads();
        int u = tid / 3, m = tid - u * 3;
        float s = 0.f;
        #pragma unroll 8
        for (int v = 0; v < 64; v++) s += Ts[u * 65 + v] * xs[v * 3 + m];
        y[(long)b * DIMT + 128 + tid] = s;
    } else {
        int b = blockIdx.x - 4096;
        float* xs = Ts + 32 * 33;
        if (tid < 160) xs[tid] = t[(long)b * DIMT + 320 + tid];
        const float* P = dPc + (long)b * KCP + S2;
        for (int i = tid; i < T2; i += 192) {
            uint32_t uv = g_uv[S2 + i];
            int u = uv >> 16, v = uv & 0xffff;
            float val = P[i];
            Ts[u * 33 + v] = val;
            Ts[v * 33 + u] = (u == v) ? 2.f * val : val;
        }
        __syncthreads();
        if (tid < 160) {
            int u = tid / 5, m = tid - u * 5;
            float s = 0.f;
            #pragma unroll 8
            for (int v = 0; v < 32; v++) s += Ts[u * 33 + v] * xs[v * 5 + m];
            y[(long)b * DIMT + 320 + tid] = s;
        }
    }
}

// ---------------- launch ----------------
extern "C" void kernel_launch(void* const* d_in, const int* in_sizes, int n_in,
                              void* d_out, int out_size)
{
    const float* tin = (const float*)d_in[0];
    const float* w0  = (const float*)d_in[1];
    const float* w1  = (const float*)d_in[2];
    const float* w2  = (const float*)d_in[3];
    const float* W1  = (const float*)d_in[4];
    const float* b1  = (const float*)d_in[5];
    const float* g1  = (const float*)d_in[6];
    const float* be1 = (const float*)d_in[7];
    const float* W2  = (const float*)d_in[8];
    const float* b2  = (const float*)d_in[9];
    const float* g2  = (const float*)d_in[10];
    const float* be2 = (const float*)d_in[11];

    float* out  = (float*)d_out;
    float* xout = out;
    float* yout = out + (long)NB * ZD;

    h16* hb = nullptr; float* fb = nullptr;
    cudaGetSymbolAddress((void**)&hb, g_hbuf);
    cudaGetSymbolAddress((void**)&fb, g_fbuf);

    h16 *PC   = hb + B_PC;
    h16 *WThi = hb + B_WTHI, *WTlo = hb + B_WTLO;
    h16 *WPhi = hb + B_WPHI, *WPlo = hb + B_WPLO;
    h16 *W1Thi= hb + B_W1THI,*W1Tlo= hb + B_W1TLO;
    h16 *W1hi = hb + B_W1HI, *W1lo = hb + B_W1LO;
    h16 *W2Thi= hb + B_W2THI,*W2Tlo= hb + B_W2TLO;
    h16 *W2hi = hb + B_W2HI, *W2lo = hb + B_W2LO;
    h16 *eh   = hb + B_EH;
    h16 *h1h  = hb + B_H1H;
    h16 *da2h = hb + B_DA2H;
    h16 *da1h = hb + B_DA1H;
    h16 *deh  = hb + B_DEH;

    float *dPC = fb + F_DPC, *a1 = fb + F_A1, *xh1 = fb + F_XH1;
    float *a2  = fb + F_A2,  *dh1 = fb + F_DH1, *rs1 = fb + F_RS1;

    const float s0 = 1.0f / sqrtf(21504.0f);
    const float s1 = s0 / sqrtf(3.0f);
    const float s2 = s0 / sqrtf(5.0f);

    cudaFuncSetAttribute(h_gemm_nt<true>,  cudaFuncAttributeMaxDynamicSharedMemorySize, GSMEM);
    cudaFuncSetAttribute(h_gemm_nt<false>, cudaFuncAttributeMaxDynamicSharedMemorySize, GSMEM);
    cudaFuncSetAttribute(grad_all, cudaFuncAttributeMaxDynamicSharedMemorySize, 128 * 129 * 4 + 768);

    // ---- prep ----
    uv_init<<<(KCP + 255) / 256, 256>>>();
    pack_both<<<dim3(344, HID / 32), 256>>>(w0, w1, w2, WThi, WTlo, WPhi, WPlo, s0, s1, s2);
    dense_all<<<6400, 256>>>(W1, W2, W1Thi, W1Tlo, W2Thi, W2Tlo, W1hi, W1lo, W2hi, W2lo);
    build_Pp_v3<<<NB, 256>>>(tin, PC);

    // ---- forward ----
    h_gemm_nt<true><<<dim3(HID / 128, NB / 128), 512, GSMEM>>>(
        PC, WThi, WTlo, nullptr, eh, KCP, HID, 1.f, nullptr);
    h_gemm_nt<true><<<dim3(HID / 128, NB / 128), 512, GSMEM>>>(
        eh, W1Thi, W1Tlo, a1, nullptr, HID, HID, 1.f, b1);
    ln_silu_fwd4<<<NB, 256>>>(a1, g1, be1, xh1, rs1, h1h);
    h_gemm_nt<true><<<dim3(ZD / 128, NB / 128), 512, GSMEM>>>(
        h1h, W2Thi, W2Tlo, a2, nullptr, HID, ZD, 1.f, b2);
    ln2_fused<<<NB, 256>>>(a2, g2, be2, xout, da2h);

    // ---- backward ----
    h_gemm_nt<true><<<dim3(HID / 128, NB / 128), 512, GSMEM>>>(
        da2h, W2hi, W2lo, dh1, nullptr, ZD, HID, 1.f, nullptr);
    ln_silu_bwd4<<<NB, 256>>>(dh1, xh1, rs1, g1, be1, da1h);
    h_gemm_nt<true><<<dim3(HID / 128, NB / 128), 512, GSMEM>>>(
        da1h, W1hi, W1lo, nullptr, deh, HID, HID, 1.f, nullptr);
    // dP GEMM: weight-hi only (error model: +1 variance unit, ~8.5e-4 total)
    h_gemm_nt<false><<<dim3(KCP / 128, NB / 128), 512, GSMEM>>>(
        deh, WPhi, WPhi, dPC, nullptr, HID, KCP, 1.f, nullptr);

    grad_all<<<6144, 192, 128 * 129 * 4 + 768>>>(dPC, tin, yout);
}

// round 13
// speedup vs baseline: 9.5024x; 1.2470x over previous
#include <cuda_runtime.h>
#include <cuda_fp16.h>
#include <math.h>
#include <stdint.h>

#define NB   2048
#define DIMT 480
#define HID  1024
#define ZD   256
#define T0   8256
#define KP0  8256
#define T1   2080
#define KP1  2112
#define T2   528
#define KP2  640
#define KCP  11008
#define S1   8256
#define S2   10368

typedef __half h16;

// ---------------- scratch pools ----------------
constexpr long NBKC = (long)NB * KCP;
constexpr long HKC  = (long)HID * KCP;
constexpr long HH   = (long)HID * HID;
constexpr long ZH   = (long)ZD * HID;
constexpr long NH   = (long)NB * HID;
constexpr long NZ   = (long)NB * ZD;

constexpr long B_PC   = 0;
constexpr long B_WTHI = B_PC   + NBKC;
constexpr long B_WPHI = B_WTHI + HKC;
constexpr long B_W1THI= B_WPHI + HKC;
constexpr long B_W1TLO= B_W1THI + HH;
constexpr long B_W1HI = B_W1TLO + HH;
constexpr long B_W1LO = B_W1HI + HH;
constexpr long B_W2THI= B_W1LO + HH;
constexpr long B_W2TLO= B_W2THI + ZH;
constexpr long B_W2HI = B_W2TLO + ZH;
constexpr long B_W2LO = B_W2HI + ZH;
constexpr long B_EH   = B_W2LO + ZH;
constexpr long B_H1H  = B_EH   + NH;
constexpr long B_DA2H = B_H1H  + NH;
constexpr long B_DA1H = B_DA2H + NZ;
constexpr long B_DEH  = B_DA1H + NH;
constexpr long B_TOT  = B_DEH  + NH;

constexpr long F_DPC  = 0;
constexpr long F_A1   = F_DPC + NBKC;
constexpr long F_XH1  = F_A1  + NH;
constexpr long F_A2   = F_XH1 + NH;
constexpr long F_DH1  = F_A2  + NZ;
constexpr long F_RS1  = F_DH1 + NH;
constexpr long F_TOT  = F_RS1 + NB;

__device__ h16      g_hbuf[B_TOT];
__device__ float    g_fbuf[F_TOT];
__device__ uint32_t g_uv[KCP];
__device__ uint32_t g_uvo[KCP];

// ---------------- helpers ----------------
__device__ __forceinline__ uint32_t smem_u32(const void* p) {
    uint32_t a;
    asm("{ .reg .u64 t; cvta.to.shared.u64 t, %1; cvt.u32.u64 %0, t; }" : "=r"(a) : "l"(p));
    return a;
}
__device__ __forceinline__ void ldsm4(uint32_t* r, uint32_t a) {
    asm volatile("ldmatrix.sync.aligned.m8n8.x4.shared.b16 {%0,%1,%2,%3},[%4];"
                 : "=r"(r[0]), "=r"(r[1]), "=r"(r[2]), "=r"(r[3]) : "r"(a));
}
__device__ __forceinline__ void mma_f16(float* d, const uint32_t* a, const uint32_t* b) {
    asm volatile("mma.sync.aligned.m16n8k16.row.col.f32.f16.f16.f32 "
                 "{%0,%1,%2,%3},{%4,%5,%6,%7},{%8,%9},{%0,%1,%2,%3};"
                 : "+f"(d[0]), "+f"(d[1]), "+f"(d[2]), "+f"(d[3])
                 : "r"(a[0]), "r"(a[1]), "r"(a[2]), "r"(a[3]), "r"(b[0]), "r"(b[1]));
}
#define CPA(dst, src) asm volatile("cp.async.cg.shared.global [%0], [%1], 16;" :: "r"(dst), "l"(src) : "memory")
#define CPCOMMIT()    asm volatile("cp.async.commit_group;" ::: "memory")
#define CPWAIT0()     asm volatile("cp.async.wait_group 0;" ::: "memory")

__device__ __forceinline__ void splith(float v, h16& h, h16& l) {
    h = __float2half(v);
    l = __float2half((v - __half2float(h)) * 2048.f);
}

// ---------------- pair LUTs ----------------
__global__ void uv_init() {
    int p = blockIdx.x * 256 + threadIdx.x;
    if (p >= KCP) return;
    int n, lp, T, nm, xoff;
    if (p < S1)      { n = 128; lp = p;      T = T0; nm = 1; xoff = 0; }
    else if (p < S2) { n = 64;  lp = p - S1; T = T1; nm = 3; xoff = 128; }
    else             { n = 32;  lp = p - S2; T = T2; nm = 5; xoff = 320; }
    if (lp >= T) { g_uv[p] = 0u; g_uvo[p] = 0xFFFFFFFFu; return; }
    float tn = 2.f * n + 1.f;
    int u = (int)((tn - sqrtf(tn * tn - 8.f * lp)) * 0.5f);
    if (u < 0) u = 0; if (u > n - 1) u = n - 1;
    while (u > 0 && u * n - u * (u - 1) / 2 > lp) u--;
    while (u < n - 1 && (u + 1) * n - (u + 1) * u / 2 <= lp) u++;
    int v = u + (lp - (u * n - u * (u - 1) / 2));
    g_uv[p]  = ((uint32_t)u << 16) | (uint32_t)v;
    g_uvo[p] = ((uint32_t)(xoff + u * nm) << 16) | (uint32_t)(xoff + v * nm);
}

// ---------------- fp16 NT GEMM: BK=128, 2-stage, 512 threads ----------------
#define TILEH 32768
#define STGH  (3 * TILEH)
#define GSMEM (2 * STGH + 1024)

template<bool LO>
__global__ __launch_bounds__(512, 1) void h_gemm_nt(
    const h16* __restrict__ A, const h16* __restrict__ Bhi, const h16* __restrict__ Blo,
    float* __restrict__ C, h16* __restrict__ Ch,
    int K, long ldc, float alpha, const float* __restrict__ bias)
{
    extern __shared__ char smem[];
    const uint32_t st0 = (smem_u32(smem) + 1023) & ~1023u;
    const int tid = threadIdx.x, wid = tid >> 5, lane = tid & 31;
    const int wm = wid >> 2, wn = wid & 3;
    const long bm = (long)blockIdx.y * 128, bn = (long)blockIdx.x * 128;

    constexpr int NCH = LO ? 12 : 8;
    const h16* gp[NCH];
    uint32_t so[NCH];
    #pragma unroll
    for (int t = 0; t < NCH; t++) {
        int q = tid + (t & 3) * 512;
        int r = q >> 4, c = q & 15;
        int tile = t >> 2;
        const h16* base = (tile == 0) ? A : (tile == 1) ? Bhi : Blo;
        long row = (tile == 0 ? bm : bn) + r;
        gp[t] = base + row * K + c * 8;
        so[t] = st0 + tile * TILEH + ((r * 256 + c * 16) ^ ((r & 7) << 4));
    }
    const int nk = K >> 7;

    #pragma unroll
    for (int t = 0; t < NCH; t++) CPA(so[t], gp[t]);
    CPCOMMIT();

    float ac1[2][4][4], ac2[2][4][4];
    #pragma unroll
    for (int a = 0; a < 2; a++)
        #pragma unroll
        for (int b = 0; b < 4; b++)
            #pragma unroll
            for (int c = 0; c < 4; c++) { ac1[a][b][c] = 0.f; if (LO) ac2[a][b][c] = 0.f; }

    const int lr = lane & 15, lc = lane >> 4;
    const uint32_t xa = (lr & 7) << 4;
    const uint32_t arow = (wm * 32 + lr) * 256 + lc * 16;
    const uint32_t brow = (wn * 32 + lr) * 256 + lc * 16;

    for (int i = 0; i < nk; i++) {
        CPWAIT0();
        __syncthreads();
        if (i + 1 < nk) {
            const uint32_t sst = ((i + 1) & 1) * STGH;
            #pragma unroll
            for (int t = 0; t < NCH; t++) CPA(so[t] + sst, gp[t] + (long)(i + 1) * 128);
            CPCOMMIT();
        }

        const uint32_t sa = st0 + (i & 1) * STGH;
        #pragma unroll
        for (int kk = 0; kk < 8; kk++) {
            uint32_t af[2][4], bh[4][2], bl[4][2];
            #pragma unroll
            for (int mi = 0; mi < 2; mi++)
                ldsm4(af[mi], sa + ((arow + mi * 4096 + kk * 32) ^ xa));
            #pragma unroll
            for (int pi = 0; pi < 2; pi++) {
                uint32_t off = (brow + pi * 4096 + kk * 32) ^ xa;
                uint32_t t0[4];
                ldsm4(t0, sa + TILEH + off);
                bh[2 * pi][0] = t0[0]; bh[2 * pi + 1][0] = t0[1];
                bh[2 * pi][1] = t0[2]; bh[2 * pi + 1][1] = t0[3];
                if (LO) {
                    uint32_t t1[4];
                    ldsm4(t1, sa + 2 * TILEH + off);
                    bl[2 * pi][0] = t1[0]; bl[2 * pi + 1][0] = t1[1];
                    bl[2 * pi][1] = t1[2]; bl[2 * pi + 1][1] = t1[3];
                }
            }
            #pragma unroll
            for (int mi = 0; mi < 2; mi++)
                #pragma unroll
                for (int ni = 0; ni < 4; ni++) {
                    mma_f16(ac1[mi][ni], af[mi], bh[ni]);
                    if (LO) mma_f16(ac2[mi][ni], af[mi], bl[ni]);
                }
        }
    }

    const int g = lane >> 2, tg = lane & 3;
    const float inv = 1.f / 2048.f;
    #pragma unroll
    for (int mi = 0; mi < 2; mi++) {
        #pragma unroll
        for (int ni = 0; ni < 4; ni++) {
            long m0 = bm + wm * 32 + mi * 16 + g;
            long n0 = bn + wn * 32 + ni * 8 + tg * 2;
            float v00, v01, v10, v11;
            if (LO) {
                v00 = alpha * (ac1[mi][ni][0] + ac2[mi][ni][0] * inv);
                v01 = alpha * (ac1[mi][ni][1] + ac2[mi][ni][1] * inv);
                v10 = alpha * (ac1[mi][ni][2] + ac2[mi][ni][2] * inv);
                v11 = alpha * (ac1[mi][ni][3] + ac2[mi][ni][3] * inv);
            } else {
                v00 = alpha * ac1[mi][ni][0];
                v01 = alpha * ac1[mi][ni][1];
                v10 = alpha * ac1[mi][ni][2];
                v11 = alpha * ac1[mi][ni][3];
            }
            if (bias) {
                float bb0 = bias[n0], bb1 = bias[n0 + 1];
                v00 += bb0; v01 += bb1; v10 += bb0; v11 += bb1;
            }
            if (C) {
                *(float2*)(C + m0 * ldc + n0) = make_float2(v00, v01);
                *(float2*)(C + (m0 + 8) * ldc + n0) = make_float2(v10, v11);
            }
            if (Ch) {
                *(__half2*)(Ch + m0 * ldc + n0) = __floats2half2_rn(v00, v01);
                *(__half2*)(Ch + (m0 + 8) * ldc + n0) = __floats2half2_rn(v10, v11);
            }
        }
    }
}

// ---------------- merged packing (hi-only outputs now) ----------------
__global__ __launch_bounds__(256) void pack_both(
    const float* __restrict__ w0, const float* __restrict__ w1, const float* __restrict__ w2,
    h16* __restrict__ thi, h16* __restrict__ phi,
    float sc0, float sc1, float sc2)
{
    __shared__ float sv[32][33];
    int bx = blockIdx.x;
    const float* w; int n, T; long kbase; float s;
    int pb;
    if (bx < 258)      { w = w0; n = 128; T = T0; kbase = 0;  s = sc0; pb = bx * 32; }
    else if (bx < 324) { w = w1; n = 64;  T = T1; kbase = S1; s = sc1; pb = (bx - 258) * 32; }
    else               { w = w2; n = 32;  T = T2; kbase = S2; s = sc2; pb = (bx - 324) * 32; }
    int hb = blockIdx.y * 32;
    int tx = threadIdx.x & 31, ty = threadIdx.x >> 5;
    #pragma unroll
    for (int i = 0; i < 32; i += 8) {
        int pp = pb + ty + i;
        float val = 0.f;
        if (pp < T) {
            uint32_t uv = g_uv[kbase + pp];
            int u = uv >> 16, v = uv & 0xffff;
            val = w[((long)u * n + v) * HID + hb + tx];
            if (u != v) val += w[((long)v * n + u) * HID + hb + tx];
            val *= s;
        }
        sv[ty + i][tx] = val;
        phi[(kbase + pp) * (long)HID + hb + tx] = __float2half(val);
    }
    __syncthreads();
    #pragma unroll
    for (int i = 0; i < 32; i += 8) {
        thi[(long)(hb + ty + i) * KCP + kbase + pb + tx] = __float2half(sv[tx][ty + i]);
    }
}

// dense_all: tsc W1 (1024) | tsc W2 (256) | sconv W1 (4096) | sconv W2 (1024)
__global__ __launch_bounds__(256) void dense_all(
    const float* __restrict__ W1, const float* __restrict__ W2,
    h16* __restrict__ W1Thi, h16* __restrict__ W1Tlo,
    h16* __restrict__ W2Thi, h16* __restrict__ W2Tlo,
    h16* __restrict__ W1hi, h16* __restrict__ W1lo,
    h16* __restrict__ W2hi, h16* __restrict__ W2lo)
{
    __shared__ float t[32][33];
    long lin = blockIdx.x;
    if (lin < 1024 + 256) {
        const float* src; h16 *dhi, *dlo; int C; long ldd; int gx, gy;
        if (lin < 1024) { src = W1; dhi = W1Thi; dlo = W1Tlo; C = HID; ldd = HID; gx = (int)(lin % 32); gy = (int)(lin / 32); }
        else { long l = lin - 1024; src = W2; dhi = W2Thi; dlo = W2Tlo; C = ZD; ldd = HID; gx = (int)(l % 8); gy = (int)(l / 8); }
        int bx = gx * 32, by = gy * 32;
        int tx = threadIdx.x & 31, ty = threadIdx.x >> 5;
        #pragma unroll
        for (int i = 0; i < 32; i += 8)
            t[ty + i][tx] = src[(long)(by + ty + i) * C + bx + tx];
        __syncthreads();
        #pragma unroll
        for (int i = 0; i < 32; i += 8) {
            h16 h, l; splith(t[tx][ty + i], h, l);
            long o = (long)(bx + ty + i) * ldd + by + tx;
            dhi[o] = h; dlo[o] = l;
        }
    } else if (lin < 1024 + 256 + 4096) {
        long i = (lin - 1280) * 256 + threadIdx.x;
        if (i < HH) { h16 h, l; splith(W1[i], h, l); W1hi[i] = h; W1lo[i] = l; }
    } else {
        long i = (lin - 5376) * 256 + threadIdx.x;
        if (i < ZH) { h16 h, l; splith(W2[i], h, l); W2hi[i] = h; W2lo[i] = l; }
    }
}

// ---------------- build_Pp v3: per-row SMEM + offset LUT ----------------
__global__ __launch_bounds__(256) void build_Pp_v3(const float* __restrict__ t, h16* __restrict__ Ph)
{
    __shared__ float xs[DIMT];
    int b = blockIdx.x, tid = threadIdx.x;
    if (tid < DIMT) xs[tid] = t[(long)b * DIMT + tid];
    if (tid + 256 < DIMT) xs[tid + 256] = t[(long)b * DIMT + tid + 256];
    __syncthreads();
    h16* out = Ph + (long)b * KCP;
    for (int p = tid; p < KP0; p += 256) {
        uint32_t o = g_uvo[p];
        out[p] = __float2half(xs[o >> 16] * xs[o & 0xffff]);
    }
    for (int p = S1 + tid; p < S1 + KP1; p += 256) {
        uint32_t o = g_uvo[p];
        float val = 0.f;
        if (o != 0xFFFFFFFFu) {
            int uo = o >> 16, vo = o & 0xffff;
            #pragma unroll
            for (int m = 0; m < 3; m++) val += xs[uo + m] * xs[vo + m];
        }
        out[p] = __float2half(val);
    }
    for (int p = S2 + tid; p < S2 + KP2; p += 256) {
        uint32_t o = g_uvo[p];
        float val = 0.f;
        if (o != 0xFFFFFFFFu) {
            int uo = o >> 16, vo = o & 0xffff;
            #pragma unroll
            for (int m = 0; m < 5; m++) val += xs[uo + m] * xs[vo + m];
        }
        out[p] = __float2half(val);
    }
}

// ---------------- block reduce ----------------
__device__ __forceinline__ float blockReduceSum(float val) {
    __shared__ float sh[8];
    int lane = threadIdx.x & 31, w = threadIdx.x >> 5;
    #pragma unroll
    for (int o = 16; o > 0; o >>= 1) val += __shfl_down_sync(0xffffffffu, val, o);
    __syncthreads();
    if (lane == 0) sh[w] = val;
    __syncthreads();
    float r = 0.f;
    if (threadIdx.x == 0) {
        int nw = blockDim.x >> 5;
        for (int i = 0; i < nw; i++) r += sh[i];
    }
    return r;
}

// ---------------- LayerNorm + SiLU forward (layer 1) ----------------
__global__ __launch_bounds__(256) void ln_silu_fwd4(
    const float* __restrict__ a, const float* __restrict__ gam, const float* __restrict__ bet,
    float* __restrict__ xh, float* __restrict__ rstd, h16* __restrict__ hh)
{
    const int D = 1024;
    int b = blockIdx.x, tid = threadIdx.x;
    const float* row = a + (long)b * D;
    float v[4];
    float s = 0.f;
    #pragma unroll
    for (int i = 0; i < 4; i++) { v[i] = row[tid + (i << 8)]; s += v[i]; }
    s = blockReduceSum(s);
    __shared__ float bc;
    if (tid == 0) bc = s * (1.f / D);
    __syncthreads();
    float mu = bc;
    float q = 0.f;
    #pragma unroll
    for (int i = 0; i < 4; i++) { float d = v[i] - mu; q += d * d; }
    q = blockReduceSum(q);
    if (tid == 0) { float r = rsqrtf(q * (1.f / D) + 1e-6f); bc = r; rstd[b] = r; }
    __syncthreads();
    float r = bc;
    #pragma unroll
    for (int i = 0; i < 4; i++) {
        int c = tid + (i << 8);
        float x = (v[i] - mu) * r;
        xh[(long)b * D + c] = x;
        float z = x * gam[c] + bet[c];
        float sg = 1.f / (1.f + expf(-z));
        hh[(long)b * D + c] = __float2half(z * sg);
    }
}

// ---------------- fused LN2 fwd + bwd (layer 2, upstream ones) ----------------
__global__ __launch_bounds__(256) void ln2_fused(
    const float* __restrict__ a, const float* __restrict__ gam, const float* __restrict__ bet,
    float* __restrict__ xout, h16* __restrict__ dah)
{
    const int D = 256;
    int b = blockIdx.x, tid = threadIdx.x;
    float v = a[(long)b * D + tid];
    float s = blockReduceSum(v);
    __shared__ float bc;
    if (tid == 0) bc = s * (1.f / D);
    __syncthreads();
    float mu = bc;
    float d = v - mu;
    float q = blockReduceSum(d * d);
    if (tid == 0) bc = rsqrtf(q * (1.f / D) + 1e-6f);
    __syncthreads();
    float r = bc;
    float x = (v - mu) * r;
    float z = x * gam[tid] + bet[tid];
    float sg = 1.f / (1.f + expf(-z));
    xout[(long)b * D + tid] = z * sg;
    float ds = sg * (1.f + z * (1.f - sg));
    float dx = ds * gam[tid];
    float t1 = blockReduceSum(dx);
    __shared__ float m1s, m2s;
    if (tid == 0) m1s = t1 * (1.f / D);
    float t2 = blockReduceSum(dx * x);
    if (tid == 0) m2s = t2 * (1.f / D);
    __syncthreads();
    dah[(long)b * D + tid] = __float2half(r * (dx - m1s - x * m2s));
}

// ---------------- (SiLU + LN) backward (layer 1) ----------------
__global__ __launch_bounds__(256) void ln_silu_bwd4(
    const float* __restrict__ dh, const float* __restrict__ xhv_, const float* __restrict__ rstd,
    const float* __restrict__ gam, const float* __restrict__ bet, h16* __restrict__ dah)
{
    const int D = 1024;
    int b = blockIdx.x, tid = threadIdx.x;
    float xh[4], dxh[4];
    float s1 = 0.f, s2 = 0.f;
    #pragma unroll
    for (int i = 0; i < 4; i++) {
        int c = tid + (i << 8);
        float x = xhv_[(long)b * D + c];
        float z = x * gam[c] + bet[c];
        float sg = 1.f / (1.f + expf(-z));
        float ds = sg * (1.f + z * (1.f - sg));
        float dx = dh[(long)b * D + c] * ds * gam[c];
        xh[i] = x; dxh[i] = dx;
        s1 += dx; s2 += dx * x;
    }
    __shared__ float m1s, m2s;
    float t1 = blockReduceSum(s1);
    if (tid == 0) m1s = t1 * (1.f / D);
    float t2 = blockReduceSum(s2);
    if (tid == 0) m2s = t2 * (1.f / D);
    __syncthreads();
    float m1 = m1s, m2 = m2s, r = rstd[b];
    #pragma unroll
    for (int i = 0; i < 4; i++) {
        int c = tid + (i << 8);
        dah[(long)b * D + c] = __float2half(r * (dxh[i] - m1 - xh[i] * m2));
    }
}

// ---------------- merged packed quadratic-form gradients -> y ----------------
__global__ __launch_bounds__(192) void grad_all(const float* __restrict__ dPc,
                                                const float* __restrict__ t, float* __restrict__ y)
{
    extern __shared__ float Ts[];
    int tid = threadIdx.x;
    if (blockIdx.x < 2048) {
        int b = blockIdx.x;
        float* xs = Ts + 128 * 129;
        if (tid < 128) xs[tid] = t[(long)b * DIMT + tid];
        const float* P = dPc + (long)b * KCP;
        for (int i = tid; i < T0; i += 192) {
            uint32_t uv = g_uv[i];
            int u = uv >> 16, v = uv & 0xffff;
            float val = P[i];
            Ts[u * 129 + v] = val;
            Ts[v * 129 + u] = (u == v) ? 2.f * val : val;
        }
        __syncthreads();
        if (tid < 128) {
            float s = 0.f;
            #pragma unroll 8
            for (int v = 0; v < 128; v++) s += Ts[tid * 129 + v] * xs[v];
            y[(long)b * DIMT + tid] = s;
        }
    } else if (blockIdx.x < 4096) {
        int b = blockIdx.x - 2048;
        float* xs = Ts + 64 * 65;
        xs[tid] = t[(long)b * DIMT + 128 + tid];
        const float* P = dPc + (long)b * KCP + S1;
        for (int i = tid; i < T1; i += 192) {
            uint32_t uv = g_uv[S1 + i];
            int u = uv >> 16, v = uv & 0xffff;
            float val = P[i];
            Ts[u * 65 + v] = val;
            Ts[v * 65 + u] = (u == v) ? 2.f * val : val;
        }
        __syncthreads();
        int u = tid / 3, m = tid - u * 3;
        float s = 0.f;
        #pragma unroll 8
        for (int v = 0; v < 64; v++) s += Ts[u * 65 + v] * xs[v * 3 + m];
        y[(long)b * DIMT + 128 + tid] = s;
    } else {
        int b = blockIdx.x - 4096;
        float* xs = Ts + 32 * 33;
        if (tid < 160) xs[tid] = t[(long)b * DIMT + 320 + tid];
        const float* P = dPc + (long)b * KCP + S2;
        for (int i = tid; i < T2; i += 192) {
            uint32_t uv = g_uv[S2 + i];
            int u = uv >> 16, v = uv & 0xffff;
            float val = P[i];
            Ts[u * 33 + v] = val;
            Ts[v * 33 + u] = (u == v) ? 2.f * val : val;
        }
        __syncthreads();
        if (tid < 160) {
            int u = tid / 5, m = tid - u * 5;
            float s = 0.f;
            #pragma unroll 8
            for (int v = 0; v < 32; v++) s += Ts[u * 33 + v] * xs[v * 5 + m];
            y[(long)b * DIMT + 320 + tid] = s;
        }
    }
}

// ---------------- launch ----------------
extern "C" void kernel_launch(void* const* d_in, const int* in_sizes, int n_in,
                              void* d_out, int out_size)
{
    const float* tin = (const float*)d_in[0];
    const float* w0  = (const float*)d_in[1];
    const float* w1  = (const float*)d_in[2];
    const float* w2  = (const float*)d_in[3];
    const float* W1  = (const float*)d_in[4];
    const float* b1  = (const float*)d_in[5];
    const float* g1  = (const float*)d_in[6];
    const float* be1 = (const float*)d_in[7];
    const float* W2  = (const float*)d_in[8];
    const float* b2  = (const float*)d_in[9];
    const float* g2  = (const float*)d_in[10];
    const float* be2 = (const float*)d_in[11];

    float* out  = (float*)d_out;
    float* xout = out;
    float* yout = out + (long)NB * ZD;

    h16* hb = nullptr; float* fb = nullptr;
    cudaGetSymbolAddress((void**)&hb, g_hbuf);
    cudaGetSymbolAddress((void**)&fb, g_fbuf);

    h16 *PC   = hb + B_PC;
    h16 *WThi = hb + B_WTHI;
    h16 *WPhi = hb + B_WPHI;
    h16 *W1Thi= hb + B_W1THI,*W1Tlo= hb + B_W1TLO;
    h16 *W1hi = hb + B_W1HI, *W1lo = hb + B_W1LO;
    h16 *W2Thi= hb + B_W2THI,*W2Tlo= hb + B_W2TLO;
    h16 *W2hi = hb + B_W2HI, *W2lo = hb + B_W2LO;
    h16 *eh   = hb + B_EH;
    h16 *h1h  = hb + B_H1H;
    h16 *da2h = hb + B_DA2H;
    h16 *da1h = hb + B_DA1H;
    h16 *deh  = hb + B_DEH;

    float *dPC = fb + F_DPC, *a1 = fb + F_A1, *xh1 = fb + F_XH1;
    float *a2  = fb + F_A2,  *dh1 = fb + F_DH1, *rs1 = fb + F_RS1;

    const float s0 = 1.0f / sqrtf(21504.0f);
    const float s1 = s0 / sqrtf(3.0f);
    const float s2 = s0 / sqrtf(5.0f);

    cudaFuncSetAttribute(h_gemm_nt<true>,  cudaFuncAttributeMaxDynamicSharedMemorySize, GSMEM);
    cudaFuncSetAttribute(h_gemm_nt<false>, cudaFuncAttributeMaxDynamicSharedMemorySize, GSMEM);
    cudaFuncSetAttribute(grad_all, cudaFuncAttributeMaxDynamicSharedMemorySize, 128 * 129 * 4 + 768);

    // ---- prep ----
    uv_init<<<(KCP + 255) / 256, 256>>>();
    pack_both<<<dim3(344, HID / 32), 256>>>(w0, w1, w2, WThi, WPhi, s0, s1, s2);
    dense_all<<<6400, 256>>>(W1, W2, W1Thi, W1Tlo, W2Thi, W2Tlo, W1hi, W1lo, W2hi, W2lo);
    build_Pp_v3<<<NB, 256>>>(tin, PC);

    // ---- forward ----
    // e-GEMM: weight-hi only (error model: +~2.2e-4 in quadrature)
    h_gemm_nt<false><<<dim3(HID / 128, NB / 128), 512, GSMEM>>>(
        PC, WThi, WThi, nullptr, eh, KCP, HID, 1.f, nullptr);
    h_gemm_nt<true><<<dim3(HID / 128, NB / 128), 512, GSMEM>>>(
        eh, W1Thi, W1Tlo, a1, nullptr, HID, HID, 1.f, b1);
    ln_silu_fwd4<<<NB, 256>>>(a1, g1, be1, xh1, rs1, h1h);
    h_gemm_nt<true><<<dim3(ZD / 128, NB / 128), 512, GSMEM>>>(
        h1h, W2Thi, W2Tlo, a2, nullptr, HID, ZD, 1.f, b2);
    ln2_fused<<<NB, 256>>>(a2, g2, be2, xout, da2h);

    // ---- backward ----
    h_gemm_nt<true><<<dim3(HID / 128, NB / 128), 512, GSMEM>>>(
        da2h, W2hi, W2lo, dh1, nullptr, ZD, HID, 1.f, nullptr);
    ln_silu_bwd4<<<NB, 256>>>(dh1, xh1, rs1, g1, be1, da1h);
    h_gemm_nt<true><<<dim3(HID / 128, NB / 128), 512, GSMEM>>>(
        da1h, W1hi, W1lo, nullptr, deh, HID, HID, 1.f, nullptr);
    h_gemm_nt<false><<<dim3(KCP / 128, NB / 128), 512, GSMEM>>>(
        deh, WPhi, WPhi, dPC, nullptr, HID, KCP, 1.f, nullptr);

    grad_all<<<6144, 192, 128 * 129 * 4 + 768>>>(dPC, tin, yout);
}

// round 14
// speedup vs baseline: 10.0843x; 1.0612x over previous
#include <cuda_runtime.h>
#include <cuda_fp16.h>
#include <math.h>
#include <stdint.h>

#define NB   2048
#define DIMT 480
#define HID  1024
#define ZD   256
#define T0   8256
#define KP0  8256
#define T1   2080
#define KP1  2112
#define T2   528
#define KP2  640
#define KCP  11008
#define S1   8256
#define S2   10368

typedef __half h16;

// ---------------- scratch pools ----------------
constexpr long NBKC = (long)NB * KCP;
constexpr long HKC  = (long)HID * KCP;
constexpr long HH   = (long)HID * HID;
constexpr long ZH   = (long)ZD * HID;
constexpr long NH   = (long)NB * HID;
constexpr long NZ   = (long)NB * ZD;

constexpr long B_PC   = 0;
constexpr long B_WTHI = B_PC   + NBKC;
constexpr long B_WPHI = B_WTHI + HKC;
constexpr long B_W1THI= B_WPHI + HKC;
constexpr long B_W1TLO= B_W1THI + HH;
constexpr long B_W1HI = B_W1TLO + HH;
constexpr long B_W1LO = B_W1HI + HH;
constexpr long B_W2THI= B_W1LO + HH;
constexpr long B_W2TLO= B_W2THI + ZH;
constexpr long B_W2HI = B_W2TLO + ZH;
constexpr long B_W2LO = B_W2HI + ZH;
constexpr long B_EH   = B_W2LO + ZH;
constexpr long B_H1H  = B_EH   + NH;
constexpr long B_DA2H = B_H1H  + NH;
constexpr long B_DA1H = B_DA2H + NZ;
constexpr long B_DEH  = B_DA1H + NH;
constexpr long B_TOT  = B_DEH  + NH;

constexpr long F_DPC  = 0;
constexpr long F_A1   = F_DPC + NBKC;
constexpr long F_XH1  = F_A1  + NH;
constexpr long F_A2   = F_XH1 + NH;
constexpr long F_DH1  = F_A2  + NZ;
constexpr long F_RS1  = F_DH1 + NH;
constexpr long F_TOT  = F_RS1 + NB;

__device__ h16      g_hbuf[B_TOT];
__device__ float    g_fbuf[F_TOT];
__device__ uint32_t g_uv[KCP];
__device__ uint32_t g_uvo[KCP];

// ---------------- helpers ----------------
__device__ __forceinline__ uint32_t smem_u32(const void* p) {
    uint32_t a;
    asm("{ .reg .u64 t; cvta.to.shared.u64 t, %1; cvt.u32.u64 %0, t; }" : "=r"(a) : "l"(p));
    return a;
}
__device__ __forceinline__ void ldsm4(uint32_t* r, uint32_t a) {
    asm volatile("ldmatrix.sync.aligned.m8n8.x4.shared.b16 {%0,%1,%2,%3},[%4];"
                 : "=r"(r[0]), "=r"(r[1]), "=r"(r[2]), "=r"(r[3]) : "r"(a));
}
__device__ __forceinline__ void mma_f16(float* d, const uint32_t* a, const uint32_t* b) {
    asm volatile("mma.sync.aligned.m16n8k16.row.col.f32.f16.f16.f32 "
                 "{%0,%1,%2,%3},{%4,%5,%6,%7},{%8,%9},{%0,%1,%2,%3};"
                 : "+f"(d[0]), "+f"(d[1]), "+f"(d[2]), "+f"(d[3])
                 : "r"(a[0]), "r"(a[1]), "r"(a[2]), "r"(a[3]), "r"(b[0]), "r"(b[1]));
}
#define CPA(dst, src) asm volatile("cp.async.cg.shared.global [%0], [%1], 16;" :: "r"(dst), "l"(src) : "memory")
#define CPCOMMIT()    asm volatile("cp.async.commit_group;" ::: "memory")
#define CPWAIT0()     asm volatile("cp.async.wait_group 0;" ::: "memory")

__device__ __forceinline__ void splith(float v, h16& h, h16& l) {
    h = __float2half(v);
    l = __float2half((v - __half2float(h)) * 2048.f);
}

// ---------------- pair LUTs ----------------
__global__ void uv_init() {
    int p = blockIdx.x * 256 + threadIdx.x;
    if (p >= KCP) return;
    int n, lp, T, nm, xoff;
    if (p < S1)      { n = 128; lp = p;      T = T0; nm = 1; xoff = 0; }
    else if (p < S2) { n = 64;  lp = p - S1; T = T1; nm = 3; xoff = 128; }
    else             { n = 32;  lp = p - S2; T = T2; nm = 5; xoff = 320; }
    if (lp >= T) { g_uv[p] = 0u; g_uvo[p] = 0xFFFFFFFFu; return; }
    float tn = 2.f * n + 1.f;
    int u = (int)((tn - sqrtf(tn * tn - 8.f * lp)) * 0.5f);
    if (u < 0) u = 0; if (u > n - 1) u = n - 1;
    while (u > 0 && u * n - u * (u - 1) / 2 > lp) u--;
    while (u < n - 1 && (u + 1) * n - (u + 1) * u / 2 <= lp) u++;
    int v = u + (lp - (u * n - u * (u - 1) / 2));
    g_uv[p]  = ((uint32_t)u << 16) | (uint32_t)v;
    g_uvo[p] = ((uint32_t)(xoff + u * nm) << 16) | (uint32_t)(xoff + v * nm);
}

// ---------------- fp16 NT GEMM: BK=128, 2-stage, 512 threads ----------------
#define TILEH 32768
#define STGH  (3 * TILEH)
#define GSMEM (2 * STGH + 1024)

template<bool LO>
__global__ __launch_bounds__(512, 1) void h_gemm_nt(
    const h16* __restrict__ A, const h16* __restrict__ Bhi, const h16* __restrict__ Blo,
    float* __restrict__ C, h16* __restrict__ Ch,
    int K, long ldc, float alpha, const float* __restrict__ bias)
{
    extern __shared__ char smem[];
    const uint32_t st0 = (smem_u32(smem) + 1023) & ~1023u;
    const int tid = threadIdx.x, wid = tid >> 5, lane = tid & 31;
    const int wm = wid >> 2, wn = wid & 3;
    const long bm = (long)blockIdx.y * 128, bn = (long)blockIdx.x * 128;

    constexpr int NCH = LO ? 12 : 8;
    const h16* gp[NCH];
    uint32_t so[NCH];
    #pragma unroll
    for (int t = 0; t < NCH; t++) {
        int q = tid + (t & 3) * 512;
        int r = q >> 4, c = q & 15;
        int tile = t >> 2;
        const h16* base = (tile == 0) ? A : (tile == 1) ? Bhi : Blo;
        long row = (tile == 0 ? bm : bn) + r;
        gp[t] = base + row * K + c * 8;
        so[t] = st0 + tile * TILEH + ((r * 256 + c * 16) ^ ((r & 7) << 4));
    }
    const int nk = K >> 7;

    #pragma unroll
    for (int t = 0; t < NCH; t++) CPA(so[t], gp[t]);
    CPCOMMIT();

    float ac1[2][4][4], ac2[2][4][4];
    #pragma unroll
    for (int a = 0; a < 2; a++)
        #pragma unroll
        for (int b = 0; b < 4; b++)
            #pragma unroll
            for (int c = 0; c < 4; c++) { ac1[a][b][c] = 0.f; if (LO) ac2[a][b][c] = 0.f; }

    const int lr = lane & 15, lc = lane >> 4;
    const uint32_t xa = (lr & 7) << 4;
    const uint32_t arow = (wm * 32 + lr) * 256 + lc * 16;
    const uint32_t brow = (wn * 32 + lr) * 256 + lc * 16;

    for (int i = 0; i < nk; i++) {
        CPWAIT0();
        __syncthreads();
        if (i + 1 < nk) {
            const uint32_t sst = ((i + 1) & 1) * STGH;
            #pragma unroll
            for (int t = 0; t < NCH; t++) CPA(so[t] + sst, gp[t] + (long)(i + 1) * 128);
            CPCOMMIT();
        }

        const uint32_t sa = st0 + (i & 1) * STGH;
        #pragma unroll
        for (int kk = 0; kk < 8; kk++) {
            uint32_t af[2][4], bh[4][2], bl[4][2];
            #pragma unroll
            for (int mi = 0; mi < 2; mi++)
                ldsm4(af[mi], sa + ((arow + mi * 4096 + kk * 32) ^ xa));
            #pragma unroll
            for (int pi = 0; pi < 2; pi++) {
                uint32_t off = (brow + pi * 4096 + kk * 32) ^ xa;
                uint32_t t0[4];
                ldsm4(t0, sa + TILEH + off);
                bh[2 * pi][0] = t0[0]; bh[2 * pi + 1][0] = t0[1];
                bh[2 * pi][1] = t0[2]; bh[2 * pi + 1][1] = t0[3];
                if (LO) {
                    uint32_t t1[4];
                    ldsm4(t1, sa + 2 * TILEH + off);
                    bl[2 * pi][0] = t1[0]; bl[2 * pi + 1][0] = t1[1];
                    bl[2 * pi][1] = t1[2]; bl[2 * pi + 1][1] = t1[3];
                }
            }
            #pragma unroll
            for (int mi = 0; mi < 2; mi++)
                #pragma unroll
                for (int ni = 0; ni < 4; ni++) {
                    mma_f16(ac1[mi][ni], af[mi], bh[ni]);
                    if (LO) mma_f16(ac2[mi][ni], af[mi], bl[ni]);
                }
        }
    }

    const int g = lane >> 2, tg = lane & 3;
    const float inv = 1.f / 2048.f;
    #pragma unroll
    for (int mi = 0; mi < 2; mi++) {
        #pragma unroll
        for (int ni = 0; ni < 4; ni++) {
            long m0 = bm + wm * 32 + mi * 16 + g;
            long n0 = bn + wn * 32 + ni * 8 + tg * 2;
            float v00, v01, v10, v11;
            if (LO) {
                v00 = alpha * (ac1[mi][ni][0] + ac2[mi][ni][0] * inv);
                v01 = alpha * (ac1[mi][ni][1] + ac2[mi][ni][1] * inv);
                v10 = alpha * (ac1[mi][ni][2] + ac2[mi][ni][2] * inv);
                v11 = alpha * (ac1[mi][ni][3] + ac2[mi][ni][3] * inv);
            } else {
                v00 = alpha * ac1[mi][ni][0];
                v01 = alpha * ac1[mi][ni][1];
                v10 = alpha * ac1[mi][ni][2];
                v11 = alpha * ac1[mi][ni][3];
            }
            if (bias) {
                float bb0 = bias[n0], bb1 = bias[n0 + 1];
                v00 += bb0; v01 += bb1; v10 += bb0; v11 += bb1;
            }
            if (C) {
                *(float2*)(C + m0 * ldc + n0) = make_float2(v00, v01);
                *(float2*)(C + (m0 + 8) * ldc + n0) = make_float2(v10, v11);
            }
            if (Ch) {
                *(__half2*)(Ch + m0 * ldc + n0) = __floats2half2_rn(v00, v01);
                *(__half2*)(Ch + (m0 + 8) * ldc + n0) = __floats2half2_rn(v10, v11);
            }
        }
    }
}

// ---------------- merged packing (hi-only outputs) ----------------
__global__ __launch_bounds__(256) void pack_both(
    const float* __restrict__ w0, const float* __restrict__ w1, const float* __restrict__ w2,
    h16* __restrict__ thi, h16* __restrict__ phi,
    float sc0, float sc1, float sc2)
{
    __shared__ float sv[32][33];
    int bx = blockIdx.x;
    const float* w; int n, T; long kbase; float s;
    int pb;
    if (bx < 258)      { w = w0; n = 128; T = T0; kbase = 0;  s = sc0; pb = bx * 32; }
    else if (bx < 324) { w = w1; n = 64;  T = T1; kbase = S1; s = sc1; pb = (bx - 258) * 32; }
    else               { w = w2; n = 32;  T = T2; kbase = S2; s = sc2; pb = (bx - 324) * 32; }
    int hb = blockIdx.y * 32;
    int tx = threadIdx.x & 31, ty = threadIdx.x >> 5;
    #pragma unroll
    for (int i = 0; i < 32; i += 8) {
        int pp = pb + ty + i;
        float val = 0.f;
        if (pp < T) {
            uint32_t uv = g_uv[kbase + pp];
            int u = uv >> 16, v = uv & 0xffff;
            val = w[((long)u * n + v) * HID + hb + tx];
            if (u != v) val += w[((long)v * n + u) * HID + hb + tx];
            val *= s;
        }
        sv[ty + i][tx] = val;
        phi[(kbase + pp) * (long)HID + hb + tx] = __float2half(val);
    }
    __syncthreads();
    #pragma unroll
    for (int i = 0; i < 32; i += 8) {
        thi[(long)(hb + ty + i) * KCP + kbase + pb + tx] = __float2half(sv[tx][ty + i]);
    }
}

// dense_all
__global__ __launch_bounds__(256) void dense_all(
    const float* __restrict__ W1, const float* __restrict__ W2,
    h16* __restrict__ W1Thi, h16* __restrict__ W1Tlo,
    h16* __restrict__ W2Thi, h16* __restrict__ W2Tlo,
    h16* __restrict__ W1hi, h16* __restrict__ W1lo,
    h16* __restrict__ W2hi, h16* __restrict__ W2lo)
{
    __shared__ float t[32][33];
    long lin = blockIdx.x;
    if (lin < 1024 + 256) {
        const float* src; h16 *dhi, *dlo; int C; long ldd; int gx, gy;
        if (lin < 1024) { src = W1; dhi = W1Thi; dlo = W1Tlo; C = HID; ldd = HID; gx = (int)(lin % 32); gy = (int)(lin / 32); }
        else { long l = lin - 1024; src = W2; dhi = W2Thi; dlo = W2Tlo; C = ZD; ldd = HID; gx = (int)(l % 8); gy = (int)(l / 8); }
        int bx = gx * 32, by = gy * 32;
        int tx = threadIdx.x & 31, ty = threadIdx.x >> 5;
        #pragma unroll
        for (int i = 0; i < 32; i += 8)
            t[ty + i][tx] = src[(long)(by + ty + i) * C + bx + tx];
        __syncthreads();
        #pragma unroll
        for (int i = 0; i < 32; i += 8) {
            h16 h, l; splith(t[tx][ty + i], h, l);
            long o = (long)(bx + ty + i) * ldd + by + tx;
            dhi[o] = h; dlo[o] = l;
        }
    } else if (lin < 1024 + 256 + 4096) {
        long i = (lin - 1280) * 256 + threadIdx.x;
        if (i < HH) { h16 h, l; splith(W1[i], h, l); W1hi[i] = h; W1lo[i] = l; }
    } else {
        long i = (lin - 5376) * 256 + threadIdx.x;
        if (i < ZH) { h16 h, l; splith(W2[i], h, l); W2hi[i] = h; W2lo[i] = l; }
    }
}

// ---------------- build_Pp v4: vectorized region 0 ----------------
__global__ __launch_bounds__(256) void build_Pp_v4(const float* __restrict__ t, h16* __restrict__ Ph)
{
    __shared__ float xs[DIMT];
    int b = blockIdx.x, tid = threadIdx.x;
    if (tid < DIMT) xs[tid] = t[(long)b * DIMT + tid];
    if (tid + 256 < DIMT) xs[tid + 256] = t[(long)b * DIMT + tid + 256];
    __syncthreads();
    h16* out = Ph + (long)b * KCP;
    // region 0: two pairs per iteration (KP0 even)
    for (int p = tid * 2; p < KP0; p += 512) {
        uint2 oo = *(const uint2*)(g_uvo + p);
        float v0 = xs[oo.x >> 16] * xs[oo.x & 0xffff];
        float v1 = xs[oo.y >> 16] * xs[oo.y & 0xffff];
        *(__half2*)(out + p) = __floats2half2_rn(v0, v1);
    }
    for (int p = S1 + tid; p < S1 + KP1; p += 256) {
        uint32_t o = g_uvo[p];
        float val = 0.f;
        if (o != 0xFFFFFFFFu) {
            int uo = o >> 16, vo = o & 0xffff;
            #pragma unroll
            for (int m = 0; m < 3; m++) val += xs[uo + m] * xs[vo + m];
        }
        out[p] = __float2half(val);
    }
    for (int p = S2 + tid; p < S2 + KP2; p += 256) {
        uint32_t o = g_uvo[p];
        float val = 0.f;
        if (o != 0xFFFFFFFFu) {
            int uo = o >> 16, vo = o & 0xffff;
            #pragma unroll
            for (int m = 0; m < 5; m++) val += xs[uo + m] * xs[vo + m];
        }
        out[p] = __float2half(val);
    }
}

// ---------------- block reduce ----------------
__device__ __forceinline__ float blockReduceSum(float val) {
    __shared__ float sh[8];
    int lane = threadIdx.x & 31, w = threadIdx.x >> 5;
    #pragma unroll
    for (int o = 16; o > 0; o >>= 1) val += __shfl_down_sync(0xffffffffu, val, o);
    __syncthreads();
    if (lane == 0) sh[w] = val;
    __syncthreads();
    float r = 0.f;
    if (threadIdx.x == 0) {
        int nw = blockDim.x >> 5;
        for (int i = 0; i < nw; i++) r += sh[i];
    }
    return r;
}

// ---------------- LayerNorm + SiLU forward (layer 1) ----------------
__global__ __launch_bounds__(256) void ln_silu_fwd4(
    const float* __restrict__ a, const float* __restrict__ gam, const float* __restrict__ bet,
    float* __restrict__ xh, float* __restrict__ rstd, h16* __restrict__ hh)
{
    const int D = 1024;
    int b = blockIdx.x, tid = threadIdx.x;
    const float* row = a + (long)b * D;
    float v[4];
    float s = 0.f;
    #pragma unroll
    for (int i = 0; i < 4; i++) { v[i] = row[tid + (i << 8)]; s += v[i]; }
    s = blockReduceSum(s);
    __shared__ float bc;
    if (tid == 0) bc = s * (1.f / D);
    __syncthreads();
    float mu = bc;
    float q = 0.f;
    #pragma unroll
    for (int i = 0; i < 4; i++) { float d = v[i] - mu; q += d * d; }
    q = blockReduceSum(q);
    if (tid == 0) { float r = rsqrtf(q * (1.f / D) + 1e-6f); bc = r; rstd[b] = r; }
    __syncthreads();
    float r = bc;
    #pragma unroll
    for (int i = 0; i < 4; i++) {
        int c = tid + (i << 8);
        float x = (v[i] - mu) * r;
        xh[(long)b * D + c] = x;
        float z = x * gam[c] + bet[c];
        float sg = 1.f / (1.f + expf(-z));
        hh[(long)b * D + c] = __float2half(z * sg);
    }
}

// ---------------- fused LN2 fwd + bwd ----------------
__global__ __launch_bounds__(256) void ln2_fused(
    const float* __restrict__ a, const float* __restrict__ gam, const float* __restrict__ bet,
    float* __restrict__ xout, h16* __restrict__ dah)
{
    const int D = 256;
    int b = blockIdx.x, tid = threadIdx.x;
    float v = a[(long)b * D + tid];
    float s = blockReduceSum(v);
    __shared__ float bc;
    if (tid == 0) bc = s * (1.f / D);
    __syncthreads();
    float mu = bc;
    float d = v - mu;
    float q = blockReduceSum(d * d);
    if (tid == 0) bc = rsqrtf(q * (1.f / D) + 1e-6f);
    __syncthreads();
    float r = bc;
    float x = (v - mu) * r;
    float z = x * gam[tid] + bet[tid];
    float sg = 1.f / (1.f + expf(-z));
    xout[(long)b * D + tid] = z * sg;
    float ds = sg * (1.f + z * (1.f - sg));
    float dx = ds * gam[tid];
    float t1 = blockReduceSum(dx);
    __shared__ float m1s, m2s;
    if (tid == 0) m1s = t1 * (1.f / D);
    float t2 = blockReduceSum(dx * x);
    if (tid == 0) m2s = t2 * (1.f / D);
    __syncthreads();
    dah[(long)b * D + tid] = __float2half(r * (dx - m1s - x * m2s));
}

// ---------------- (SiLU + LN) backward (layer 1) ----------------
__global__ __launch_bounds__(256) void ln_silu_bwd4(
    const float* __restrict__ dh, const float* __restrict__ xhv_, const float* __restrict__ rstd,
    const float* __restrict__ gam, const float* __restrict__ bet, h16* __restrict__ dah)
{
    const int D = 1024;
    int b = blockIdx.x, tid = threadIdx.x;
    float xh[4], dxh[4];
    float s1 = 0.f, s2 = 0.f;
    #pragma unroll
    for (int i = 0; i < 4; i++) {
        int c = tid + (i << 8);
        float x = xhv_[(long)b * D + c];
        float z = x * gam[c] + bet[c];
        float sg = 1.f / (1.f + expf(-z));
        float ds = sg * (1.f + z * (1.f - sg));
        float dx = dh[(long)b * D + c] * ds * gam[c];
        xh[i] = x; dxh[i] = dx;
        s1 += dx; s2 += dx * x;
    }
    __shared__ float m1s, m2s;
    float t1 = blockReduceSum(s1);
    if (tid == 0) m1s = t1 * (1.f / D);
    float t2 = blockReduceSum(s2);
    if (tid == 0) m2s = t2 * (1.f / D);
    __syncthreads();
    float m1 = m1s, m2 = m2s, r = rstd[b];
    #pragma unroll
    for (int i = 0; i < 4; i++) {
        int c = tid + (i << 8);
        dah[(long)b * D + c] = __float2half(r * (dxh[i] - m1 - xh[i] * m2));
    }
}

// ---------------- merged packed quadratic-form gradients -> y ----------------
__global__ __launch_bounds__(192) void grad_all(const float* __restrict__ dPc,
                                                const float* __restrict__ t, float* __restrict__ y)
{
    extern __shared__ float Ts[];
    int tid = threadIdx.x;
    if (blockIdx.x < 2048) {
        int b = blockIdx.x;
        float* xs = Ts + 128 * 129;
        if (tid < 128) xs[tid] = t[(long)b * DIMT + tid];
        const float* P = dPc + (long)b * KCP;
        // vectorized scatter: 4 consecutive elements per iter (T0 % 4 == 0)
        for (int i = tid * 4; i < T0; i += 768) {
            float4 pv = *(const float4*)(P + i);
            uint4  ov = *(const uint4*)(g_uv + i);
            float  vv[4] = {pv.x, pv.y, pv.z, pv.w};
            uint32_t oo[4] = {ov.x, ov.y, ov.z, ov.w};
            #pragma unroll
            for (int k = 0; k < 4; k++) {
                int u = oo[k] >> 16, v = oo[k] & 0xffff;
                Ts[u * 129 + v] = vv[k];
                Ts[v * 129 + u] = (u == v) ? 2.f * vv[k] : vv[k];
            }
        }
        __syncthreads();
        if (tid < 128) {
            float s = 0.f;
            #pragma unroll 8
            for (int v = 0; v < 128; v++) s += Ts[tid * 129 + v] * xs[v];
            y[(long)b * DIMT + tid] = s;
        }
    } else if (blockIdx.x < 4096) {
        int b = blockIdx.x - 2048;
        float* xs = Ts + 64 * 65;
        xs[tid] = t[(long)b * DIMT + 128 + tid];
        const float* P = dPc + (long)b * KCP + S1;
        for (int i = tid * 4; i < T0 + 0; i += 768) {   // bound replaced below
            break;
        }
        for (int i = tid * 4; i < T1; i += 768) {       // T1 = 2080, 2080 % 4 == 0
            float4 pv = *(const float4*)(P + i);
            uint4  ov = *(const uint4*)(g_uv + S1 + i);
            float  vv[4] = {pv.x, pv.y, pv.z, pv.w};
            uint32_t oo[4] = {ov.x, ov.y, ov.z, ov.w};
            #pragma unroll
            for (int k = 0; k < 4; k++) {
                int u = oo[k] >> 16, v = oo[k] & 0xffff;
                Ts[u * 65 + v] = vv[k];
                Ts[v * 65 + u] = (u == v) ? 2.f * vv[k] : vv[k];
            }
        }
        __syncthreads();
        int u = tid / 3, m = tid - u * 3;
        float s = 0.f;
        #pragma unroll 8
        for (int v = 0; v < 64; v++) s += Ts[u * 65 + v] * xs[v * 3 + m];
        y[(long)b * DIMT + 128 + tid] = s;
    } else {
        int b = blockIdx.x - 4096;
        float* xs = Ts + 32 * 33;
        if (tid < 160) xs[tid] = t[(long)b * DIMT + 320 + tid];
        const float* P = dPc + (long)b * KCP + S2;
        for (int i = tid * 4; i < T2; i += 768) {       // T2 = 528, 528 % 4 == 0
            float4 pv = *(const float4*)(P + i);
            uint4  ov = *(const uint4*)(g_uv + S2 + i);
            float  vv[4] = {pv.x, pv.y, pv.z, pv.w};
            uint32_t oo[4] = {ov.x, ov.y, ov.z, ov.w};
            #pragma unroll
            for (int k = 0; k < 4; k++) {
                int u = oo[k] >> 16, v = oo[k] & 0xffff;
                Ts[u * 33 + v] = vv[k];
                Ts[v * 33 + u] = (u == v) ? 2.f * vv[k] : vv[k];
            }
        }
        __syncthreads();
        if (tid < 160) {
            int u = tid / 5, m = tid - u * 5;
            float s = 0.f;
            #pragma unroll 8
            for (int v = 0; v < 32; v++) s += Ts[u * 33 + v] * xs[v * 5 + m];
            y[(long)b * DIMT + 320 + tid] = s;
        }
    }
}

// ---------------- launch ----------------
extern "C" void kernel_launch(void* const* d_in, const int* in_sizes, int n_in,
                              void* d_out, int out_size)
{
    const float* tin = (const float*)d_in[0];
    const float* w0  = (const float*)d_in[1];
    const float* w1  = (const float*)d_in[2];
    const float* w2  = (const float*)d_in[3];
    const float* W1  = (const float*)d_in[4];
    const float* b1  = (const float*)d_in[5];
    const float* g1  = (const float*)d_in[6];
    const float* be1 = (const float*)d_in[7];
    const float* W2  = (const float*)d_in[8];
    const float* b2  = (const float*)d_in[9];
    const float* g2  = (const float*)d_in[10];
    const float* be2 = (const float*)d_in[11];

    float* out  = (float*)d_out;
    float* xout = out;
    float* yout = out + (long)NB * ZD;

    h16* hb = nullptr; float* fb = nullptr;
    cudaGetSymbolAddress((void**)&hb, g_hbuf);
    cudaGetSymbolAddress((void**)&fb, g_fbuf);

    h16 *PC   = hb + B_PC;
    h16 *WThi = hb + B_WTHI;
    h16 *WPhi = hb + B_WPHI;
    h16 *W1Thi= hb + B_W1THI,*W1Tlo= hb + B_W1TLO;
    h16 *W1hi = hb + B_W1HI, *W1lo = hb + B_W1LO;
    h16 *W2Thi= hb + B_W2THI,*W2Tlo= hb + B_W2TLO;
    h16 *W2hi = hb + B_W2HI, *W2lo = hb + B_W2LO;
    h16 *eh   = hb + B_EH;
    h16 *h1h  = hb + B_H1H;
    h16 *da2h = hb + B_DA2H;
    h16 *da1h = hb + B_DA1H;
    h16 *deh  = hb + B_DEH;

    float *dPC = fb + F_DPC, *a1 = fb + F_A1, *xh1 = fb + F_XH1;
    float *a2  = fb + F_A2,  *dh1 = fb + F_DH1, *rs1 = fb + F_RS1;

    const float s0 = 1.0f / sqrtf(21504.0f);
    const float s1 = s0 / sqrtf(3.0f);
    const float s2 = s0 / sqrtf(5.0f);

    cudaFuncSetAttribute(h_gemm_nt<true>,  cudaFuncAttributeMaxDynamicSharedMemorySize, GSMEM);
    cudaFuncSetAttribute(h_gemm_nt<false>, cudaFuncAttributeMaxDynamicSharedMemorySize, GSMEM);
    cudaFuncSetAttribute(grad_all, cudaFuncAttributeMaxDynamicSharedMemorySize, 128 * 129 * 4 + 768);

    // ---- prep ----
    uv_init<<<(KCP + 255) / 256, 256>>>();
    pack_both<<<dim3(344, HID / 32), 256>>>(w0, w1, w2, WThi, WPhi, s0, s1, s2);
    dense_all<<<6400, 256>>>(W1, W2, W1Thi, W1Tlo, W2Thi, W2Tlo, W1hi, W1lo, W2hi, W2lo);
    build_Pp_v4<<<NB, 256>>>(tin, PC);

    // ---- forward ----
    h_gemm_nt<false><<<dim3(HID / 128, NB / 128), 512, GSMEM>>>(
        PC, WThi, WThi, nullptr, eh, KCP, HID, 1.f, nullptr);
    h_gemm_nt<true><<<dim3(HID / 128, NB / 128), 512, GSMEM>>>(
        eh, W1Thi, W1Tlo, a1, nullptr, HID, HID, 1.f, b1);
    ln_silu_fwd4<<<NB, 256>>>(a1, g1, be1, xh1, rs1, h1h);
    h_gemm_nt<true><<<dim3(ZD / 128, NB / 128), 512, GSMEM>>>(
        h1h, W2Thi, W2Tlo, a2, nullptr, HID, ZD, 1.f, b2);
    ln2_fused<<<NB, 256>>>(a2, g2, be2, xout, da2h);

    // ---- backward ----
    h_gemm_nt<true><<<dim3(HID / 128, NB / 128), 512, GSMEM>>>(
        da2h, W2hi, W2lo, dh1, nullptr, ZD, HID, 1.f, nullptr);
    ln_silu_bwd4<<<NB, 256>>>(dh1, xh1, rs1, g1, be1, da1h);
    h_gemm_nt<true><<<dim3(HID / 128, NB / 128), 512, GSMEM>>>(
        da1h, W1hi, W1lo, nullptr, deh, HID, HID, 1.f, nullptr);
    h_gemm_nt<false><<<dim3(KCP / 128, NB / 128), 512, GSMEM>>>(
        deh, WPhi, WPhi, dPC, nullptr, HID, KCP, 1.f, nullptr);

    grad_all<<<6144, 192, 128 * 129 * 4 + 768>>>(dPC, tin, yout);
}

// round 15
// speedup vs baseline: 10.1965x; 1.0111x over previous
#include <cuda_runtime.h>
#include <cuda_fp16.h>
#include <math.h>
#include <stdint.h>

#define NB   2048
#define DIMT 480
#define HID  1024
#define ZD   256
#define T0   8256
#define KP0  8256
#define T1   2080
#define KP1  2112
#define T2   528
#define KP2  640
#define KCP  11008
#define S1   8256
#define S2   10368

typedef __half h16;

// ---------------- scratch pools ----------------
constexpr long NBKC = (long)NB * KCP;
constexpr long HKC  = (long)HID * KCP;
constexpr long HH   = (long)HID * HID;
constexpr long ZH   = (long)ZD * HID;
constexpr long NH   = (long)NB * HID;
constexpr long NZ   = (long)NB * ZD;

constexpr long B_PC   = 0;
constexpr long B_WTHI = B_PC   + NBKC;
constexpr long B_WPHI = B_WTHI + HKC;
constexpr long B_W1THI= B_WPHI + HKC;
constexpr long B_W1TLO= B_W1THI + HH;
constexpr long B_W1HI = B_W1TLO + HH;
constexpr long B_W1LO = B_W1HI + HH;
constexpr long B_W2THI= B_W1LO + HH;
constexpr long B_W2TLO= B_W2THI + ZH;
constexpr long B_W2HI = B_W2TLO + ZH;
constexpr long B_W2LO = B_W2HI + ZH;
constexpr long B_EH   = B_W2LO + ZH;
constexpr long B_H1H  = B_EH   + NH;
constexpr long B_DA2H = B_H1H  + NH;
constexpr long B_DA1H = B_DA2H + NZ;
constexpr long B_DEH  = B_DA1H + NH;
constexpr long B_TOT  = B_DEH  + NH;

constexpr long F_DPC  = 0;
constexpr long F_A1   = F_DPC + NBKC;
constexpr long F_XH1  = F_A1  + NH;
constexpr long F_A2   = F_XH1 + NH;
constexpr long F_DH1  = F_A2  + NZ;
constexpr long F_RS1  = F_DH1 + NH;
constexpr long F_TOT  = F_RS1 + NB;

__device__ h16      g_hbuf[B_TOT];
__device__ float    g_fbuf[F_TOT];
__device__ uint32_t g_uv[KCP];
__device__ uint32_t g_uvo[KCP];

// ---------------- helpers ----------------
__device__ __forceinline__ uint32_t smem_u32(const void* p) {
    uint32_t a;
    asm("{ .reg .u64 t; cvta.to.shared.u64 t, %1; cvt.u32.u64 %0, t; }" : "=r"(a) : "l"(p));
    return a;
}
__device__ __forceinline__ void ldsm4(uint32_t* r, uint32_t a) {
    asm volatile("ldmatrix.sync.aligned.m8n8.x4.shared.b16 {%0,%1,%2,%3},[%4];"
                 : "=r"(r[0]), "=r"(r[1]), "=r"(r[2]), "=r"(r[3]) : "r"(a));
}
__device__ __forceinline__ void mma_f16(float* d, const uint32_t* a, const uint32_t* b) {
    asm volatile("mma.sync.aligned.m16n8k16.row.col.f32.f16.f16.f32 "
                 "{%0,%1,%2,%3},{%4,%5,%6,%7},{%8,%9},{%0,%1,%2,%3};"
                 : "+f"(d[0]), "+f"(d[1]), "+f"(d[2]), "+f"(d[3])
                 : "r"(a[0]), "r"(a[1]), "r"(a[2]), "r"(a[3]), "r"(b[0]), "r"(b[1]));
}
#define CPA(dst, src) asm volatile("cp.async.cg.shared.global [%0], [%1], 16;" :: "r"(dst), "l"(src) : "memory")
#define CPCOMMIT()    asm volatile("cp.async.commit_group;" ::: "memory")
#define CPWAIT0()     asm volatile("cp.async.wait_group 0;" ::: "memory")

__device__ __forceinline__ void splith(float v, h16& h, h16& l) {
    h = __float2half(v);
    l = __float2half((v - __half2float(h)) * 2048.f);
}

// ---------------- pair LUTs ----------------
__global__ void uv_init() {
    int p = blockIdx.x * 256 + threadIdx.x;
    if (p >= KCP) return;
    int n, lp, T, nm, xoff;
    if (p < S1)      { n = 128; lp = p;      T = T0; nm = 1; xoff = 0; }
    else if (p < S2) { n = 64;  lp = p - S1; T = T1; nm = 3; xoff = 128; }
    else             { n = 32;  lp = p - S2; T = T2; nm = 5; xoff = 320; }
    if (lp >= T) { g_uv[p] = 0u; g_uvo[p] = 0xFFFFFFFFu; return; }
    float tn = 2.f * n + 1.f;
    int u = (int)((tn - sqrtf(tn * tn - 8.f * lp)) * 0.5f);
    if (u < 0) u = 0; if (u > n - 1) u = n - 1;
    while (u > 0 && u * n - u * (u - 1) / 2 > lp) u--;
    while (u < n - 1 && (u + 1) * n - (u + 1) * u / 2 <= lp) u++;
    int v = u + (lp - (u * n - u * (u - 1) / 2));
    g_uv[p]  = ((uint32_t)u << 16) | (uint32_t)v;
    g_uvo[p] = ((uint32_t)(xoff + u * nm) << 16) | (uint32_t)(xoff + v * nm);
}

// ---------------- fp16 NT GEMM: BK=128, 2-stage, 512 threads ----------------
#define TILEH 32768
#define STGH  (3 * TILEH)
#define GSMEM (2 * STGH + 1024)

template<bool LO>
__global__ __launch_bounds__(512, 1) void h_gemm_nt(
    const h16* __restrict__ A, const h16* __restrict__ Bhi, const h16* __restrict__ Blo,
    float* __restrict__ C, h16* __restrict__ Ch,
    int K, long ldc, float alpha, const float* __restrict__ bias)
{
    extern __shared__ char smem[];
    const uint32_t st0 = (smem_u32(smem) + 1023) & ~1023u;
    const int tid = threadIdx.x, wid = tid >> 5, lane = tid & 31;
    const int wm = wid >> 2, wn = wid & 3;
    const long bm = (long)blockIdx.y * 128, bn = (long)blockIdx.x * 128;

    constexpr int NCH = LO ? 12 : 8;
    const h16* gp[NCH];
    uint32_t so[NCH];
    #pragma unroll
    for (int t = 0; t < NCH; t++) {
        int q = tid + (t & 3) * 512;
        int r = q >> 4, c = q & 15;
        int tile = t >> 2;
        const h16* base = (tile == 0) ? A : (tile == 1) ? Bhi : Blo;
        long row = (tile == 0 ? bm : bn) + r;
        gp[t] = base + row * K + c * 8;
        so[t] = st0 + tile * TILEH + ((r * 256 + c * 16) ^ ((r & 7) << 4));
    }
    const int nk = K >> 7;

    #pragma unroll
    for (int t = 0; t < NCH; t++) CPA(so[t], gp[t]);
    CPCOMMIT();

    float ac1[2][4][4], ac2[2][4][4];
    #pragma unroll
    for (int a = 0; a < 2; a++)
        #pragma unroll
        for (int b = 0; b < 4; b++)
            #pragma unroll
            for (int c = 0; c < 4; c++) { ac1[a][b][c] = 0.f; if (LO) ac2[a][b][c] = 0.f; }

    const int lr = lane & 15, lc = lane >> 4;
    const uint32_t xa = (lr & 7) << 4;
    const uint32_t arow = (wm * 32 + lr) * 256 + lc * 16;
    const uint32_t brow = (wn * 32 + lr) * 256 + lc * 16;

    for (int i = 0; i < nk; i++) {
        CPWAIT0();
        __syncthreads();
        if (i + 1 < nk) {
            const uint32_t sst = ((i + 1) & 1) * STGH;
            #pragma unroll
            for (int t = 0; t < NCH; t++) CPA(so[t] + sst, gp[t] + (long)(i + 1) * 128);
            CPCOMMIT();
        }

        const uint32_t sa = st0 + (i & 1) * STGH;
        #pragma unroll
        for (int kk = 0; kk < 8; kk++) {
            uint32_t af[2][4], bh[4][2], bl[4][2];
            #pragma unroll
            for (int mi = 0; mi < 2; mi++)
                ldsm4(af[mi], sa + ((arow + mi * 4096 + kk * 32) ^ xa));
            #pragma unroll
            for (int pi = 0; pi < 2; pi++) {
                uint32_t off = (brow + pi * 4096 + kk * 32) ^ xa;
                uint32_t t0[4];
                ldsm4(t0, sa + TILEH + off);
                bh[2 * pi][0] = t0[0]; bh[2 * pi + 1][0] = t0[1];
                bh[2 * pi][1] = t0[2]; bh[2 * pi + 1][1] = t0[3];
                if (LO) {
                    uint32_t t1[4];
                    ldsm4(t1, sa + 2 * TILEH + off);
                    bl[2 * pi][0] = t1[0]; bl[2 * pi + 1][0] = t1[1];
                    bl[2 * pi][1] = t1[2]; bl[2 * pi + 1][1] = t1[3];
                }
            }
            #pragma unroll
            for (int mi = 0; mi < 2; mi++)
                #pragma unroll
                for (int ni = 0; ni < 4; ni++) {
                    mma_f16(ac1[mi][ni], af[mi], bh[ni]);
                    if (LO) mma_f16(ac2[mi][ni], af[mi], bl[ni]);
                }
        }
    }

    const int g = lane >> 2, tg = lane & 3;
    const float inv = 1.f / 2048.f;
    #pragma unroll
    for (int mi = 0; mi < 2; mi++) {
        #pragma unroll
        for (int ni = 0; ni < 4; ni++) {
            long m0 = bm + wm * 32 + mi * 16 + g;
            long n0 = bn + wn * 32 + ni * 8 + tg * 2;
            float v00, v01, v10, v11;
            if (LO) {
                v00 = alpha * (ac1[mi][ni][0] + ac2[mi][ni][0] * inv);
                v01 = alpha * (ac1[mi][ni][1] + ac2[mi][ni][1] * inv);
                v10 = alpha * (ac1[mi][ni][2] + ac2[mi][ni][2] * inv);
                v11 = alpha * (ac1[mi][ni][3] + ac2[mi][ni][3] * inv);
            } else {
                v00 = alpha * ac1[mi][ni][0];
                v01 = alpha * ac1[mi][ni][1];
                v10 = alpha * ac1[mi][ni][2];
                v11 = alpha * ac1[mi][ni][3];
            }
            if (bias) {
                float bb0 = bias[n0], bb1 = bias[n0 + 1];
                v00 += bb0; v01 += bb1; v10 += bb0; v11 += bb1;
            }
            if (C) {
                *(float2*)(C + m0 * ldc + n0) = make_float2(v00, v01);
                *(float2*)(C + (m0 + 8) * ldc + n0) = make_float2(v10, v11);
            }
            if (Ch) {
                *(__half2*)(Ch + m0 * ldc + n0) = __floats2half2_rn(v00, v01);
                *(__half2*)(Ch + (m0 + 8) * ldc + n0) = __floats2half2_rn(v10, v11);
            }
        }
    }
}

// ---------------- merged packing (hi-only outputs) ----------------
__global__ __launch_bounds__(256) void pack_both(
    const float* __restrict__ w0, const float* __restrict__ w1, const float* __restrict__ w2,
    h16* __restrict__ thi, h16* __restrict__ phi,
    float sc0, float sc1, float sc2)
{
    __shared__ float sv[32][33];
    int bx = blockIdx.x;
    const float* w; int n, T; long kbase; float s;
    int pb;
    if (bx < 258)      { w = w0; n = 128; T = T0; kbase = 0;  s = sc0; pb = bx * 32; }
    else if (bx < 324) { w = w1; n = 64;  T = T1; kbase = S1; s = sc1; pb = (bx - 258) * 32; }
    else               { w = w2; n = 32;  T = T2; kbase = S2; s = sc2; pb = (bx - 324) * 32; }
    int hb = blockIdx.y * 32;
    int tx = threadIdx.x & 31, ty = threadIdx.x >> 5;
    #pragma unroll
    for (int i = 0; i < 32; i += 8) {
        int pp = pb + ty + i;
        float val = 0.f;
        if (pp < T) {
            uint32_t uv = g_uv[kbase + pp];
            int u = uv >> 16, v = uv & 0xffff;
            val = w[((long)u * n + v) * HID + hb + tx];
            if (u != v) val += w[((long)v * n + u) * HID + hb + tx];
            val *= s;
        }
        sv[ty + i][tx] = val;
        phi[(kbase + pp) * (long)HID + hb + tx] = __float2half(val);
    }
    __syncthreads();
    #pragma unroll
    for (int i = 0; i < 32; i += 8) {
        thi[(long)(hb + ty + i) * KCP + kbase + pb + tx] = __float2half(sv[tx][ty + i]);
    }
}

// dense_all
__global__ __launch_bounds__(256) void dense_all(
    const float* __restrict__ W1, const float* __restrict__ W2,
    h16* __restrict__ W1Thi, h16* __restrict__ W1Tlo,
    h16* __restrict__ W2Thi, h16* __restrict__ W2Tlo,
    h16* __restrict__ W1hi, h16* __restrict__ W1lo,
    h16* __restrict__ W2hi, h16* __restrict__ W2lo)
{
    __shared__ float t[32][33];
    long lin = blockIdx.x;
    if (lin < 1024 + 256) {
        const float* src; h16 *dhi, *dlo; int C; long ldd; int gx, gy;
        if (lin < 1024) { src = W1; dhi = W1Thi; dlo = W1Tlo; C = HID; ldd = HID; gx = (int)(lin % 32); gy = (int)(lin / 32); }
        else { long l = lin - 1024; src = W2; dhi = W2Thi; dlo = W2Tlo; C = ZD; ldd = HID; gx = (int)(l % 8); gy = (int)(l / 8); }
        int bx = gx * 32, by = gy * 32;
        int tx = threadIdx.x & 31, ty = threadIdx.x >> 5;
        #pragma unroll
        for (int i = 0; i < 32; i += 8)
            t[ty + i][tx] = src[(long)(by + ty + i) * C + bx + tx];
        __syncthreads();
        #pragma unroll
        for (int i = 0; i < 32; i += 8) {
            h16 h, l; splith(t[tx][ty + i], h, l);
            long o = (long)(bx + ty + i) * ldd + by + tx;
            dhi[o] = h; dlo[o] = l;
        }
    } else if (lin < 1024 + 256 + 4096) {
        long i = (lin - 1280) * 256 + threadIdx.x;
        if (i < HH) { h16 h, l; splith(W1[i], h, l); W1hi[i] = h; W1lo[i] = l; }
    } else {
        long i = (lin - 5376) * 256 + threadIdx.x;
        if (i < ZH) { h16 h, l; splith(W2[i], h, l); W2hi[i] = h; W2lo[i] = l; }
    }
}

// ---------------- build_Pp v4: vectorized region 0 ----------------
__global__ __launch_bounds__(256) void build_Pp_v4(const float* __restrict__ t, h16* __restrict__ Ph)
{
    __shared__ float xs[DIMT];
    int b = blockIdx.x, tid = threadIdx.x;
    if (tid < DIMT) xs[tid] = t[(long)b * DIMT + tid];
    if (tid + 256 < DIMT) xs[tid + 256] = t[(long)b * DIMT + tid + 256];
    __syncthreads();
    h16* out = Ph + (long)b * KCP;
    for (int p = tid * 2; p < KP0; p += 512) {
        uint2 oo = *(const uint2*)(g_uvo + p);
        float v0 = xs[oo.x >> 16] * xs[oo.x & 0xffff];
        float v1 = xs[oo.y >> 16] * xs[oo.y & 0xffff];
        *(__half2*)(out + p) = __floats2half2_rn(v0, v1);
    }
    for (int p = S1 + tid; p < S1 + KP1; p += 256) {
        uint32_t o = g_uvo[p];
        float val = 0.f;
        if (o != 0xFFFFFFFFu) {
            int uo = o >> 16, vo = o & 0xffff;
            #pragma unroll
            for (int m = 0; m < 3; m++) val += xs[uo + m] * xs[vo + m];
        }
        out[p] = __float2half(val);
    }
    for (int p = S2 + tid; p < S2 + KP2; p += 256) {
        uint32_t o = g_uvo[p];
        float val = 0.f;
        if (o != 0xFFFFFFFFu) {
            int uo = o >> 16, vo = o & 0xffff;
            #pragma unroll
            for (int m = 0; m < 5; m++) val += xs[uo + m] * xs[vo + m];
        }
        out[p] = __float2half(val);
    }
}

// ---------------- block reduce ----------------
__device__ __forceinline__ float blockReduceSum(float val) {
    __shared__ float sh[8];
    int lane = threadIdx.x & 31, w = threadIdx.x >> 5;
    #pragma unroll
    for (int o = 16; o > 0; o >>= 1) val += __shfl_down_sync(0xffffffffu, val, o);
    __syncthreads();
    if (lane == 0) sh[w] = val;
    __syncthreads();
    float r = 0.f;
    if (threadIdx.x == 0) {
        int nw = blockDim.x >> 5;
        for (int i = 0; i < nw; i++) r += sh[i];
    }
    return r;
}

// ---------------- LayerNorm + SiLU forward (layer 1) ----------------
__global__ __launch_bounds__(256) void ln_silu_fwd4(
    const float* __restrict__ a, const float* __restrict__ gam, const float* __restrict__ bet,
    float* __restrict__ xh, float* __restrict__ rstd, h16* __restrict__ hh)
{
    const int D = 1024;
    int b = blockIdx.x, tid = threadIdx.x;
    const float* row = a + (long)b * D;
    float v[4];
    float s = 0.f;
    #pragma unroll
    for (int i = 0; i < 4; i++) { v[i] = row[tid + (i << 8)]; s += v[i]; }
    s = blockReduceSum(s);
    __shared__ float bc;
    if (tid == 0) bc = s * (1.f / D);
    __syncthreads();
    float mu = bc;
    float q = 0.f;
    #pragma unroll
    for (int i = 0; i < 4; i++) { float d = v[i] - mu; q += d * d; }
    q = blockReduceSum(q);
    if (tid == 0) { float r = rsqrtf(q * (1.f / D) + 1e-6f); bc = r; rstd[b] = r; }
    __syncthreads();
    float r = bc;
    #pragma unroll
    for (int i = 0; i < 4; i++) {
        int c = tid + (i << 8);
        float x = (v[i] - mu) * r;
        xh[(long)b * D + c] = x;
        float z = x * gam[c] + bet[c];
        float sg = 1.f / (1.f + expf(-z));
        hh[(long)b * D + c] = __float2half(z * sg);
    }
}

// ---------------- fused LN2 fwd + bwd ----------------
__global__ __launch_bounds__(256) void ln2_fused(
    const float* __restrict__ a, const float* __restrict__ gam, const float* __restrict__ bet,
    float* __restrict__ xout, h16* __restrict__ dah)
{
    const int D = 256;
    int b = blockIdx.x, tid = threadIdx.x;
    float v = a[(long)b * D + tid];
    float s = blockReduceSum(v);
    __shared__ float bc;
    if (tid == 0) bc = s * (1.f / D);
    __syncthreads();
    float mu = bc;
    float d = v - mu;
    float q = blockReduceSum(d * d);
    if (tid == 0) bc = rsqrtf(q * (1.f / D) + 1e-6f);
    __syncthreads();
    float r = bc;
    float x = (v - mu) * r;
    float z = x * gam[tid] + bet[tid];
    float sg = 1.f / (1.f + expf(-z));
    xout[(long)b * D + tid] = z * sg;
    float ds = sg * (1.f + z * (1.f - sg));
    float dx = ds * gam[tid];
    float t1 = blockReduceSum(dx);
    __shared__ float m1s, m2s;
    if (tid == 0) m1s = t1 * (1.f / D);
    float t2 = blockReduceSum(dx * x);
    if (tid == 0) m2s = t2 * (1.f / D);
    __syncthreads();
    dah[(long)b * D + tid] = __float2half(r * (dx - m1s - x * m2s));
}

// ---------------- (SiLU + LN) backward (layer 1) ----------------
__global__ __launch_bounds__(256) void ln_silu_bwd4(
    const float* __restrict__ dh, const float* __restrict__ xhv_, const float* __restrict__ rstd,
    const float* __restrict__ gam, const float* __restrict__ bet, h16* __restrict__ dah)
{
    const int D = 1024;
    int b = blockIdx.x, tid = threadIdx.x;
    float xh[4], dxh[4];
    float s1 = 0.f, s2 = 0.f;
    #pragma unroll
    for (int i = 0; i < 4; i++) {
        int c = tid + (i << 8);
        float x = xhv_[(long)b * D + c];
        float z = x * gam[c] + bet[c];
        float sg = 1.f / (1.f + expf(-z));
        float ds = sg * (1.f + z * (1.f - sg));
        float dx = dh[(long)b * D + c] * ds * gam[c];
        xh[i] = x; dxh[i] = dx;
        s1 += dx; s2 += dx * x;
    }
    __shared__ float m1s, m2s;
    float t1 = blockReduceSum(s1);
    if (tid == 0) m1s = t1 * (1.f / D);
    float t2 = blockReduceSum(s2);
    if (tid == 0) m2s = t2 * (1.f / D);
    __syncthreads();
    float m1 = m1s, m2 = m2s, r = rstd[b];
    #pragma unroll
    for (int i = 0; i < 4; i++) {
        int c = tid + (i << 8);
        dah[(long)b * D + c] = __float2half(r * (dxh[i] - m1 - xh[i] * m2));
    }
}

// ---------------- merged packed quadratic-form gradients -> y ----------------
__global__ __launch_bounds__(192) void grad_all(const float* __restrict__ dPc,
                                                const float* __restrict__ t, float* __restrict__ y)
{
    extern __shared__ float Ts[];
    int tid = threadIdx.x;
    if (blockIdx.x < 2048) {
        int b = blockIdx.x;
        float* xs = Ts + 128 * 129;
        if (tid < 128) xs[tid] = t[(long)b * DIMT + tid];
        const float* P = dPc + (long)b * KCP;
        for (int i = tid * 4; i < T0; i += 768) {
            float4 pv = *(const float4*)(P + i);
            uint4  ov = *(const uint4*)(g_uv + i);
            float  vv[4] = {pv.x, pv.y, pv.z, pv.w};
            uint32_t oo[4] = {ov.x, ov.y, ov.z, ov.w};
            #pragma unroll
            for (int k = 0; k < 4; k++) {
                int u = oo[k] >> 16, v = oo[k] & 0xffff;
                Ts[u * 129 + v] = vv[k];
                Ts[v * 129 + u] = (u == v) ? 2.f * vv[k] : vv[k];
            }
        }
        __syncthreads();
        if (tid < 128) {
            float s = 0.f;
            #pragma unroll 8
            for (int v = 0; v < 128; v++) s += Ts[tid * 129 + v] * xs[v];
            y[(long)b * DIMT + tid] = s;
        }
    } else if (blockIdx.x < 4096) {
        int b = blockIdx.x - 2048;
        float* xs = Ts + 64 * 65;
        xs[tid] = t[(long)b * DIMT + 128 + tid];
        const float* P = dPc + (long)b * KCP + S1;
        for (int i = tid * 4; i < T1; i += 768) {
            float4 pv = *(const float4*)(P + i);
            uint4  ov = *(const uint4*)(g_uv + S1 + i);
            float  vv[4] = {pv.x, pv.y, pv.z, pv.w};
            uint32_t oo[4] = {ov.x, ov.y, ov.z, ov.w};
            #pragma unroll
            for (int k = 0; k < 4; k++) {
                int u = oo[k] >> 16, v = oo[k] & 0xffff;
                Ts[u * 65 + v] = vv[k];
                Ts[v * 65 + u] = (u == v) ? 2.f * vv[k] : vv[k];
            }
        }
        __syncthreads();
        int u = tid / 3, m = tid - u * 3;
        float s = 0.f;
        #pragma unroll 8
        for (int v = 0; v < 64; v++) s += Ts[u * 65 + v] * xs[v * 3 + m];
        y[(long)b * DIMT + 128 + tid] = s;
    } else {
        int b = blockIdx.x - 4096;
        float* xs = Ts + 32 * 33;
        if (tid < 160) xs[tid] = t[(long)b * DIMT + 320 + tid];
        const float* P = dPc + (long)b * KCP + S2;
        for (int i = tid * 4; i < T2; i += 768) {
            float4 pv = *(const float4*)(P + i);
            uint4  ov = *(const uint4*)(g_uv + S2 + i);
            float  vv[4] = {pv.x, pv.y, pv.z, pv.w};
            uint32_t oo[4] = {ov.x, ov.y, ov.z, ov.w};
            #pragma unroll
            for (int k = 0; k < 4; k++) {
                int u = oo[k] >> 16, v = oo[k] & 0xffff;
                Ts[u * 33 + v] = vv[k];
                Ts[v * 33 + u] = (u == v) ? 2.f * vv[k] : vv[k];
            }
        }
        __syncthreads();
        if (tid < 160) {
            int u = tid / 5, m = tid - u * 5;
            float s = 0.f;
            #pragma unroll 8
            for (int v = 0; v < 32; v++) s += Ts[u * 33 + v] * xs[v * 5 + m];
            y[(long)b * DIMT + 320 + tid] = s;
        }
    }
}

// ---------------- launch ----------------
extern "C" void kernel_launch(void* const* d_in, const int* in_sizes, int n_in,
                              void* d_out, int out_size)
{
    const float* tin = (const float*)d_in[0];
    const float* w0  = (const float*)d_in[1];
    const float* w1  = (const float*)d_in[2];
    const float* w2  = (const float*)d_in[3];
    const float* W1  = (const float*)d_in[4];
    const float* b1  = (const float*)d_in[5];
    const float* g1  = (const float*)d_in[6];
    const float* be1 = (const float*)d_in[7];
    const float* W2  = (const float*)d_in[8];
    const float* b2  = (const float*)d_in[9];
    const float* g2  = (const float*)d_in[10];
    const float* be2 = (const float*)d_in[11];

    float* out  = (float*)d_out;
    float* xout = out;
    float* yout = out + (long)NB * ZD;

    h16* hb = nullptr; float* fb = nullptr;
    cudaGetSymbolAddress((void**)&hb, g_hbuf);
    cudaGetSymbolAddress((void**)&fb, g_fbuf);

    h16 *PC   = hb + B_PC;
    h16 *WThi = hb + B_WTHI;
    h16 *WPhi = hb + B_WPHI;
    h16 *W1Thi= hb + B_W1THI,*W1Tlo= hb + B_W1TLO;
    h16 *W1hi = hb + B_W1HI, *W1lo = hb + B_W1LO;
    h16 *W2Thi= hb + B_W2THI,*W2Tlo= hb + B_W2TLO;
    h16 *W2hi = hb + B_W2HI, *W2lo = hb + B_W2LO;
    h16 *eh   = hb + B_EH;
    h16 *h1h  = hb + B_H1H;
    h16 *da2h = hb + B_DA2H;
    h16 *da1h = hb + B_DA1H;
    h16 *deh  = hb + B_DEH;

    float *dPC = fb + F_DPC, *a1 = fb + F_A1, *xh1 = fb + F_XH1;
    float *a2  = fb + F_A2,  *dh1 = fb + F_DH1, *rs1 = fb + F_RS1;

    const float s0 = 1.0f / sqrtf(21504.0f);
    const float s1 = s0 / sqrtf(3.0f);
    const float s2 = s0 / sqrtf(5.0f);

    // static side-stream + fork/join events (host-side objects; created once,
    // on the first -- uncaptured -- correctness call)
    static cudaStream_t s2s = nullptr;
    static cudaEvent_t evFork = nullptr, evPack = nullptr, evDense = nullptr;
    if (!s2s) {
        cudaStreamCreateWithFlags(&s2s, cudaStreamNonBlocking);
        cudaEventCreateWithFlags(&evFork,  cudaEventDisableTiming);
        cudaEventCreateWithFlags(&evPack,  cudaEventDisableTiming);
        cudaEventCreateWithFlags(&evDense, cudaEventDisableTiming);
    }

    cudaFuncSetAttribute(h_gemm_nt<true>,  cudaFuncAttributeMaxDynamicSharedMemorySize, GSMEM);
    cudaFuncSetAttribute(h_gemm_nt<false>, cudaFuncAttributeMaxDynamicSharedMemorySize, GSMEM);
    cudaFuncSetAttribute(grad_all, cudaFuncAttributeMaxDynamicSharedMemorySize, 128 * 129 * 4 + 768);

    // ---- prep: fork ----
    uv_init<<<(KCP + 255) / 256, 256>>>();
    cudaEventRecord(evFork, 0);
    cudaStreamWaitEvent(s2s, evFork, 0);
    // side stream: weight packing (needed before e-GEMM) then dense weights (needed before a1-GEMM)
    pack_both<<<dim3(344, HID / 32), 256, 0, s2s>>>(w0, w1, w2, WThi, WPhi, s0, s1, s2);
    cudaEventRecord(evPack, s2s);
    dense_all<<<6400, 256, 0, s2s>>>(W1, W2, W1Thi, W1Tlo, W2Thi, W2Tlo, W1hi, W1lo, W2hi, W2lo);
    cudaEventRecord(evDense, s2s);
    // main stream (concurrent): activation pair products
    build_Pp_v4<<<NB, 256>>>(tin, PC);
    cudaStreamWaitEvent(0, evPack, 0);

    // ---- forward ----
    h_gemm_nt<false><<<dim3(HID / 128, NB / 128), 512, GSMEM>>>(
        PC, WThi, WThi, nullptr, eh, KCP, HID, 1.f, nullptr);
    cudaStreamWaitEvent(0, evDense, 0);
    h_gemm_nt<true><<<dim3(HID / 128, NB / 128), 512, GSMEM>>>(
        eh, W1Thi, W1Tlo, a1, nullptr, HID, HID, 1.f, b1);
    ln_silu_fwd4<<<NB, 256>>>(a1, g1, be1, xh1, rs1, h1h);
    h_gemm_nt<true><<<dim3(ZD / 128, NB / 128), 512, GSMEM>>>(
        h1h, W2Thi, W2Tlo, a2, nullptr, HID, ZD, 1.f, b2);
    ln2_fused<<<NB, 256>>>(a2, g2, be2, xout, da2h);

    // ---- backward ----
    h_gemm_nt<true><<<dim3(HID / 128, NB / 128), 512, GSMEM>>>(
        da2h, W2hi, W2lo, dh1, nullptr, ZD, HID, 1.f, nullptr);
    ln_silu_bwd4<<<NB, 256>>>(dh1, xh1, rs1, g1, be1, da1h);
    h_gemm_nt<true><<<dim3(HID / 128, NB / 128), 512, GSMEM>>>(
        da1h, W1hi, W1lo, nullptr, deh, HID, HID, 1.f, nullptr);
    h_gemm_nt<false><<<dim3(KCP / 128, NB / 128), 512, GSMEM>>>(
        deh, WPhi, WPhi, dPC, nullptr, HID, KCP, 1.f, nullptr);

    grad_all<<<6144, 192, 128 * 129 * 4 + 768>>>(dPC, tin, yout);
}

// round 16
// speedup vs baseline: 10.5276x; 1.0325x over previous
#include <cuda_runtime.h>
#include <cuda_fp16.h>
#include <math.h>
#include <stdint.h>

#define NB   2048
#define DIMT 480
#define HID  1024
#define ZD   256
#define T0   8256
#define KP0  8256
#define T1   2080
#define KP1  2112
#define T2   528
#define KP2  640
#define KCP  11008
#define S1   8256
#define S2   10368

typedef __half h16;

// ---------------- scratch pools ----------------
constexpr long NBKC = (long)NB * KCP;
constexpr long HKC  = (long)HID * KCP;
constexpr long HH   = (long)HID * HID;
constexpr long ZH   = (long)ZD * HID;
constexpr long NH   = (long)NB * HID;
constexpr long NZ   = (long)NB * ZD;

constexpr long B_PC   = 0;
constexpr long B_WTHI = B_PC   + NBKC;
constexpr long B_WPHI = B_WTHI + HKC;
constexpr long B_W1THI= B_WPHI + HKC;
constexpr long B_W1TLO= B_W1THI + HH;
constexpr long B_W1HI = B_W1TLO + HH;
constexpr long B_W1LO = B_W1HI + HH;
constexpr long B_W2THI= B_W1LO + HH;
constexpr long B_W2TLO= B_W2THI + ZH;
constexpr long B_W2HI = B_W2TLO + ZH;
constexpr long B_W2LO = B_W2HI + ZH;
constexpr long B_EH   = B_W2LO + ZH;
constexpr long B_H1H  = B_EH   + NH;
constexpr long B_DA2H = B_H1H  + NH;
constexpr long B_DA1H = B_DA2H + NZ;
constexpr long B_DEH  = B_DA1H + NH;
constexpr long B_TOT  = B_DEH  + NH;

constexpr long F_DPC  = 0;
constexpr long F_A1   = F_DPC + NBKC;
constexpr long F_XH1  = F_A1  + NH;
constexpr long F_A2   = F_XH1 + NH;          // 4 x NZ (split-K chunks)
constexpr long F_DH1  = F_A2  + 4 * NZ;
constexpr long F_RS1  = F_DH1 + NH;
constexpr long F_TOT  = F_RS1 + NB;

__device__ h16      g_hbuf[B_TOT];
__device__ float    g_fbuf[F_TOT];
__device__ uint32_t g_uv[KCP];
__device__ uint32_t g_uvo[KCP];

// ---------------- helpers ----------------
__device__ __forceinline__ uint32_t smem_u32(const void* p) {
    uint32_t a;
    asm("{ .reg .u64 t; cvta.to.shared.u64 t, %1; cvt.u32.u64 %0, t; }" : "=r"(a) : "l"(p));
    return a;
}
__device__ __forceinline__ void ldsm4(uint32_t* r, uint32_t a) {
    asm volatile("ldmatrix.sync.aligned.m8n8.x4.shared.b16 {%0,%1,%2,%3},[%4];"
                 : "=r"(r[0]), "=r"(r[1]), "=r"(r[2]), "=r"(r[3]) : "r"(a));
}
__device__ __forceinline__ void mma_f16(float* d, const uint32_t* a, const uint32_t* b) {
    asm volatile("mma.sync.aligned.m16n8k16.row.col.f32.f16.f16.f32 "
                 "{%0,%1,%2,%3},{%4,%5,%6,%7},{%8,%9},{%0,%1,%2,%3};"
                 : "+f"(d[0]), "+f"(d[1]), "+f"(d[2]), "+f"(d[3])
                 : "r"(a[0]), "r"(a[1]), "r"(a[2]), "r"(a[3]), "r"(b[0]), "r"(b[1]));
}
#define CPA(dst, src) asm volatile("cp.async.cg.shared.global [%0], [%1], 16;" :: "r"(dst), "l"(src) : "memory")
#define CPCOMMIT()    asm volatile("cp.async.commit_group;" ::: "memory")
#define CPWAIT0()     asm volatile("cp.async.wait_group 0;" ::: "memory")

__device__ __forceinline__ void splith(float v, h16& h, h16& l) {
    h = __float2half(v);
    l = __float2half((v - __half2float(h)) * 2048.f);
}

// ---------------- pair LUTs ----------------
__global__ void uv_init() {
    int p = blockIdx.x * 256 + threadIdx.x;
    if (p >= KCP) return;
    int n, lp, T, nm, xoff;
    if (p < S1)      { n = 128; lp = p;      T = T0; nm = 1; xoff = 0; }
    else if (p < S2) { n = 64;  lp = p - S1; T = T1; nm = 3; xoff = 128; }
    else             { n = 32;  lp = p - S2; T = T2; nm = 5; xoff = 320; }
    if (lp >= T) { g_uv[p] = 0u; g_uvo[p] = 0xFFFFFFFFu; return; }
    float tn = 2.f * n + 1.f;
    int u = (int)((tn - sqrtf(tn * tn - 8.f * lp)) * 0.5f);
    if (u < 0) u = 0; if (u > n - 1) u = n - 1;
    while (u > 0 && u * n - u * (u - 1) / 2 > lp) u--;
    while (u < n - 1 && (u + 1) * n - (u + 1) * u / 2 <= lp) u++;
    int v = u + (lp - (u * n - u * (u - 1) / 2));
    g_uv[p]  = ((uint32_t)u << 16) | (uint32_t)v;
    g_uvo[p] = ((uint32_t)(xoff + u * nm) << 16) | (uint32_t)(xoff + v * nm);
}

// ---------------- fp16 NT GEMM: BK=128, 2-stage, 512 threads ----------------
// K = loop extent (per z-slice), ld = row stride of A/B, csplit = C offset per blockIdx.z
#define TILEH 32768
#define STGH  (3 * TILEH)
#define GSMEM (2 * STGH + 1024)

template<bool LO>
__global__ __launch_bounds__(512, 1) void h_gemm_nt(
    const h16* __restrict__ A, const h16* __restrict__ Bhi, const h16* __restrict__ Blo,
    float* __restrict__ C, h16* __restrict__ Ch,
    int K, long ld, long ldc, long csplit, float alpha, const float* __restrict__ bias)
{
    extern __shared__ char smem[];
    const uint32_t st0 = (smem_u32(smem) + 1023) & ~1023u;
    const int tid = threadIdx.x, wid = tid >> 5, lane = tid & 31;
    const int wm = wid >> 2, wn = wid & 3;
    const long bm = (long)blockIdx.y * 128, bn = (long)blockIdx.x * 128;
    const long kz = (long)blockIdx.z * K;

    const h16* Ab  = A   + kz;
    const h16* Bb  = Bhi + kz;
    const h16* Blb = Blo + kz;
    if (C) C += (long)blockIdx.z * csplit;

    constexpr int NCH = LO ? 12 : 8;
    const h16* gp[NCH];
    uint32_t so[NCH];
    #pragma unroll
    for (int t = 0; t < NCH; t++) {
        int q = tid + (t & 3) * 512;
        int r = q >> 4, c = q & 15;
        int tile = t >> 2;
        const h16* base = (tile == 0) ? Ab : (tile == 1) ? Bb : Blb;
        long row = (tile == 0 ? bm : bn) + r;
        gp[t] = base + row * ld + c * 8;
        so[t] = st0 + tile * TILEH + ((r * 256 + c * 16) ^ ((r & 7) << 4));
    }
    const int nk = K >> 7;

    #pragma unroll
    for (int t = 0; t < NCH; t++) CPA(so[t], gp[t]);
    CPCOMMIT();

    float ac1[2][4][4], ac2[2][4][4];
    #pragma unroll
    for (int a = 0; a < 2; a++)
        #pragma unroll
        for (int b = 0; b < 4; b++)
            #pragma unroll
            for (int c = 0; c < 4; c++) { ac1[a][b][c] = 0.f; if (LO) ac2[a][b][c] = 0.f; }

    const int lr = lane & 15, lc = lane >> 4;
    const uint32_t xa = (lr & 7) << 4;
    const uint32_t arow = (wm * 32 + lr) * 256 + lc * 16;
    const uint32_t brow = (wn * 32 + lr) * 256 + lc * 16;

    for (int i = 0; i < nk; i++) {
        CPWAIT0();
        __syncthreads();
        if (i + 1 < nk) {
            const uint32_t sst = ((i + 1) & 1) * STGH;
            #pragma unroll
            for (int t = 0; t < NCH; t++) CPA(so[t] + sst, gp[t] + (long)(i + 1) * 128);
            CPCOMMIT();
        }

        const uint32_t sa = st0 + (i & 1) * STGH;
        #pragma unroll
        for (int kk = 0; kk < 8; kk++) {
            uint32_t af[2][4], bh[4][2], bl[4][2];
            #pragma unroll
            for (int mi = 0; mi < 2; mi++)
                ldsm4(af[mi], sa + ((arow + mi * 4096 + kk * 32) ^ xa));
            #pragma unroll
            for (int pi = 0; pi < 2; pi++) {
                uint32_t off = (brow + pi * 4096 + kk * 32) ^ xa;
                uint32_t t0[4];
                ldsm4(t0, sa + TILEH + off);
                bh[2 * pi][0] = t0[0]; bh[2 * pi + 1][0] = t0[1];
                bh[2 * pi][1] = t0[2]; bh[2 * pi + 1][1] = t0[3];
                if (LO) {
                    uint32_t t1[4];
                    ldsm4(t1, sa + 2 * TILEH + off);
                    bl[2 * pi][0] = t1[0]; bl[2 * pi + 1][0] = t1[1];
                    bl[2 * pi][1] = t1[2]; bl[2 * pi + 1][1] = t1[3];
                }
            }
            #pragma unroll
            for (int mi = 0; mi < 2; mi++)
                #pragma unroll
                for (int ni = 0; ni < 4; ni++) {
                    mma_f16(ac1[mi][ni], af[mi], bh[ni]);
                    if (LO) mma_f16(ac2[mi][ni], af[mi], bl[ni]);
                }
        }
    }

    const int g = lane >> 2, tg = lane & 3;
    const float inv = 1.f / 2048.f;
    #pragma unroll
    for (int mi = 0; mi < 2; mi++) {
        #pragma unroll
        for (int ni = 0; ni < 4; ni++) {
            long m0 = bm + wm * 32 + mi * 16 + g;
            long n0 = bn + wn * 32 + ni * 8 + tg * 2;
            float v00, v01, v10, v11;
            if (LO) {
                v00 = alpha * (ac1[mi][ni][0] + ac2[mi][ni][0] * inv);
                v01 = alpha * (ac1[mi][ni][1] + ac2[mi][ni][1] * inv);
                v10 = alpha * (ac1[mi][ni][2] + ac2[mi][ni][2] * inv);
                v11 = alpha * (ac1[mi][ni][3] + ac2[mi][ni][3] * inv);
            } else {
                v00 = alpha * ac1[mi][ni][0];
                v01 = alpha * ac1[mi][ni][1];
                v10 = alpha * ac1[mi][ni][2];
                v11 = alpha * ac1[mi][ni][3];
            }
            if (bias) {
                float bb0 = bias[n0], bb1 = bias[n0 + 1];
                v00 += bb0; v01 += bb1; v10 += bb0; v11 += bb1;
            }
            if (C) {
                *(float2*)(C + m0 * ldc + n0) = make_float2(v00, v01);
                *(float2*)(C + (m0 + 8) * ldc + n0) = make_float2(v10, v11);
            }
            if (Ch) {
                *(__half2*)(Ch + m0 * ldc + n0) = __floats2half2_rn(v00, v01);
                *(__half2*)(Ch + (m0 + 8) * ldc + n0) = __floats2half2_rn(v10, v11);
            }
        }
    }
}

// ---------------- merged packing (hi-only outputs) ----------------
__global__ __launch_bounds__(256) void pack_both(
    const float* __restrict__ w0, const float* __restrict__ w1, const float* __restrict__ w2,
    h16* __restrict__ thi, h16* __restrict__ phi,
    float sc0, float sc1, float sc2)
{
    __shared__ float sv[32][33];
    int bx = blockIdx.x;
    const float* w; int n, T; long kbase; float s;
    int pb;
    if (bx < 258)      { w = w0; n = 128; T = T0; kbase = 0;  s = sc0; pb = bx * 32; }
    else if (bx < 324) { w = w1; n = 64;  T = T1; kbase = S1; s = sc1; pb = (bx - 258) * 32; }
    else               { w = w2; n = 32;  T = T2; kbase = S2; s = sc2; pb = (bx - 324) * 32; }
    int hb = blockIdx.y * 32;
    int tx = threadIdx.x & 31, ty = threadIdx.x >> 5;
    #pragma unroll
    for (int i = 0; i < 32; i += 8) {
        int pp = pb + ty + i;
        float val = 0.f;
        if (pp < T) {
            uint32_t uv = g_uv[kbase + pp];
            int u = uv >> 16, v = uv & 0xffff;
            val = w[((long)u * n + v) * HID + hb + tx];
            if (u != v) val += w[((long)v * n + u) * HID + hb + tx];
            val *= s;
        }
        sv[ty + i][tx] = val;
        phi[(kbase + pp) * (long)HID + hb + tx] = __float2half(val);
    }
    __syncthreads();
    #pragma unroll
    for (int i = 0; i < 32; i += 8) {
        thi[(long)(hb + ty + i) * KCP + kbase + pb + tx] = __float2half(sv[tx][ty + i]);
    }
}

// dense_all
__global__ __launch_bounds__(256) void dense_all(
    const float* __restrict__ W1, const float* __restrict__ W2,
    h16* __restrict__ W1Thi, h16* __restrict__ W1Tlo,
    h16* __restrict__ W2Thi, h16* __restrict__ W2Tlo,
    h16* __restrict__ W1hi, h16* __restrict__ W1lo,
    h16* __restrict__ W2hi, h16* __restrict__ W2lo)
{
    __shared__ float t[32][33];
    long lin = blockIdx.x;
    if (lin < 1024 + 256) {
        const float* src; h16 *dhi, *dlo; int C; long ldd; int gx, gy;
        if (lin < 1024) { src = W1; dhi = W1Thi; dlo = W1Tlo; C = HID; ldd = HID; gx = (int)(lin % 32); gy = (int)(lin / 32); }
        else { long l = lin - 1024; src = W2; dhi = W2Thi; dlo = W2Tlo; C = ZD; ldd = HID; gx = (int)(l % 8); gy = (int)(l / 8); }
        int bx = gx * 32, by = gy * 32;
        int tx = threadIdx.x & 31, ty = threadIdx.x >> 5;
        #pragma unroll
        for (int i = 0; i < 32; i += 8)
            t[ty + i][tx] = src[(long)(by + ty + i) * C + bx + tx];
        __syncthreads();
        #pragma unroll
        for (int i = 0; i < 32; i += 8) {
            h16 h, l; splith(t[tx][ty + i], h, l);
            long o = (long)(bx + ty + i) * ldd + by + tx;
            dhi[o] = h; dlo[o] = l;
        }
    } else if (lin < 1024 + 256 + 4096) {
        long i = (lin - 1280) * 256 + threadIdx.x;
        if (i < HH) { h16 h, l; splith(W1[i], h, l); W1hi[i] = h; W1lo[i] = l; }
    } else {
        long i = (lin - 5376) * 256 + threadIdx.x;
        if (i < ZH) { h16 h, l; splith(W2[i], h, l); W2hi[i] = h; W2lo[i] = l; }
    }
}

// ---------------- build_Pp v5: 4-wide region 0 ----------------
__global__ __launch_bounds__(256) void build_Pp_v5(const float* __restrict__ t, h16* __restrict__ Ph)
{
    __shared__ float xs[DIMT];
    int b = blockIdx.x, tid = threadIdx.x;
    if (tid < DIMT) xs[tid] = t[(long)b * DIMT + tid];
    if (tid + 256 < DIMT) xs[tid + 256] = t[(long)b * DIMT + tid + 256];
    __syncthreads();
    h16* out = Ph + (long)b * KCP;
    for (int p = tid * 4; p < KP0; p += 1024) {
        uint4 oo = *(const uint4*)(g_uvo + p);
        float v0 = xs[oo.x >> 16] * xs[oo.x & 0xffff];
        float v1 = xs[oo.y >> 16] * xs[oo.y & 0xffff];
        float v2 = xs[oo.z >> 16] * xs[oo.z & 0xffff];
        float v3 = xs[oo.w >> 16] * xs[oo.w & 0xffff];
        __half2 h01 = __floats2half2_rn(v0, v1);
        __half2 h23 = __floats2half2_rn(v2, v3);
        float2 pk;
        pk.x = __uint_as_float(*(uint32_t*)&h01);
        pk.y = __uint_as_float(*(uint32_t*)&h23);
        *(float2*)(out + p) = pk;
    }
    for (int p = S1 + tid; p < S1 + KP1; p += 256) {
        uint32_t o = g_uvo[p];
        float val = 0.f;
        if (o != 0xFFFFFFFFu) {
            int uo = o >> 16, vo = o & 0xffff;
            #pragma unroll
            for (int m = 0; m < 3; m++) val += xs[uo + m] * xs[vo + m];
        }
        out[p] = __float2half(val);
    }
    for (int p = S2 + tid; p < S2 + KP2; p += 256) {
        uint32_t o = g_uvo[p];
        float val = 0.f;
        if (o != 0xFFFFFFFFu) {
            int uo = o >> 16, vo = o & 0xffff;
            #pragma unroll
            for (int m = 0; m < 5; m++) val += xs[uo + m] * xs[vo + m];
        }
        out[p] = __float2half(val);
    }
}

// ---------------- block reduce ----------------
__device__ __forceinline__ float blockReduceSum(float val) {
    __shared__ float sh[8];
    int lane = threadIdx.x & 31, w = threadIdx.x >> 5;
    #pragma unroll
    for (int o = 16; o > 0; o >>= 1) val += __shfl_down_sync(0xffffffffu, val, o);
    __syncthreads();
    if (lane == 0) sh[w] = val;
    __syncthreads();
    float r = 0.f;
    if (threadIdx.x == 0) {
        int nw = blockDim.x >> 5;
        for (int i = 0; i < nw; i++) r += sh[i];
    }
    return r;
}

// ---------------- LayerNorm + SiLU forward (layer 1) ----------------
__global__ __launch_bounds__(256) void ln_silu_fwd4(
    const float* __restrict__ a, const float* __restrict__ gam, const float* __restrict__ bet,
    float* __restrict__ xh, float* __restrict__ rstd, h16* __restrict__ hh)
{
    const int D = 1024;
    int b = blockIdx.x, tid = threadIdx.x;
    const float* row = a + (long)b * D;
    float v[4];
    float s = 0.f;
    #pragma unroll
    for (int i = 0; i < 4; i++) { v[i] = row[tid + (i << 8)]; s += v[i]; }
    s = blockReduceSum(s);
    __shared__ float bc;
    if (tid == 0) bc = s * (1.f / D);
    __syncthreads();
    float mu = bc;
    float q = 0.f;
    #pragma unroll
    for (int i = 0; i < 4; i++) { float d = v[i] - mu; q += d * d; }
    q = blockReduceSum(q);
    if (tid == 0) { float r = rsqrtf(q * (1.f / D) + 1e-6f); bc = r; rstd[b] = r; }
    __syncthreads();
    float r = bc;
    #pragma unroll
    for (int i = 0; i < 4; i++) {
        int c = tid + (i << 8);
        float x = (v[i] - mu) * r;
        xh[(long)b * D + c] = x;
        float z = x * gam[c] + bet[c];
        float sg = 1.f / (1.f + expf(-z));
        hh[(long)b * D + c] = __float2half(z * sg);
    }
}

// ---------------- fused LN2 fwd + bwd; sums 4 split-K chunks + bias ----------------
__global__ __launch_bounds__(256) void ln2_fused(
    const float* __restrict__ a, const float* __restrict__ b2,
    const float* __restrict__ gam, const float* __restrict__ bet,
    float* __restrict__ xout, h16* __restrict__ dah)
{
    const int D = 256;
    int b = blockIdx.x, tid = threadIdx.x;
    long idx = (long)b * D + tid;
    float v = ((a[idx] + a[idx + NZ]) + (a[idx + 2 * NZ] + a[idx + 3 * NZ])) + b2[tid];
    float s = blockReduceSum(v);
    __shared__ float bc;
    if (tid == 0) bc = s * (1.f / D);
    __syncthreads();
    float mu = bc;
    float d = v - mu;
    float q = blockReduceSum(d * d);
    if (tid == 0) bc = rsqrtf(q * (1.f / D) + 1e-6f);
    __syncthreads();
    float r = bc;
    float x = (v - mu) * r;
    float z = x * gam[tid] + bet[tid];
    float sg = 1.f / (1.f + expf(-z));
    xout[idx] = z * sg;
    float ds = sg * (1.f + z * (1.f - sg));
    float dx = ds * gam[tid];
    float t1 = blockReduceSum(dx);
    __shared__ float m1s, m2s;
    if (tid == 0) m1s = t1 * (1.f / D);
    float t2 = blockReduceSum(dx * x);
    if (tid == 0) m2s = t2 * (1.f / D);
    __syncthreads();
    dah[idx] = __float2half(r * (dx - m1s - x * m2s));
}

// ---------------- (SiLU + LN) backward (layer 1) ----------------
__global__ __launch_bounds__(256) void ln_silu_bwd4(
    const float* __restrict__ dh, const float* __restrict__ xhv_, const float* __restrict__ rstd,
    const float* __restrict__ gam, const float* __restrict__ bet, h16* __restrict__ dah)
{
    const int D = 1024;
    int b = blockIdx.x, tid = threadIdx.x;
    float xh[4], dxh[4];
    float s1 = 0.f, s2 = 0.f;
    #pragma unroll
    for (int i = 0; i < 4; i++) {
        int c = tid + (i << 8);
        float x = xhv_[(long)b * D + c];
        float z = x * gam[c] + bet[c];
        float sg = 1.f / (1.f + expf(-z));
        float ds = sg * (1.f + z * (1.f - sg));
        float dx = dh[(long)b * D + c] * ds * gam[c];
        xh[i] = x; dxh[i] = dx;
        s1 += dx; s2 += dx * x;
    }
    __shared__ float m1s, m2s;
    float t1 = blockReduceSum(s1);
    if (tid == 0) m1s = t1 * (1.f / D);
    float t2 = blockReduceSum(s2);
    if (tid == 0) m2s = t2 * (1.f / D);
    __syncthreads();
    float m1 = m1s, m2 = m2s, r = rstd[b];
    #pragma unroll
    for (int i = 0; i < 4; i++) {
        int c = tid + (i << 8);
        dah[(long)b * D + c] = __float2half(r * (dxh[i] - m1 - xh[i] * m2));
    }
}

// ---------------- merged packed quadratic-form gradients -> y ----------------
__global__ __launch_bounds__(192) void grad_all(const float* __restrict__ dPc,
                                                const float* __restrict__ t, float* __restrict__ y)
{
    extern __shared__ float Ts[];
    int tid = threadIdx.x;
    if (blockIdx.x < 2048) {
        int b = blockIdx.x;
        float* xs = Ts + 128 * 129;
        if (tid < 128) xs[tid] = t[(long)b * DIMT + tid];
        const float* P = dPc + (long)b * KCP;
        for (int i = tid * 4; i < T0; i += 768) {
            float4 pv = *(const float4*)(P + i);
            uint4  ov = *(const uint4*)(g_uv + i);
            float  vv[4] = {pv.x, pv.y, pv.z, pv.w};
            uint32_t oo[4] = {ov.x, ov.y, ov.z, ov.w};
            #pragma unroll
            for (int k = 0; k < 4; k++) {
                int u = oo[k] >> 16, v = oo[k] & 0xffff;
                Ts[u * 129 + v] = vv[k];
                Ts[v * 129 + u] = (u == v) ? 2.f * vv[k] : vv[k];
            }
        }
        __syncthreads();
        if (tid < 128) {
            float s = 0.f;
            #pragma unroll 8
            for (int v = 0; v < 128; v++) s += Ts[tid * 129 + v] * xs[v];
            y[(long)b * DIMT + tid] = s;
        }
    } else if (blockIdx.x < 4096) {
        int b = blockIdx.x - 2048;
        float* xs = Ts + 64 * 65;
        xs[tid] = t[(long)b * DIMT + 128 + tid];
        const float* P = dPc + (long)b * KCP + S1;
        for (int i = tid * 4; i < T1; i += 768) {
            float4 pv = *(const float4*)(P + i);
            uint4  ov = *(const uint4*)(g_uv + S1 + i);
            float  vv[4] = {pv.x, pv.y, pv.z, pv.w};
            uint32_t oo[4] = {ov.x, ov.y, ov.z, ov.w};
            #pragma unroll
            for (int k = 0; k < 4; k++) {
                int u = oo[k] >> 16, v = oo[k] & 0xffff;
                Ts[u * 65 + v] = vv[k];
                Ts[v * 65 + u] = (u == v) ? 2.f * vv[k] : vv[k];
            }
        }
        __syncthreads();
        int u = tid / 3, m = tid - u * 3;
        float s = 0.f;
        #pragma unroll 8
        for (int v = 0; v < 64; v++) s += Ts[u * 65 + v] * xs[v * 3 + m];
        y[(long)b * DIMT + 128 + tid] = s;
    } else {
        int b = blockIdx.x - 4096;
        float* xs = Ts + 32 * 33;
        if (tid < 160) xs[tid] = t[(long)b * DIMT + 320 + tid];
        const float* P = dPc + (long)b * KCP + S2;
        for (int i = tid * 4; i < T2; i += 768) {
            float4 pv = *(const float4*)(P + i);
            uint4  ov = *(const uint4*)(g_uv + S2 + i);
            float  vv[4] = {pv.x, pv.y, pv.z, pv.w};
            uint32_t oo[4] = {ov.x, ov.y, ov.z, ov.w};
            #pragma unroll
            for (int k = 0; k < 4; k++) {
                int u = oo[k] >> 16, v = oo[k] & 0xffff;
                Ts[u * 33 + v] = vv[k];
                Ts[v * 33 + u] = (u == v) ? 2.f * vv[k] : vv[k];
            }
        }
        __syncthreads();
        if (tid < 160) {
            int u = tid / 5, m = tid - u * 5;
            float s = 0.f;
            #pragma unroll 8
            for (int v = 0; v < 32; v++) s += Ts[u * 33 + v] * xs[v * 5 + m];
            y[(long)b * DIMT + 320 + tid] = s;
        }
    }
}

// ---------------- launch ----------------
extern "C" void kernel_launch(void* const* d_in, const int* in_sizes, int n_in,
                              void* d_out, int out_size)
{
    const float* tin = (const float*)d_in[0];
    const float* w0  = (const float*)d_in[1];
    const float* w1  = (const float*)d_in[2];
    const float* w2  = (const float*)d_in[3];
    const float* W1  = (const float*)d_in[4];
    const float* b1  = (const float*)d_in[5];
    const float* g1  = (const float*)d_in[6];
    const float* be1 = (const float*)d_in[7];
    const float* W2  = (const float*)d_in[8];
    const float* b2  = (const float*)d_in[9];
    const float* g2  = (const float*)d_in[10];
    const float* be2 = (const float*)d_in[11];

    float* out  = (float*)d_out;
    float* xout = out;
    float* yout = out + (long)NB * ZD;

    h16* hb = nullptr; float* fb = nullptr;
    cudaGetSymbolAddress((void**)&hb, g_hbuf);
    cudaGetSymbolAddress((void**)&fb, g_fbuf);

    h16 *PC   = hb + B_PC;
    h16 *WThi = hb + B_WTHI;
    h16 *WPhi = hb + B_WPHI;
    h16 *W1Thi= hb + B_W1THI,*W1Tlo= hb + B_W1TLO;
    h16 *W1hi = hb + B_W1HI, *W1lo = hb + B_W1LO;
    h16 *W2Thi= hb + B_W2THI,*W2Tlo= hb + B_W2TLO;
    h16 *W2hi = hb + B_W2HI, *W2lo = hb + B_W2LO;
    h16 *eh   = hb + B_EH;
    h16 *h1h  = hb + B_H1H;
    h16 *da2h = hb + B_DA2H;
    h16 *da1h = hb + B_DA1H;
    h16 *deh  = hb + B_DEH;

    float *dPC = fb + F_DPC, *a1 = fb + F_A1, *xh1 = fb + F_XH1;
    float *a2  = fb + F_A2,  *dh1 = fb + F_DH1, *rs1 = fb + F_RS1;

    const float s0 = 1.0f / sqrtf(21504.0f);
    const float s1 = s0 / sqrtf(3.0f);
    const float s2 = s0 / sqrtf(5.0f);

    static cudaStream_t s2s = nullptr;
    static cudaEvent_t evFork = nullptr, evPack = nullptr, evDense = nullptr;
    if (!s2s) {
        cudaStreamCreateWithFlags(&s2s, cudaStreamNonBlocking);
        cudaEventCreateWithFlags(&evFork,  cudaEventDisableTiming);
        cudaEventCreateWithFlags(&evPack,  cudaEventDisableTiming);
        cudaEventCreateWithFlags(&evDense, cudaEventDisableTiming);
    }

    cudaFuncSetAttribute(h_gemm_nt<true>,  cudaFuncAttributeMaxDynamicSharedMemorySize, GSMEM);
    cudaFuncSetAttribute(h_gemm_nt<false>, cudaFuncAttributeMaxDynamicSharedMemorySize, GSMEM);
    cudaFuncSetAttribute(grad_all, cudaFuncAttributeMaxDynamicSharedMemorySize, 128 * 129 * 4 + 768);

    // ---- prep: fork ----
    uv_init<<<(KCP + 255) / 256, 256>>>();
    cudaEventRecord(evFork, 0);
    cudaStreamWaitEvent(s2s, evFork, 0);
    pack_both<<<dim3(344, HID / 32), 256, 0, s2s>>>(w0, w1, w2, WThi, WPhi, s0, s1, s2);
    cudaEventRecord(evPack, s2s);
    dense_all<<<6400, 256, 0, s2s>>>(W1, W2, W1Thi, W1Tlo, W2Thi, W2Tlo, W1hi, W1lo, W2hi, W2lo);
    cudaEventRecord(evDense, s2s);
    build_Pp_v5<<<NB, 256>>>(tin, PC);
    cudaStreamWaitEvent(0, evPack, 0);

    // ---- forward ----
    h_gemm_nt<false><<<dim3(HID / 128, NB / 128), 512, GSMEM>>>(
        PC, WThi, WThi, nullptr, eh, KCP, KCP, HID, 0, 1.f, nullptr);
    cudaStreamWaitEvent(0, evDense, 0);
    h_gemm_nt<true><<<dim3(HID / 128, NB / 128), 512, GSMEM>>>(
        eh, W1Thi, W1Tlo, a1, nullptr, HID, HID, HID, 0, 1.f, b1);
    ln_silu_fwd4<<<NB, 256>>>(a1, g1, be1, xh1, rs1, h1h);
    // W2 fwd: split-K=4 across gridDim.z (deterministic; chunks summed in ln2_fused)
    h_gemm_nt<true><<<dim3(ZD / 128, NB / 128, 4), 512, GSMEM>>>(
        h1h, W2Thi, W2Tlo, a2, nullptr, HID / 4, HID, ZD, NZ, 1.f, nullptr);
    ln2_fused<<<NB, 256>>>(a2, b2, g2, be2, xout, da2h);

    // ---- backward ----
    h_gemm_nt<true><<<dim3(HID / 128, NB / 128), 512, GSMEM>>>(
        da2h, W2hi, W2lo, dh1, nullptr, ZD, ZD, HID, 0, 1.f, nullptr);
    ln_silu_bwd4<<<NB, 256>>>(dh1, xh1, rs1, g1, be1, da1h);
    h_gemm_nt<true><<<dim3(HID / 128, NB / 128), 512, GSMEM>>>(
        da1h, W1hi, W1lo, nullptr, deh, HID, HID, HID, 0, 1.f, nullptr);
    h_gemm_nt<false><<<dim3(KCP / 128, NB / 128), 512, GSMEM>>>(
        deh, WPhi, WPhi, dPC, nullptr, HID, HID, KCP, 0, 1.f, nullptr);

    grad_all<<<6144, 192, 128 * 129 * 4 + 768>>>(dPC, tin, yout);
}

// round 17
// speedup vs baseline: 10.6925x; 1.0157x over previous
#include <cuda_runtime.h>
#include <cuda_fp16.h>
#include <math.h>
#include <stdint.h>

#define NB   2048
#define DIMT 480
#define HID  1024
#define ZD   256
#define T0   8256
#define KP0  8256
#define T1   2080
#define KP1  2112
#define T2   528
#define KP2  640
#define KCP  11008
#define S1   8256
#define S2   10368

typedef __half h16;

// ---------------- scratch pools ----------------
constexpr long NBKC = (long)NB * KCP;
constexpr long HKC  = (long)HID * KCP;
constexpr long HH   = (long)HID * HID;
constexpr long ZH   = (long)ZD * HID;
constexpr long NH   = (long)NB * HID;
constexpr long NZ   = (long)NB * ZD;

constexpr long B_PC   = 0;
constexpr long B_WTHI = B_PC   + NBKC;
constexpr long B_WPHI = B_WTHI + HKC;
constexpr long B_W1THI= B_WPHI + HKC;
constexpr long B_W1TLO= B_W1THI + HH;
constexpr long B_W1HI = B_W1TLO + HH;
constexpr long B_W1LO = B_W1HI + HH;
constexpr long B_W2THI= B_W1LO + HH;
constexpr long B_W2TLO= B_W2THI + ZH;
constexpr long B_W2HI = B_W2TLO + ZH;
constexpr long B_W2LO = B_W2HI + ZH;
constexpr long B_EH   = B_W2LO + ZH;
constexpr long B_H1H  = B_EH   + NH;
constexpr long B_DA2H = B_H1H  + NH;
constexpr long B_DA1H = B_DA2H + NZ;
constexpr long B_DEH  = B_DA1H + NH;
constexpr long B_TOT  = B_DEH  + NH;

constexpr long F_DPC  = 0;
constexpr long F_A1   = F_DPC + NBKC;
constexpr long F_XH1  = F_A1  + NH;
constexpr long F_A2   = F_XH1 + NH;          // 4 x NZ (split-K chunks)
constexpr long F_DH1  = F_A2  + 4 * NZ;
constexpr long F_RS1  = F_DH1 + NH;
constexpr long F_TOT  = F_RS1 + NB;

__device__ h16      g_hbuf[B_TOT];
__device__ float    g_fbuf[F_TOT];
__device__ uint32_t g_uv[KCP];
__device__ uint32_t g_uvo[KCP];

// ---------------- helpers ----------------
__device__ __forceinline__ uint32_t smem_u32(const void* p) {
    uint32_t a;
    asm("{ .reg .u64 t; cvta.to.shared.u64 t, %1; cvt.u32.u64 %0, t; }" : "=r"(a) : "l"(p));
    return a;
}
__device__ __forceinline__ void ldsm4(uint32_t* r, uint32_t a) {
    asm volatile("ldmatrix.sync.aligned.m8n8.x4.shared.b16 {%0,%1,%2,%3},[%4];"
                 : "=r"(r[0]), "=r"(r[1]), "=r"(r[2]), "=r"(r[3]) : "r"(a));
}
__device__ __forceinline__ void mma_f16(float* d, const uint32_t* a, const uint32_t* b) {
    asm volatile("mma.sync.aligned.m16n8k16.row.col.f32.f16.f16.f32 "
                 "{%0,%1,%2,%3},{%4,%5,%6,%7},{%8,%9},{%0,%1,%2,%3};"
                 : "+f"(d[0]), "+f"(d[1]), "+f"(d[2]), "+f"(d[3])
                 : "r"(a[0]), "r"(a[1]), "r"(a[2]), "r"(a[3]), "r"(b[0]), "r"(b[1]));
}
#define CPA(dst, src) asm volatile("cp.async.cg.shared.global [%0], [%1], 16;" :: "r"(dst), "l"(src) : "memory")
#define CPCOMMIT()    asm volatile("cp.async.commit_group;" ::: "memory")
#define CPWAIT0()     asm volatile("cp.async.wait_group 0;" ::: "memory")

__device__ __forceinline__ void splith(float v, h16& h, h16& l) {
    h = __float2half(v);
    l = __float2half((v - __half2float(h)) * 2048.f);
}

// ---------------- pair LUTs ----------------
__global__ void uv_init() {
    int p = blockIdx.x * 256 + threadIdx.x;
    if (p >= KCP) return;
    int n, lp, T, nm, xoff;
    if (p < S1)      { n = 128; lp = p;      T = T0; nm = 1; xoff = 0; }
    else if (p < S2) { n = 64;  lp = p - S1; T = T1; nm = 3; xoff = 128; }
    else             { n = 32;  lp = p - S2; T = T2; nm = 5; xoff = 320; }
    if (lp >= T) { g_uv[p] = 0u; g_uvo[p] = 0xFFFFFFFFu; return; }
    float tn = 2.f * n + 1.f;
    int u = (int)((tn - sqrtf(tn * tn - 8.f * lp)) * 0.5f);
    if (u < 0) u = 0; if (u > n - 1) u = n - 1;
    while (u > 0 && u * n - u * (u - 1) / 2 > lp) u--;
    while (u < n - 1 && (u + 1) * n - (u + 1) * u / 2 <= lp) u++;
    int v = u + (lp - (u * n - u * (u - 1) / 2));
    g_uv[p]  = ((uint32_t)u << 16) | (uint32_t)v;
    g_uvo[p] = ((uint32_t)(xoff + u * nm) << 16) | (uint32_t)(xoff + v * nm);
}

// ---------------- fp16 NT GEMM: BK=128, 2-stage, 512 threads ----------------
#define TILEH 32768
#define STGH  (3 * TILEH)
#define GSMEM (2 * STGH + 1024)

template<bool LO>
__global__ __launch_bounds__(512, 1) void h_gemm_nt(
    const h16* __restrict__ A, const h16* __restrict__ Bhi, const h16* __restrict__ Blo,
    float* __restrict__ C, h16* __restrict__ Ch,
    int K, long ld, long ldc, long csplit, float alpha, const float* __restrict__ bias)
{
    extern __shared__ char smem[];
    const uint32_t st0 = (smem_u32(smem) + 1023) & ~1023u;
    const int tid = threadIdx.x, wid = tid >> 5, lane = tid & 31;
    const int wm = wid >> 2, wn = wid & 3;
    const long bm = (long)blockIdx.y * 128, bn = (long)blockIdx.x * 128;
    const long kz = (long)blockIdx.z * K;

    const h16* Ab  = A   + kz;
    const h16* Bb  = Bhi + kz;
    const h16* Blb = Blo + kz;
    if (C) C += (long)blockIdx.z * csplit;

    constexpr int NCH = LO ? 12 : 8;
    const h16* gp[NCH];
    uint32_t so[NCH];
    #pragma unroll
    for (int t = 0; t < NCH; t++) {
        int q = tid + (t & 3) * 512;
        int r = q >> 4, c = q & 15;
        int tile = t >> 2;
        const h16* base = (tile == 0) ? Ab : (tile == 1) ? Bb : Blb;
        long row = (tile == 0 ? bm : bn) + r;
        gp[t] = base + row * ld + c * 8;
        so[t] = st0 + tile * TILEH + ((r * 256 + c * 16) ^ ((r & 7) << 4));
    }
    const int nk = K >> 7;

    #pragma unroll
    for (int t = 0; t < NCH; t++) CPA(so[t], gp[t]);
    CPCOMMIT();

    float ac1[2][4][4], ac2[2][4][4];
    #pragma unroll
    for (int a = 0; a < 2; a++)
        #pragma unroll
        for (int b = 0; b < 4; b++)
            #pragma unroll
            for (int c = 0; c < 4; c++) { ac1[a][b][c] = 0.f; if (LO) ac2[a][b][c] = 0.f; }

    const int lr = lane & 15, lc = lane >> 4;
    const uint32_t xa = (lr & 7) << 4;
    const uint32_t arow = (wm * 32 + lr) * 256 + lc * 16;
    const uint32_t brow = (wn * 32 + lr) * 256 + lc * 16;

    for (int i = 0; i < nk; i++) {
        CPWAIT0();
        __syncthreads();
        if (i + 1 < nk) {
            const uint32_t sst = ((i + 1) & 1) * STGH;
            #pragma unroll
            for (int t = 0; t < NCH; t++) CPA(so[t] + sst, gp[t] + (long)(i + 1) * 128);
            CPCOMMIT();
        }

        const uint32_t sa = st0 + (i & 1) * STGH;
        #pragma unroll
        for (int kk = 0; kk < 8; kk++) {
            uint32_t af[2][4], bh[4][2], bl[4][2];
            #pragma unroll
            for (int mi = 0; mi < 2; mi++)
                ldsm4(af[mi], sa + ((arow + mi * 4096 + kk * 32) ^ xa));
            #pragma unroll
            for (int pi = 0; pi < 2; pi++) {
                uint32_t off = (brow + pi * 4096 + kk * 32) ^ xa;
                uint32_t t0[4];
                ldsm4(t0, sa + TILEH + off);
                bh[2 * pi][0] = t0[0]; bh[2 * pi + 1][0] = t0[1];
                bh[2 * pi][1] = t0[2]; bh[2 * pi + 1][1] = t0[3];
                if (LO) {
                    uint32_t t1[4];
                    ldsm4(t1, sa + 2 * TILEH + off);
                    bl[2 * pi][0] = t1[0]; bl[2 * pi + 1][0] = t1[1];
                    bl[2 * pi][1] = t1[2]; bl[2 * pi + 1][1] = t1[3];
                }
            }
            #pragma unroll
            for (int mi = 0; mi < 2; mi++)
                #pragma unroll
                for (int ni = 0; ni < 4; ni++) {
                    mma_f16(ac1[mi][ni], af[mi], bh[ni]);
                    if (LO) mma_f16(ac2[mi][ni], af[mi], bl[ni]);
                }
        }
    }

    const int g = lane >> 2, tg = lane & 3;
    const float inv = 1.f / 2048.f;
    #pragma unroll
    for (int mi = 0; mi < 2; mi++) {
        #pragma unroll
        for (int ni = 0; ni < 4; ni++) {
            long m0 = bm + wm * 32 + mi * 16 + g;
            long n0 = bn + wn * 32 + ni * 8 + tg * 2;
            float v00, v01, v10, v11;
            if (LO) {
                v00 = alpha * (ac1[mi][ni][0] + ac2[mi][ni][0] * inv);
                v01 = alpha * (ac1[mi][ni][1] + ac2[mi][ni][1] * inv);
                v10 = alpha * (ac1[mi][ni][2] + ac2[mi][ni][2] * inv);
                v11 = alpha * (ac1[mi][ni][3] + ac2[mi][ni][3] * inv);
            } else {
                v00 = alpha * ac1[mi][ni][0];
                v01 = alpha * ac1[mi][ni][1];
                v10 = alpha * ac1[mi][ni][2];
                v11 = alpha * ac1[mi][ni][3];
            }
            if (bias) {
                float bb0 = bias[n0], bb1 = bias[n0 + 1];
                v00 += bb0; v01 += bb1; v10 += bb0; v11 += bb1;
            }
            if (C) {
                *(float2*)(C + m0 * ldc + n0) = make_float2(v00, v01);
                *(float2*)(C + (m0 + 8) * ldc + n0) = make_float2(v10, v11);
            }
            if (Ch) {
                *(__half2*)(Ch + m0 * ldc + n0) = __floats2half2_rn(v00, v01);
                *(__half2*)(Ch + (m0 + 8) * ldc + n0) = __floats2half2_rn(v10, v11);
            }
        }
    }
}

// ---------------- merged packing (hi-only outputs) ----------------
__global__ __launch_bounds__(256) void pack_both(
    const float* __restrict__ w0, const float* __restrict__ w1, const float* __restrict__ w2,
    h16* __restrict__ thi, h16* __restrict__ phi,
    float sc0, float sc1, float sc2)
{
    __shared__ float sv[32][33];
    int bx = blockIdx.x;
    const float* w; int n, T; long kbase; float s;
    int pb;
    if (bx < 258)      { w = w0; n = 128; T = T0; kbase = 0;  s = sc0; pb = bx * 32; }
    else if (bx < 324) { w = w1; n = 64;  T = T1; kbase = S1; s = sc1; pb = (bx - 258) * 32; }
    else               { w = w2; n = 32;  T = T2; kbase = S2; s = sc2; pb = (bx - 324) * 32; }
    int hb = blockIdx.y * 32;
    int tx = threadIdx.x & 31, ty = threadIdx.x >> 5;
    #pragma unroll
    for (int i = 0; i < 32; i += 8) {
        int pp = pb + ty + i;
        float val = 0.f;
        if (pp < T) {
            uint32_t uv = g_uv[kbase + pp];
            int u = uv >> 16, v = uv & 0xffff;
            val = w[((long)u * n + v) * HID + hb + tx];
            if (u != v) val += w[((long)v * n + u) * HID + hb + tx];
            val *= s;
        }
        sv[ty + i][tx] = val;
        phi[(kbase + pp) * (long)HID + hb + tx] = __float2half(val);
    }
    __syncthreads();
    #pragma unroll
    for (int i = 0; i < 32; i += 8) {
        thi[(long)(hb + ty + i) * KCP + kbase + pb + tx] = __float2half(sv[tx][ty + i]);
    }
}

// dense_all
__global__ __launch_bounds__(256) void dense_all(
    const float* __restrict__ W1, const float* __restrict__ W2,
    h16* __restrict__ W1Thi, h16* __restrict__ W1Tlo,
    h16* __restrict__ W2Thi, h16* __restrict__ W2Tlo,
    h16* __restrict__ W1hi, h16* __restrict__ W1lo,
    h16* __restrict__ W2hi, h16* __restrict__ W2lo)
{
    __shared__ float t[32][33];
    long lin = blockIdx.x;
    if (lin < 1024 + 256) {
        const float* src; h16 *dhi, *dlo; int C; long ldd; int gx, gy;
        if (lin < 1024) { src = W1; dhi = W1Thi; dlo = W1Tlo; C = HID; ldd = HID; gx = (int)(lin % 32); gy = (int)(lin / 32); }
        else { long l = lin - 1024; src = W2; dhi = W2Thi; dlo = W2Tlo; C = ZD; ldd = HID; gx = (int)(l % 8); gy = (int)(l / 8); }
        int bx = gx * 32, by = gy * 32;
        int tx = threadIdx.x & 31, ty = threadIdx.x >> 5;
        #pragma unroll
        for (int i = 0; i < 32; i += 8)
            t[ty + i][tx] = src[(long)(by + ty + i) * C + bx + tx];
        __syncthreads();
        #pragma unroll
        for (int i = 0; i < 32; i += 8) {
            h16 h, l; splith(t[tx][ty + i], h, l);
            long o = (long)(bx + ty + i) * ldd + by + tx;
            dhi[o] = h; dlo[o] = l;
        }
    } else if (lin < 1024 + 256 + 4096) {
        long i = (lin - 1280) * 256 + threadIdx.x;
        if (i < HH) { h16 h, l; splith(W1[i], h, l); W1hi[i] = h; W1lo[i] = l; }
    } else {
        long i = (lin - 5376) * 256 + threadIdx.x;
        if (i < ZH) { h16 h, l; splith(W2[i], h, l); W2hi[i] = h; W2lo[i] = l; }
    }
}

// ---------------- build_Pp v6: 4-wide region 0, 2-wide regions 1/2 ----------------
__global__ __launch_bounds__(256) void build_Pp_v6(const float* __restrict__ t, h16* __restrict__ Ph)
{
    __shared__ float xs[DIMT];
    int b = blockIdx.x, tid = threadIdx.x;
    if (tid < DIMT) xs[tid] = t[(long)b * DIMT + tid];
    if (tid + 256 < DIMT) xs[tid + 256] = t[(long)b * DIMT + tid + 256];
    __syncthreads();
    h16* out = Ph + (long)b * KCP;
    for (int p = tid * 4; p < KP0; p += 1024) {
        uint4 oo = *(const uint4*)(g_uvo + p);
        float v0 = xs[oo.x >> 16] * xs[oo.x & 0xffff];
        float v1 = xs[oo.y >> 16] * xs[oo.y & 0xffff];
        float v2 = xs[oo.z >> 16] * xs[oo.z & 0xffff];
        float v3 = xs[oo.w >> 16] * xs[oo.w & 0xffff];
        __half2 h01 = __floats2half2_rn(v0, v1);
        __half2 h23 = __floats2half2_rn(v2, v3);
        float2 pk;
        pk.x = __uint_as_float(*(uint32_t*)&h01);
        pk.y = __uint_as_float(*(uint32_t*)&h23);
        *(float2*)(out + p) = pk;
    }
    // region 1: 2-wide (S1 even, KP1 even)
    for (int p = S1 + tid * 2; p < S1 + KP1; p += 512) {
        uint2 oo = *(const uint2*)(g_uvo + p);
        float v0 = 0.f, v1 = 0.f;
        if (oo.x != 0xFFFFFFFFu) {
            int uo = oo.x >> 16, vo = oo.x & 0xffff;
            #pragma unroll
            for (int m = 0; m < 3; m++) v0 += xs[uo + m] * xs[vo + m];
        }
        if (oo.y != 0xFFFFFFFFu) {
            int uo = oo.y >> 16, vo = oo.y & 0xffff;
            #pragma unroll
            for (int m = 0; m < 3; m++) v1 += xs[uo + m] * xs[vo + m];
        }
        *(__half2*)(out + p) = __floats2half2_rn(v0, v1);
    }
    // region 2: 2-wide (S2 even, KP2 even)
    for (int p = S2 + tid * 2; p < S2 + KP2; p += 512) {
        uint2 oo = *(const uint2*)(g_uvo + p);
        float v0 = 0.f, v1 = 0.f;
        if (oo.x != 0xFFFFFFFFu) {
            int uo = oo.x >> 16, vo = oo.x & 0xffff;
            #pragma unroll
            for (int m = 0; m < 5; m++) v0 += xs[uo + m] * xs[vo + m];
        }
        if (oo.y != 0xFFFFFFFFu) {
            int uo = oo.y >> 16, vo = oo.y & 0xffff;
            #pragma unroll
            for (int m = 0; m < 5; m++) v1 += xs[uo + m] * xs[vo + m];
        }
        *(__half2*)(out + p) = __floats2half2_rn(v0, v1);
    }
}

// ---------------- block reduce ----------------
__device__ __forceinline__ float blockReduceSum(float val) {
    __shared__ float sh[8];
    int lane = threadIdx.x & 31, w = threadIdx.x >> 5;
    #pragma unroll
    for (int o = 16; o > 0; o >>= 1) val += __shfl_down_sync(0xffffffffu, val, o);
    __syncthreads();
    if (lane == 0) sh[w] = val;
    __syncthreads();
    float r = 0.f;
    if (threadIdx.x == 0) {
        int nw = blockDim.x >> 5;
        for (int i = 0; i < nw; i++) r += sh[i];
    }
    return r;
}

// ---------------- LayerNorm + SiLU forward (layer 1) ----------------
__global__ __launch_bounds__(256) void ln_silu_fwd4(
    const float* __restrict__ a, const float* __restrict__ gam, const float* __restrict__ bet,
    float* __restrict__ xh, float* __restrict__ rstd, h16* __restrict__ hh)
{
    const int D = 1024;
    int b = blockIdx.x, tid = threadIdx.x;
    const float* row = a + (long)b * D;
    float v[4];
    float s = 0.f;
    #pragma unroll
    for (int i = 0; i < 4; i++) { v[i] = row[tid + (i << 8)]; s += v[i]; }
    s = blockReduceSum(s);
    __shared__ float bc;
    if (tid == 0) bc = s * (1.f / D);
    __syncthreads();
    float mu = bc;
    float q = 0.f;
    #pragma unroll
    for (int i = 0; i < 4; i++) { float d = v[i] - mu; q += d * d; }
    q = blockReduceSum(q);
    if (tid == 0) { float r = rsqrtf(q * (1.f / D) + 1e-6f); bc = r; rstd[b] = r; }
    __syncthreads();
    float r = bc;
    #pragma unroll
    for (int i = 0; i < 4; i++) {
        int c = tid + (i << 8);
        float x = (v[i] - mu) * r;
        xh[(long)b * D + c] = x;
        float z = x * gam[c] + bet[c];
        float sg = 1.f / (1.f + expf(-z));
        hh[(long)b * D + c] = __float2half(z * sg);
    }
}

// ---------------- fused LN2 fwd + bwd; sums 4 split-K chunks + bias ----------------
__global__ __launch_bounds__(256) void ln2_fused(
    const float* __restrict__ a, const float* __restrict__ b2,
    const float* __restrict__ gam, const float* __restrict__ bet,
    float* __restrict__ xout, h16* __restrict__ dah)
{
    const int D = 256;
    int b = blockIdx.x, tid = threadIdx.x;
    long idx = (long)b * D + tid;
    float v = ((a[idx] + a[idx + NZ]) + (a[idx + 2 * NZ] + a[idx + 3 * NZ])) + b2[tid];
    float s = blockReduceSum(v);
    __shared__ float bc;
    if (tid == 0) bc = s * (1.f / D);
    __syncthreads();
    float mu = bc;
    float d = v - mu;
    float q = blockReduceSum(d * d);
    if (tid == 0) bc = rsqrtf(q * (1.f / D) + 1e-6f);
    __syncthreads();
    float r = bc;
    float x = (v - mu) * r;
    float z = x * gam[tid] + bet[tid];
    float sg = 1.f / (1.f + expf(-z));
    xout[idx] = z * sg;
    float ds = sg * (1.f + z * (1.f - sg));
    float dx = ds * gam[tid];
    float t1 = blockReduceSum(dx);
    __shared__ float m1s, m2s;
    if (tid == 0) m1s = t1 * (1.f / D);
    float t2 = blockReduceSum(dx * x);
    if (tid == 0) m2s = t2 * (1.f / D);
    __syncthreads();
    dah[idx] = __float2half(r * (dx - m1s - x * m2s));
}

// ---------------- (SiLU + LN) backward (layer 1) ----------------
__global__ __launch_bounds__(256) void ln_silu_bwd4(
    const float* __restrict__ dh, const float* __restrict__ xhv_, const float* __restrict__ rstd,
    const float* __restrict__ gam, const float* __restrict__ bet, h16* __restrict__ dah)
{
    const int D = 1024;
    int b = blockIdx.x, tid = threadIdx.x;
    float xh[4], dxh[4];
    float s1 = 0.f, s2 = 0.f;
    #pragma unroll
    for (int i = 0; i < 4; i++) {
        int c = tid + (i << 8);
        float x = xhv_[(long)b * D + c];
        float z = x * gam[c] + bet[c];
        float sg = 1.f / (1.f + expf(-z));
        float ds = sg * (1.f + z * (1.f - sg));
        float dx = dh[(long)b * D + c] * ds * gam[c];
        xh[i] = x; dxh[i] = dx;
        s1 += dx; s2 += dx * x;
    }
    __shared__ float m1s, m2s;
    float t1 = blockReduceSum(s1);
    if (tid == 0) m1s = t1 * (1.f / D);
    float t2 = blockReduceSum(s2);
    if (tid == 0) m2s = t2 * (1.f / D);
    __syncthreads();
    float m1 = m1s, m2 = m2s, r = rstd[b];
    #pragma unroll
    for (int i = 0; i < 4; i++) {
        int c = tid + (i << 8);
        dah[(long)b * D + c] = __float2half(r * (dxh[i] - m1 - xh[i] * m2));
    }
}

// ---------------- merged packed quadratic-form gradients -> y ----------------
__global__ __launch_bounds__(192) void grad_all(const float* __restrict__ dPc,
                                                const float* __restrict__ t, float* __restrict__ y)
{
    extern __shared__ float Ts[];
    int tid = threadIdx.x;
    if (blockIdx.x < 2048) {
        int b = blockIdx.x;
        float* xs = Ts + 128 * 129;
        if (tid < 128) xs[tid] = t[(long)b * DIMT + tid];
        const float* P = dPc + (long)b * KCP;
        for (int i = tid * 4; i < T0; i += 768) {
            float4 pv = *(const float4*)(P + i);
            uint4  ov = *(const uint4*)(g_uv + i);
            float  vv[4] = {pv.x, pv.y, pv.z, pv.w};
            uint32_t oo[4] = {ov.x, ov.y, ov.z, ov.w};
            #pragma unroll
            for (int k = 0; k < 4; k++) {
                int u = oo[k] >> 16, v = oo[k] & 0xffff;
                Ts[u * 129 + v] = vv[k];
                Ts[v * 129 + u] = (u == v) ? 2.f * vv[k] : vv[k];
            }
        }
        __syncthreads();
        if (tid < 128) {
            float s = 0.f;
            #pragma unroll 8
            for (int v = 0; v < 128; v++) s += Ts[tid * 129 + v] * xs[v];
            y[(long)b * DIMT + tid] = s;
        }
    } else if (blockIdx.x < 4096) {
        int b = blockIdx.x - 2048;
        float* xs = Ts + 64 * 65;
        xs[tid] = t[(long)b * DIMT + 128 + tid];
        const float* P = dPc + (long)b * KCP + S1;
        for (int i = tid * 4; i < T1; i += 768) {
            float4 pv = *(const float4*)(P + i);
            uint4  ov = *(const uint4*)(g_uv + S1 + i);
            float  vv[4] = {pv.x, pv.y, pv.z, pv.w};
            uint32_t oo[4] = {ov.x, ov.y, ov.z, ov.w};
            #pragma unroll
            for (int k = 0; k < 4; k++) {
                int u = oo[k] >> 16, v = oo[k] & 0xffff;
                Ts[u * 65 + v] = vv[k];
                Ts[v * 65 + u] = (u == v) ? 2.f * vv[k] : vv[k];
            }
        }
        __syncthreads();
        int u = tid / 3, m = tid - u * 3;
        float s = 0.f;
        #pragma unroll 8
        for (int v = 0; v < 64; v++) s += Ts[u * 65 + v] * xs[v * 3 + m];
        y[(long)b * DIMT + 128 + tid] = s;
    } else {
        int b = blockIdx.x - 4096;
        float* xs = Ts + 32 * 33;
        if (tid < 160) xs[tid] = t[(long)b * DIMT + 320 + tid];
        const float* P = dPc + (long)b * KCP + S2;
        for (int i = tid * 4; i < T2; i += 768) {
            float4 pv = *(const float4*)(P + i);
            uint4  ov = *(const uint4*)(g_uv + S2 + i);
            float  vv[4] = {pv.x, pv.y, pv.z, pv.w};
            uint32_t oo[4] = {ov.x, ov.y, ov.z, ov.w};
            #pragma unroll
            for (int k = 0; k < 4; k++) {
                int u = oo[k] >> 16, v = oo[k] & 0xffff;
                Ts[u * 33 + v] = vv[k];
                Ts[v * 33 + u] = (u == v) ? 2.f * vv[k] : vv[k];
            }
        }
        __syncthreads();
        if (tid < 160) {
            int u = tid / 5, m = tid - u * 5;
            float s = 0.f;
            #pragma unroll 8
            for (int v = 0; v < 32; v++) s += Ts[u * 33 + v] * xs[v * 5 + m];
            y[(long)b * DIMT + 320 + tid] = s;
        }
    }
}

// ---------------- launch ----------------
extern "C" void kernel_launch(void* const* d_in, const int* in_sizes, int n_in,
                              void* d_out, int out_size)
{
    const float* tin = (const float*)d_in[0];
    const float* w0  = (const float*)d_in[1];
    const float* w1  = (const float*)d_in[2];
    const float* w2  = (const float*)d_in[3];
    const float* W1  = (const float*)d_in[4];
    const float* b1  = (const float*)d_in[5];
    const float* g1  = (const float*)d_in[6];
    const float* be1 = (const float*)d_in[7];
    const float* W2  = (const float*)d_in[8];
    const float* b2  = (const float*)d_in[9];
    const float* g2  = (const float*)d_in[10];
    const float* be2 = (const float*)d_in[11];

    float* out  = (float*)d_out;
    float* xout = out;
    float* yout = out + (long)NB * ZD;

    h16* hb = nullptr; float* fb = nullptr;
    cudaGetSymbolAddress((void**)&hb, g_hbuf);
    cudaGetSymbolAddress((void**)&fb, g_fbuf);

    h16 *PC   = hb + B_PC;
    h16 *WThi = hb + B_WTHI;
    h16 *WPhi = hb + B_WPHI;
    h16 *W1Thi= hb + B_W1THI,*W1Tlo= hb + B_W1TLO;
    h16 *W1hi = hb + B_W1HI, *W1lo = hb + B_W1LO;
    h16 *W2Thi= hb + B_W2THI,*W2Tlo= hb + B_W2TLO;
    h16 *W2hi = hb + B_W2HI, *W2lo = hb + B_W2LO;
    h16 *eh   = hb + B_EH;
    h16 *h1h  = hb + B_H1H;
    h16 *da2h = hb + B_DA2H;
    h16 *da1h = hb + B_DA1H;
    h16 *deh  = hb + B_DEH;

    float *dPC = fb + F_DPC, *a1 = fb + F_A1, *xh1 = fb + F_XH1;
    float *a2  = fb + F_A2,  *dh1 = fb + F_DH1, *rs1 = fb + F_RS1;

    const float s0 = 1.0f / sqrtf(21504.0f);
    const float s1 = s0 / sqrtf(3.0f);
    const float s2 = s0 / sqrtf(5.0f);

    static cudaStream_t s2s = nullptr;
    static cudaEvent_t evFork = nullptr, evPack = nullptr, evDense = nullptr;
    if (!s2s) {
        cudaStreamCreateWithFlags(&s2s, cudaStreamNonBlocking);
        cudaEventCreateWithFlags(&evFork,  cudaEventDisableTiming);
        cudaEventCreateWithFlags(&evPack,  cudaEventDisableTiming);
        cudaEventCreateWithFlags(&evDense, cudaEventDisableTiming);
    }

    cudaFuncSetAttribute(h_gemm_nt<true>,  cudaFuncAttributeMaxDynamicSharedMemorySize, GSMEM);
    cudaFuncSetAttribute(h_gemm_nt<false>, cudaFuncAttributeMaxDynamicSharedMemorySize, GSMEM);
    cudaFuncSetAttribute(grad_all, cudaFuncAttributeMaxDynamicSharedMemorySize, 128 * 129 * 4 + 768);

    // ---- prep: fork ----
    uv_init<<<(KCP + 255) / 256, 256>>>();
    cudaEventRecord(evFork, 0);
    cudaStreamWaitEvent(s2s, evFork, 0);
    pack_both<<<dim3(344, HID / 32), 256, 0, s2s>>>(w0, w1, w2, WThi, WPhi, s0, s1, s2);
    cudaEventRecord(evPack, s2s);
    dense_all<<<6400, 256, 0, s2s>>>(W1, W2, W1Thi, W1Tlo, W2Thi, W2Tlo, W1hi, W1lo, W2hi, W2lo);
    cudaEventRecord(evDense, s2s);
    build_Pp_v6<<<NB, 256>>>(tin, PC);
    cudaStreamWaitEvent(0, evPack, 0);

    // ---- forward ----
    h_gemm_nt<false><<<dim3(HID / 128, NB / 128), 512, GSMEM>>>(
        PC, WThi, WThi, nullptr, eh, KCP, KCP, HID, 0, 1.f, nullptr);
    cudaStreamWaitEvent(0, evDense, 0);
    h_gemm_nt<true><<<dim3(HID / 128, NB / 128), 512, GSMEM>>>(
        eh, W1Thi, W1Tlo, a1, nullptr, HID, HID, HID, 0, 1.f, b1);
    ln_silu_fwd4<<<NB, 256>>>(a1, g1, be1, xh1, rs1, h1h);
    h_gemm_nt<true><<<dim3(ZD / 128, NB / 128, 4), 512, GSMEM>>>(
        h1h, W2Thi, W2Tlo, a2, nullptr, HID / 4, HID, ZD, NZ, 1.f, nullptr);
    ln2_fused<<<NB, 256>>>(a2, b2, g2, be2, xout, da2h);

    // ---- backward ----
    h_gemm_nt<true><<<dim3(HID / 128, NB / 128), 512, GSMEM>>>(
        da2h, W2hi, W2lo, dh1, nullptr, ZD, ZD, HID, 0, 1.f, nullptr);
    ln_silu_bwd4<<<NB, 256>>>(dh1, xh1, rs1, g1, be1, da1h);
    h_gemm_nt<true><<<dim3(HID / 128, NB / 128), 512, GSMEM>>>(
        da1h, W1hi, W1lo, nullptr, deh, HID, HID, HID, 0, 1.f, nullptr);
    h_gemm_nt<false><<<dim3(KCP / 128, NB / 128), 512, GSMEM>>>(
        deh, WPhi, WPhi, dPC, nullptr, HID, HID, KCP, 0, 1.f, nullptr);

    grad_all<<<6144, 192, 128 * 129 * 4 + 768>>>(dPC, tin, yout);
}